// round 4
// baseline (speedup 1.0000x reference)
#include <cuda_runtime.h>
#include <math.h>
#include <float.h>

#define DMODEL 1024
#define NB     4
#define TQL    512
#define TKVL   4096
#define NH     8
#define HD     128

// Scratch (device globals -- no allocation allowed)
__device__ float g_Q[NB * TQL  * DMODEL];
__device__ float g_K[NB * TKVL * DMODEL];
__device__ float g_V[NB * TKVL * DMODEL];
__device__ float g_A[NB * TQL  * DMODEL];

// ---------------------------------------------------------------------------
// SGEMM: C[M,1024] = A[M,1024] @ W[1024,1024] + bias   (128x128x8, 8x8/thread)
// grid = (1024/128, M/128), block = 256
// ---------------------------------------------------------------------------
__global__ __launch_bounds__(256) void gemm_bias_kernel(
    const float* __restrict__ A, const float* __restrict__ W,
    const float* __restrict__ bias, float* __restrict__ C)
{
    __shared__ float As[8][128];
    __shared__ float Bs[8][128];

    const int tid = threadIdx.x;
    const int bm  = blockIdx.y * 128;
    const int bn  = blockIdx.x * 128;
    const int tx  = tid & 15;
    const int ty  = tid >> 4;

    const int a_row = tid >> 1;
    const int a_col = (tid & 1) * 4;
    const int b_row = tid >> 5;
    const int b_col = (tid & 31) * 4;

    const float* Ap = A + (size_t)(bm + a_row) * DMODEL + a_col;
    const float* Wp = W + (size_t)b_row * DMODEL + bn + b_col;

    float acc[8][8];
#pragma unroll
    for (int i = 0; i < 8; i++)
#pragma unroll
        for (int j = 0; j < 8; j++) acc[i][j] = 0.0f;

    for (int k0 = 0; k0 < DMODEL; k0 += 8) {
        float4 av = *(const float4*)(Ap + k0);
        float4 wv = *(const float4*)(Wp + (size_t)k0 * DMODEL);

        As[a_col + 0][a_row] = av.x;
        As[a_col + 1][a_row] = av.y;
        As[a_col + 2][a_row] = av.z;
        As[a_col + 3][a_row] = av.w;
        *(float4*)&Bs[b_row][b_col] = wv;
        __syncthreads();

#pragma unroll
        for (int kk = 0; kk < 8; kk++) {
            float a[8], b[8];
#pragma unroll
            for (int i = 0; i < 8; i++) a[i] = As[kk][ty + 16 * i];
#pragma unroll
            for (int j = 0; j < 8; j++) b[j] = Bs[kk][tx + 16 * j];
#pragma unroll
            for (int i = 0; i < 8; i++)
#pragma unroll
                for (int j = 0; j < 8; j++) acc[i][j] += a[i] * b[j];
        }
        __syncthreads();
    }

    float bv[8];
#pragma unroll
    for (int j = 0; j < 8; j++) bv[j] = bias[bn + tx + 16 * j];

#pragma unroll
    for (int i = 0; i < 8; i++) {
        float* Cp = C + (size_t)(bm + ty + 16 * i) * DMODEL + bn;
#pragma unroll
        for (int j = 0; j < 8; j++) Cp[tx + 16 * j] = acc[i][j] + bv[j];
    }
}

// ---------------------------------------------------------------------------
// Flash attention: per (q_tile=64, head, batch) block.
// Q/K tiles padded to stride 132 (fp32-128b vector loads, conflict-free).
// Online softmax; masked entries skipped; all-masked rows -> zero output.
// Mask input is int32 (bool upcast by the harness); packed to bytes in smem.
// ---------------------------------------------------------------------------
#define QSTRIDE 132
#define PSTRIDE 68

__global__ __launch_bounds__(256) void attn_kernel(const int* __restrict__ mask)
{
    extern __shared__ float sm[];
    float* Qs = sm;                       // [64][132]
    float* Ks = Qs + 64 * QSTRIDE;        // [64][132]
    float* Vs = Ks + 64 * QSTRIDE;        // [64][128]
    float* Ps = Vs + 64 * 128;            // [64][68]
    unsigned char* Ms = (unsigned char*)(Ps + 64 * PSTRIDE); // [64][64]

    const int tid = threadIdx.x;
    const int tx  = tid & 15;
    const int ty  = tid >> 4;
    const int q0  = blockIdx.x * 64;
    const int h   = blockIdx.y;
    const int b   = blockIdx.z;

    const float* Qg = g_Q + (size_t)(b * TQL + q0) * DMODEL + h * HD;
    const float* Kg = g_K + (size_t)(b * TKVL) * DMODEL + h * HD;
    const float* Vg = g_V + (size_t)(b * TKVL) * DMODEL + h * HD;
    const int*   Mg = mask + (size_t)(b * TQL + q0) * TKVL;

    // Load Q tile (64x128)
#pragma unroll
    for (int it = 0; it < 8; it++) {
        int idx = tid + it * 256;
        int r = idx >> 5, c4 = (idx & 31) * 4;
        float4 v = *(const float4*)(Qg + (size_t)r * DMODEL + c4);
        *(float4*)&Qs[r * QSTRIDE + c4] = v;
    }

    float m_run[4], l_run[4], acc[4][8];
#pragma unroll
    for (int i = 0; i < 4; i++) {
        m_run[i] = -INFINITY;
        l_run[i] = 0.0f;
#pragma unroll
        for (int j = 0; j < 8; j++) acc[i][j] = 0.0f;
    }

    const float scale = 0.088388347648318447f; // 1/sqrt(128)

    for (int kv0 = 0; kv0 < TKVL; kv0 += 64) {
        __syncthreads(); // previous tile's compute done before overwriting smem

        // Load K, V tiles (64x128 each)
#pragma unroll
        for (int it = 0; it < 8; it++) {
            int idx = tid + it * 256;
            int r = idx >> 5, c4 = (idx & 31) * 4;
            float4 kv = *(const float4*)(Kg + (size_t)(kv0 + r) * DMODEL + c4);
            *(float4*)&Ks[r * QSTRIDE + c4] = kv;
            float4 vv = *(const float4*)(Vg + (size_t)(kv0 + r) * DMODEL + c4);
            *(float4*)&Vs[r * 128 + c4] = vv;
        }
        // Load mask tile (64x64 int32 -> packed bytes in smem)
        {
            int r = tid >> 2, c = (tid & 3) * 16;
            const int* mrow = Mg + (size_t)r * TKVL + kv0 + c;
            unsigned pk[4];
#pragma unroll
            for (int q = 0; q < 4; q++) {
                int4 mv = *(const int4*)(mrow + q * 4);
                pk[q] = (mv.x ? 1u : 0u)
                      | ((mv.y ? 1u : 0u) << 8)
                      | ((mv.z ? 1u : 0u) << 16)
                      | ((mv.w ? 1u : 0u) << 24);
            }
            *(uint4*)&Ms[r * 64 + c] = make_uint4(pk[0], pk[1], pk[2], pk[3]);
        }
        __syncthreads();

        // --- S = Q K^T (64x64), each thread 4 rows (ty*4+i) x 4 cols (tx+16j)
        float s[4][4];
#pragma unroll
        for (int i = 0; i < 4; i++)
#pragma unroll
            for (int j = 0; j < 4; j++) s[i][j] = 0.0f;

#pragma unroll 8
        for (int k4 = 0; k4 < 32; k4++) {
            float4 a[4], bb[4];
#pragma unroll
            for (int i = 0; i < 4; i++)
                a[i] = *(const float4*)&Qs[(ty * 4 + i) * QSTRIDE + k4 * 4];
#pragma unroll
            for (int j = 0; j < 4; j++)
                bb[j] = *(const float4*)&Ks[(tx + 16 * j) * QSTRIDE + k4 * 4];
#pragma unroll
            for (int i = 0; i < 4; i++)
#pragma unroll
                for (int j = 0; j < 4; j++) {
                    s[i][j] += a[i].x * bb[j].x;
                    s[i][j] += a[i].y * bb[j].y;
                    s[i][j] += a[i].z * bb[j].z;
                    s[i][j] += a[i].w * bb[j].w;
                }
        }

        // --- mask + scale + online softmax
#pragma unroll
        for (int i = 0; i < 4; i++) {
            float mm = -INFINITY;
#pragma unroll
            for (int j = 0; j < 4; j++) {
                bool valid = Ms[(ty * 4 + i) * 64 + tx + 16 * j] != 0;
                s[i][j] = valid ? s[i][j] * scale : -INFINITY;
                mm = fmaxf(mm, s[i][j]);
            }
#pragma unroll
            for (int off = 8; off > 0; off >>= 1)
                mm = fmaxf(mm, __shfl_xor_sync(0xffffffffu, mm, off));

            float mnew  = fmaxf(m_run[i], mm);
            float alpha = (m_run[i] == -INFINITY) ? 1.0f : __expf(m_run[i] - mnew);

            float rsum = 0.0f;
#pragma unroll
            for (int j = 0; j < 4; j++) {
                float p = (s[i][j] == -INFINITY) ? 0.0f : __expf(s[i][j] - mnew);
                Ps[(ty * 4 + i) * PSTRIDE + tx + 16 * j] = p;
                rsum += p;
            }
#pragma unroll
            for (int off = 8; off > 0; off >>= 1)
                rsum += __shfl_xor_sync(0xffffffffu, rsum, off);

            l_run[i] = l_run[i] * alpha + rsum;
            m_run[i] = mnew;
#pragma unroll
            for (int j = 0; j < 8; j++) acc[i][j] *= alpha;
        }
        __syncwarp(); // P rows read by the same 16-lane group that wrote them

        // --- acc += P (64x64) @ V (64x128); thread cols = tx+16j, j<8
#pragma unroll 4
        for (int k4 = 0; k4 < 16; k4++) {
            float pr[4][4];
#pragma unroll
            for (int i = 0; i < 4; i++)
                *(float4*)&pr[i][0] =
                    *(const float4*)&Ps[(ty * 4 + i) * PSTRIDE + k4 * 4];
#pragma unroll
            for (int kk = 0; kk < 4; kk++) {
                int k = k4 * 4 + kk;
                float v[8];
#pragma unroll
                for (int j = 0; j < 8; j++) v[j] = Vs[k * 128 + tx + 16 * j];
#pragma unroll
                for (int i = 0; i < 4; i++)
#pragma unroll
                    for (int j = 0; j < 8; j++) acc[i][j] += pr[i][kk] * v[j];
            }
        }
    }

    // --- epilogue: normalize (zero rows whose mask was entirely false)
#pragma unroll
    for (int i = 0; i < 4; i++) {
        float inv = (l_run[i] > 0.0f) ? (1.0f / l_run[i]) : 0.0f;
        float* Og = g_A + (size_t)(b * TQL + q0 + ty * 4 + i) * DMODEL + h * HD;
#pragma unroll
        for (int j = 0; j < 8; j++) Og[tx + 16 * j] = acc[i][j] * inv;
    }
}

// ---------------------------------------------------------------------------
extern "C" void kernel_launch(void* const* d_in, const int* in_sizes, int n_in,
                              void* d_out, int out_size)
{
    (void)in_sizes; (void)n_in; (void)out_size;

    const float* xq   = (const float*)d_in[0];
    const float* xkv  = (const float*)d_in[1];
    const int*   mask = (const int*)d_in[2];     // bool upcast to int32
    const float* Wq = (const float*)d_in[3];
    const float* bq = (const float*)d_in[4];
    const float* Wk = (const float*)d_in[5];
    const float* bk = (const float*)d_in[6];
    const float* Wv = (const float*)d_in[7];
    const float* bv = (const float*)d_in[8];
    const float* Wo = (const float*)d_in[9];
    const float* bo = (const float*)d_in[10];
    float* out = (float*)d_out;

    float *Qd, *Kd, *Vd, *Ad;
    cudaGetSymbolAddress((void**)&Qd, g_Q);
    cudaGetSymbolAddress((void**)&Kd, g_K);
    cudaGetSymbolAddress((void**)&Vd, g_V);
    cudaGetSymbolAddress((void**)&Ad, g_A);

    const int smem_attn = (64 * QSTRIDE * 2 + 64 * 128 + 64 * PSTRIDE) * 4 + 64 * 64;
    static int configured = 0;
    if (!configured) {
        cudaFuncSetAttribute(attn_kernel,
                             cudaFuncAttributeMaxDynamicSharedMemorySize, smem_attn);
        configured = 1;
    }

    dim3 thr(256);
    gemm_bias_kernel<<<dim3(8, 16),  thr>>>(xq,  Wq, bq, Qd);
    gemm_bias_kernel<<<dim3(8, 128), thr>>>(xkv, Wk, bk, Kd);
    gemm_bias_kernel<<<dim3(8, 128), thr>>>(xkv, Wv, bv, Vd);
    attn_kernel<<<dim3(TQL / 64, NH, NB), thr, smem_attn>>>(mask);
    gemm_bias_kernel<<<dim3(8, 16),  thr>>>(Ad, Wo, bo, out);
}

// round 5
// speedup vs baseline: 1.7261x; 1.7261x over previous
#include <cuda_runtime.h>
#include <cuda_bf16.h>
#include <math.h>
#include <float.h>

#define DMODEL 1024
#define NB     4
#define TQL    512
#define TKVL   4096
#define NH     8
#define HD     128

// Scratch (device globals -- no allocation allowed)
__device__ float g_Q[NB * TQL  * DMODEL];
__device__ float g_K[NB * TKVL * DMODEL];
__device__ float g_V[NB * TKVL * DMODEL];
__device__ float g_A[NB * TQL  * DMODEL];

// ===========================================================================
// bf16x3 tensor-core GEMM: C[M,1024] = A[M,1024] @ W[1024,1024] + bias
// fp32 operands split into hi+lo bf16; C = Ah*Wh + Ah*Wl + Al*Wh (fp32 acc).
// Error ~ eps_bf16^2 ~ 1.5e-5 per element. 128x128x32 tile, 8 warps (64x32).
// grid = (1024/128, M/128), block = 256
// ===========================================================================
#define AS 40     // A smem row stride (bf16 elems), 32 used; 80B row, 16B-mult
#define WS 136    // W smem row stride (bf16 elems), 128 used; 272B row

__device__ __forceinline__ unsigned smem_u32(const void* p) {
    return (unsigned)__cvta_generic_to_shared(p);
}
__device__ __forceinline__ void ldsm_x4(unsigned& r0, unsigned& r1,
                                        unsigned& r2, unsigned& r3, unsigned a) {
    asm volatile("ldmatrix.sync.aligned.m8n8.x4.shared.b16 {%0,%1,%2,%3}, [%4];"
                 : "=r"(r0), "=r"(r1), "=r"(r2), "=r"(r3) : "r"(a));
}
__device__ __forceinline__ void ldsm_x2t(unsigned& r0, unsigned& r1, unsigned a) {
    asm volatile("ldmatrix.sync.aligned.m8n8.x2.trans.shared.b16 {%0,%1}, [%2];"
                 : "=r"(r0), "=r"(r1) : "r"(a));
}
__device__ __forceinline__ void mma_bf16(float* d, const unsigned* a, const unsigned* b) {
    asm volatile(
        "mma.sync.aligned.m16n8k16.row.col.f32.bf16.bf16.f32 "
        "{%0,%1,%2,%3}, {%4,%5,%6,%7}, {%8,%9}, {%0,%1,%2,%3};"
        : "+f"(d[0]), "+f"(d[1]), "+f"(d[2]), "+f"(d[3])
        : "r"(a[0]), "r"(a[1]), "r"(a[2]), "r"(a[3]), "r"(b[0]), "r"(b[1]));
}

__global__ __launch_bounds__(256) void gemm_bf16x3_kernel(
    const float* __restrict__ A, const float* __restrict__ W,
    const float* __restrict__ bias, float* __restrict__ C)
{
    __shared__ __align__(16) __nv_bfloat16 AsH[128 * AS];
    __shared__ __align__(16) __nv_bfloat16 AsL[128 * AS];
    __shared__ __align__(16) __nv_bfloat16 WsH[32 * WS];
    __shared__ __align__(16) __nv_bfloat16 WsL[32 * WS];

    const int tid  = threadIdx.x;
    const int lane = tid & 31;
    const int wid  = tid >> 5;
    const int bm   = blockIdx.y * 128;
    const int bn   = blockIdx.x * 128;
    const int wm   = (wid >> 2) * 64;   // warp m-offset (2 warp-rows of 64)
    const int wn   = (wid & 3) * 32;    // warp n-offset (4 warp-cols of 32)

    float acc[4][4][4];
#pragma unroll
    for (int mi = 0; mi < 4; mi++)
#pragma unroll
        for (int nj = 0; nj < 4; nj++)
#pragma unroll
            for (int r = 0; r < 4; r++) acc[mi][nj][r] = 0.0f;

    // gmem->smem load assignments (4 float4 each for A tile and W tile)
    const int a_row = tid >> 3,  a_c4 = (tid & 7) * 4;    // +32 rows per it
    const int w_row = tid >> 5,  w_c4 = (tid & 31) * 4;   // +8 rows per it

    for (int k0 = 0; k0 < DMODEL; k0 += 32) {
        __syncthreads();
        // A tile: 128 x 32 fp32 -> split to bf16 hi/lo
#pragma unroll
        for (int it = 0; it < 4; it++) {
            int r = a_row + it * 32;
            float4 v = *(const float4*)(A + (size_t)(bm + r) * DMODEL + k0 + a_c4);
            __nv_bfloat16 hx = __float2bfloat16(v.x), hy = __float2bfloat16(v.y);
            __nv_bfloat16 hz = __float2bfloat16(v.z), hw = __float2bfloat16(v.w);
            __nv_bfloat16 lx = __float2bfloat16(v.x - __bfloat162float(hx));
            __nv_bfloat16 ly = __float2bfloat16(v.y - __bfloat162float(hy));
            __nv_bfloat16 lz = __float2bfloat16(v.z - __bfloat162float(hz));
            __nv_bfloat16 lw = __float2bfloat16(v.w - __bfloat162float(hw));
            __nv_bfloat162* ph = (__nv_bfloat162*)&AsH[r * AS + a_c4];
            __nv_bfloat162* pl = (__nv_bfloat162*)&AsL[r * AS + a_c4];
            ph[0] = __nv_bfloat162(hx, hy); ph[1] = __nv_bfloat162(hz, hw);
            pl[0] = __nv_bfloat162(lx, ly); pl[1] = __nv_bfloat162(lz, lw);
        }
        // W tile: 32 x 128 fp32 -> split to bf16 hi/lo
#pragma unroll
        for (int it = 0; it < 4; it++) {
            int r = w_row + it * 8;
            float4 v = *(const float4*)(W + (size_t)(k0 + r) * DMODEL + bn + w_c4);
            __nv_bfloat16 hx = __float2bfloat16(v.x), hy = __float2bfloat16(v.y);
            __nv_bfloat16 hz = __float2bfloat16(v.z), hw = __float2bfloat16(v.w);
            __nv_bfloat16 lx = __float2bfloat16(v.x - __bfloat162float(hx));
            __nv_bfloat16 ly = __float2bfloat16(v.y - __bfloat162float(hy));
            __nv_bfloat16 lz = __float2bfloat16(v.z - __bfloat162float(hz));
            __nv_bfloat16 lw = __float2bfloat16(v.w - __bfloat162float(hw));
            __nv_bfloat162* ph = (__nv_bfloat162*)&WsH[r * WS + w_c4];
            __nv_bfloat162* pl = (__nv_bfloat162*)&WsL[r * WS + w_c4];
            ph[0] = __nv_bfloat162(hx, hy); ph[1] = __nv_bfloat162(hz, hw);
            pl[0] = __nv_bfloat162(lx, ly); pl[1] = __nv_bfloat162(lz, lw);
        }
        __syncthreads();

#pragma unroll
        for (int ks = 0; ks < 2; ks++) {
            const int k16 = ks * 16;
            unsigned ah[4][4], al[4][4], bh[4][2], bl[4][2];
            // A fragments (16x16 each): row = lane%16, col-half = lane/16
            const int ar = lane & 15, ac = (lane >> 4) * 8;
#pragma unroll
            for (int mi = 0; mi < 4; mi++) {
                unsigned adH = smem_u32(&AsH[(wm + mi * 16 + ar) * AS + k16 + ac]);
                unsigned adL = smem_u32(&AsL[(wm + mi * 16 + ar) * AS + k16 + ac]);
                ldsm_x4(ah[mi][0], ah[mi][1], ah[mi][2], ah[mi][3], adH);
                ldsm_x4(al[mi][0], al[mi][1], al[mi][2], al[mi][3], adL);
            }
            // B fragments (16x8, trans): row = lane%16 (k), col = wn+nj*8
            const int br = lane & 15;
#pragma unroll
            for (int nj = 0; nj < 4; nj++) {
                unsigned bdH = smem_u32(&WsH[(k16 + br) * WS + wn + nj * 8]);
                unsigned bdL = smem_u32(&WsL[(k16 + br) * WS + wn + nj * 8]);
                ldsm_x2t(bh[nj][0], bh[nj][1], bdH);
                ldsm_x2t(bl[nj][0], bl[nj][1], bdL);
            }
#pragma unroll
            for (int mi = 0; mi < 4; mi++)
#pragma unroll
                for (int nj = 0; nj < 4; nj++) {
                    mma_bf16(acc[mi][nj], ah[mi], bh[nj]);
                    mma_bf16(acc[mi][nj], ah[mi], bl[nj]);
                    mma_bf16(acc[mi][nj], al[mi], bh[nj]);
                }
        }
    }

    // Epilogue: d0,d1 -> (row lane/4, col (lane%4)*2); d2,d3 -> row+8
    const int er = lane >> 2, ec = (lane & 3) * 2;
#pragma unroll
    for (int mi = 0; mi < 4; mi++)
#pragma unroll
        for (int nj = 0; nj < 4; nj++) {
            int row = bm + wm + mi * 16 + er;
            int col = bn + wn + nj * 8 + ec;
            float2 bv = *(const float2*)&bias[col];
            *(float2*)&C[(size_t)row * DMODEL + col] =
                make_float2(acc[mi][nj][0] + bv.x, acc[mi][nj][1] + bv.y);
            *(float2*)&C[(size_t)(row + 8) * DMODEL + col] =
                make_float2(acc[mi][nj][2] + bv.x, acc[mi][nj][3] + bv.y);
        }
}

// ---------------------------------------------------------------------------
// Flash attention: per (q_tile=64, head, batch) block. (unchanged this round)
// ---------------------------------------------------------------------------
#define QSTRIDE 132
#define PSTRIDE 68

__global__ __launch_bounds__(256) void attn_kernel(const int* __restrict__ mask)
{
    extern __shared__ float sm[];
    float* Qs = sm;                       // [64][132]
    float* Ks = Qs + 64 * QSTRIDE;        // [64][132]
    float* Vs = Ks + 64 * QSTRIDE;        // [64][128]
    float* Ps = Vs + 64 * 128;            // [64][68]
    unsigned char* Ms = (unsigned char*)(Ps + 64 * PSTRIDE); // [64][64]

    const int tid = threadIdx.x;
    const int tx  = tid & 15;
    const int ty  = tid >> 4;
    const int q0  = blockIdx.x * 64;
    const int h   = blockIdx.y;
    const int b   = blockIdx.z;

    const float* Qg = g_Q + (size_t)(b * TQL + q0) * DMODEL + h * HD;
    const float* Kg = g_K + (size_t)(b * TKVL) * DMODEL + h * HD;
    const float* Vg = g_V + (size_t)(b * TKVL) * DMODEL + h * HD;
    const int*   Mg = mask + (size_t)(b * TQL + q0) * TKVL;

#pragma unroll
    for (int it = 0; it < 8; it++) {
        int idx = tid + it * 256;
        int r = idx >> 5, c4 = (idx & 31) * 4;
        float4 v = *(const float4*)(Qg + (size_t)r * DMODEL + c4);
        *(float4*)&Qs[r * QSTRIDE + c4] = v;
    }

    float m_run[4], l_run[4], acc[4][8];
#pragma unroll
    for (int i = 0; i < 4; i++) {
        m_run[i] = -INFINITY;
        l_run[i] = 0.0f;
#pragma unroll
        for (int j = 0; j < 8; j++) acc[i][j] = 0.0f;
    }

    const float scale = 0.088388347648318447f; // 1/sqrt(128)

    for (int kv0 = 0; kv0 < TKVL; kv0 += 64) {
        __syncthreads();

#pragma unroll
        for (int it = 0; it < 8; it++) {
            int idx = tid + it * 256;
            int r = idx >> 5, c4 = (idx & 31) * 4;
            float4 kv = *(const float4*)(Kg + (size_t)(kv0 + r) * DMODEL + c4);
            *(float4*)&Ks[r * QSTRIDE + c4] = kv;
            float4 vv = *(const float4*)(Vg + (size_t)(kv0 + r) * DMODEL + c4);
            *(float4*)&Vs[r * 128 + c4] = vv;
        }
        {
            int r = tid >> 2, c = (tid & 3) * 16;
            const int* mrow = Mg + (size_t)r * TKVL + kv0 + c;
            unsigned pk[4];
#pragma unroll
            for (int q = 0; q < 4; q++) {
                int4 mv = *(const int4*)(mrow + q * 4);
                pk[q] = (mv.x ? 1u : 0u)
                      | ((mv.y ? 1u : 0u) << 8)
                      | ((mv.z ? 1u : 0u) << 16)
                      | ((mv.w ? 1u : 0u) << 24);
            }
            *(uint4*)&Ms[r * 64 + c] = make_uint4(pk[0], pk[1], pk[2], pk[3]);
        }
        __syncthreads();

        float s[4][4];
#pragma unroll
        for (int i = 0; i < 4; i++)
#pragma unroll
            for (int j = 0; j < 4; j++) s[i][j] = 0.0f;

#pragma unroll 8
        for (int k4 = 0; k4 < 32; k4++) {
            float4 a[4], bb[4];
#pragma unroll
            for (int i = 0; i < 4; i++)
                a[i] = *(const float4*)&Qs[(ty * 4 + i) * QSTRIDE + k4 * 4];
#pragma unroll
            for (int j = 0; j < 4; j++)
                bb[j] = *(const float4*)&Ks[(tx + 16 * j) * QSTRIDE + k4 * 4];
#pragma unroll
            for (int i = 0; i < 4; i++)
#pragma unroll
                for (int j = 0; j < 4; j++) {
                    s[i][j] += a[i].x * bb[j].x;
                    s[i][j] += a[i].y * bb[j].y;
                    s[i][j] += a[i].z * bb[j].z;
                    s[i][j] += a[i].w * bb[j].w;
                }
        }

#pragma unroll
        for (int i = 0; i < 4; i++) {
            float mm = -INFINITY;
#pragma unroll
            for (int j = 0; j < 4; j++) {
                bool valid = Ms[(ty * 4 + i) * 64 + tx + 16 * j] != 0;
                s[i][j] = valid ? s[i][j] * scale : -INFINITY;
                mm = fmaxf(mm, s[i][j]);
            }
#pragma unroll
            for (int off = 8; off > 0; off >>= 1)
                mm = fmaxf(mm, __shfl_xor_sync(0xffffffffu, mm, off));

            float mnew  = fmaxf(m_run[i], mm);
            float alpha = (m_run[i] == -INFINITY) ? 1.0f : __expf(m_run[i] - mnew);

            float rsum = 0.0f;
#pragma unroll
            for (int j = 0; j < 4; j++) {
                float p = (s[i][j] == -INFINITY) ? 0.0f : __expf(s[i][j] - mnew);
                Ps[(ty * 4 + i) * PSTRIDE + tx + 16 * j] = p;
                rsum += p;
            }
#pragma unroll
            for (int off = 8; off > 0; off >>= 1)
                rsum += __shfl_xor_sync(0xffffffffu, rsum, off);

            l_run[i] = l_run[i] * alpha + rsum;
            m_run[i] = mnew;
#pragma unroll
            for (int j = 0; j < 8; j++) acc[i][j] *= alpha;
        }
        __syncwarp();

#pragma unroll 4
        for (int k4 = 0; k4 < 16; k4++) {
            float pr[4][4];
#pragma unroll
            for (int i = 0; i < 4; i++)
                *(float4*)&pr[i][0] =
                    *(const float4*)&Ps[(ty * 4 + i) * PSTRIDE + k4 * 4];
#pragma unroll
            for (int kk = 0; kk < 4; kk++) {
                int k = k4 * 4 + kk;
                float v[8];
#pragma unroll
                for (int j = 0; j < 8; j++) v[j] = Vs[k * 128 + tx + 16 * j];
#pragma unroll
                for (int i = 0; i < 4; i++)
#pragma unroll
                    for (int j = 0; j < 8; j++) acc[i][j] += pr[i][kk] * v[j];
            }
        }
    }

#pragma unroll
    for (int i = 0; i < 4; i++) {
        float inv = (l_run[i] > 0.0f) ? (1.0f / l_run[i]) : 0.0f;
        float* Og = g_A + (size_t)(b * TQL + q0 + ty * 4 + i) * DMODEL + h * HD;
#pragma unroll
        for (int j = 0; j < 8; j++) Og[tx + 16 * j] = acc[i][j] * inv;
    }
}

// ---------------------------------------------------------------------------
extern "C" void kernel_launch(void* const* d_in, const int* in_sizes, int n_in,
                              void* d_out, int out_size)
{
    (void)in_sizes; (void)n_in; (void)out_size;

    const float* xq   = (const float*)d_in[0];
    const float* xkv  = (const float*)d_in[1];
    const int*   mask = (const int*)d_in[2];     // bool upcast to int32
    const float* Wq = (const float*)d_in[3];
    const float* bq = (const float*)d_in[4];
    const float* Wk = (const float*)d_in[5];
    const float* bk = (const float*)d_in[6];
    const float* Wv = (const float*)d_in[7];
    const float* bv = (const float*)d_in[8];
    const float* Wo = (const float*)d_in[9];
    const float* bo = (const float*)d_in[10];
    float* out = (float*)d_out;

    float *Qd, *Kd, *Vd, *Ad;
    cudaGetSymbolAddress((void**)&Qd, g_Q);
    cudaGetSymbolAddress((void**)&Kd, g_K);
    cudaGetSymbolAddress((void**)&Vd, g_V);
    cudaGetSymbolAddress((void**)&Ad, g_A);

    const int smem_attn = (64 * QSTRIDE * 2 + 64 * 128 + 64 * PSTRIDE) * 4 + 64 * 64;
    static int configured = 0;
    if (!configured) {
        cudaFuncSetAttribute(attn_kernel,
                             cudaFuncAttributeMaxDynamicSharedMemorySize, smem_attn);
        configured = 1;
    }

    dim3 thr(256);
    gemm_bf16x3_kernel<<<dim3(8, 16),  thr>>>(xq,  Wq, bq, Qd);
    gemm_bf16x3_kernel<<<dim3(8, 128), thr>>>(xkv, Wk, bk, Kd);
    gemm_bf16x3_kernel<<<dim3(8, 128), thr>>>(xkv, Wv, bv, Vd);
    attn_kernel<<<dim3(TQL / 64, NH, NB), thr, smem_attn>>>(mask);
    gemm_bf16x3_kernel<<<dim3(8, 16),  thr>>>(Ad, Wo, bo, out);
}

// round 6
// speedup vs baseline: 3.5681x; 2.0672x over previous
#include <cuda_runtime.h>
#include <cuda_bf16.h>
#include <cuda_fp16.h>
#include <math.h>
#include <float.h>

#define DMODEL 1024
#define NB     4
#define TQL    512
#define TKVL   4096
#define NH     8
#define HD     128

// Scratch (device globals -- no allocation allowed)
__device__ __half g_Qh[NB * TQL  * DMODEL];
__device__ __half g_Kh[NB * TKVL * DMODEL];
__device__ __half g_Vh[NB * TKVL * DMODEL];
__device__ float  g_A [NB * TQL  * DMODEL];
__device__ unsigned long long g_Mb[NB * TQL * (TKVL / 64)];

// ===========================================================================
// common mma helpers
// ===========================================================================
__device__ __forceinline__ unsigned smem_u32(const void* p) {
    return (unsigned)__cvta_generic_to_shared(p);
}
__device__ __forceinline__ void ldsm_x4(unsigned& r0, unsigned& r1,
                                        unsigned& r2, unsigned& r3, unsigned a) {
    asm volatile("ldmatrix.sync.aligned.m8n8.x4.shared.b16 {%0,%1,%2,%3}, [%4];"
                 : "=r"(r0), "=r"(r1), "=r"(r2), "=r"(r3) : "r"(a));
}
__device__ __forceinline__ void ldsm_x2(unsigned& r0, unsigned& r1, unsigned a) {
    asm volatile("ldmatrix.sync.aligned.m8n8.x2.shared.b16 {%0,%1}, [%2];"
                 : "=r"(r0), "=r"(r1) : "r"(a));
}
__device__ __forceinline__ void ldsm_x2t(unsigned& r0, unsigned& r1, unsigned a) {
    asm volatile("ldmatrix.sync.aligned.m8n8.x2.trans.shared.b16 {%0,%1}, [%2];"
                 : "=r"(r0), "=r"(r1) : "r"(a));
}
__device__ __forceinline__ void mma_bf16(float* d, const unsigned* a, const unsigned* b) {
    asm volatile(
        "mma.sync.aligned.m16n8k16.row.col.f32.bf16.bf16.f32 "
        "{%0,%1,%2,%3}, {%4,%5,%6,%7}, {%8,%9}, {%0,%1,%2,%3};"
        : "+f"(d[0]), "+f"(d[1]), "+f"(d[2]), "+f"(d[3])
        : "r"(a[0]), "r"(a[1]), "r"(a[2]), "r"(a[3]), "r"(b[0]), "r"(b[1]));
}
__device__ __forceinline__ void mma_f16(float* d, const unsigned* a, const unsigned* b) {
    asm volatile(
        "mma.sync.aligned.m16n8k16.row.col.f32.f16.f16.f32 "
        "{%0,%1,%2,%3}, {%4,%5,%6,%7}, {%8,%9}, {%0,%1,%2,%3};"
        : "+f"(d[0]), "+f"(d[1]), "+f"(d[2]), "+f"(d[3])
        : "r"(a[0]), "r"(a[1]), "r"(a[2]), "r"(a[3]), "r"(b[0]), "r"(b[1]));
}
#define CP_ASYNC16(dst, src) \
    asm volatile("cp.async.cg.shared.global [%0], [%1], 16;" :: "r"(dst), "l"(src))
#define CP_ASYNC8(dst, src) \
    asm volatile("cp.async.ca.shared.global [%0], [%1], 8;"  :: "r"(dst), "l"(src))
#define CP_COMMIT()  asm volatile("cp.async.commit_group;")
#define CP_WAIT0()   asm volatile("cp.async.wait_group 0;")
#define CP_WAIT1()   asm volatile("cp.async.wait_group 1;")

// Fast exp2 (deg-5 poly, magic-number round). Relative err ~2e-6.
// Uses __fadd_rn/__fsub_rn so fast-math can't fold the magic.
__device__ __forceinline__ float exp2p(float x) {
    float xx = fmaxf(x, -80.0f);
    float fk = __fadd_rn(xx, 12582912.0f);
    int   n  = __float_as_int(fk);
    float t  = __fsub_rn(fk, 12582912.0f);
    float f  = __fsub_rn(xx, t);
    float p  = 0.0013333558f;
    p = fmaf(p, f, 0.0096181291f);
    p = fmaf(p, f, 0.0555041087f);
    p = fmaf(p, f, 0.2402265070f);
    p = fmaf(p, f, 0.6931471806f);
    p = fmaf(p, f, 1.0f);
    return __int_as_float(__float_as_int(p) + (n << 23));
}

// ===========================================================================
// mask bit-pack: one ballot per 32 int32 -> 32-bit word
// ===========================================================================
__global__ __launch_bounds__(256) void mask_pack_kernel(const int* __restrict__ m,
                                                        unsigned* __restrict__ out)
{
    const int lane = threadIdx.x & 31;
    const int wg   = (blockIdx.x * 256 + threadIdx.x) >> 5;  // global warp 0..8191
    const int base = wg * 1024;
    unsigned myw = 0;
#pragma unroll
    for (int it = 0; it < 32; it++) {
        int v = m[base + it * 32 + lane];
        unsigned b = __ballot_sync(0xffffffffu, v != 0);
        if (lane == it) myw = b;
    }
    out[wg * 32 + lane] = myw;
}

// ===========================================================================
// bf16x3 tensor-core GEMM: C[M,1024] = A[M,1024] @ W[1024,1024] + bias
// HALFOUT: write __half output (for Q/K/V projections feeding fp16 attention)
// ===========================================================================
#define AS 40
#define WS 136

template<bool HALFOUT>
__global__ __launch_bounds__(256) void gemm_bf16x3_kernel(
    const float* __restrict__ A, const float* __restrict__ W,
    const float* __restrict__ bias, float* __restrict__ C, __half* __restrict__ Ch)
{
    __shared__ __align__(16) __nv_bfloat16 AsH[128 * AS];
    __shared__ __align__(16) __nv_bfloat16 AsL[128 * AS];
    __shared__ __align__(16) __nv_bfloat16 WsH[32 * WS];
    __shared__ __align__(16) __nv_bfloat16 WsL[32 * WS];

    const int tid  = threadIdx.x;
    const int lane = tid & 31;
    const int wid  = tid >> 5;
    const int bm   = blockIdx.y * 128;
    const int bn   = blockIdx.x * 128;
    const int wm   = (wid >> 2) * 64;
    const int wn   = (wid & 3) * 32;

    float acc[4][4][4];
#pragma unroll
    for (int mi = 0; mi < 4; mi++)
#pragma unroll
        for (int nj = 0; nj < 4; nj++)
#pragma unroll
            for (int r = 0; r < 4; r++) acc[mi][nj][r] = 0.0f;

    const int a_row = tid >> 3,  a_c4 = (tid & 7) * 4;
    const int w_row = tid >> 5,  w_c4 = (tid & 31) * 4;

    for (int k0 = 0; k0 < DMODEL; k0 += 32) {
        __syncthreads();
#pragma unroll
        for (int it = 0; it < 4; it++) {
            int r = a_row + it * 32;
            float4 v = *(const float4*)(A + (size_t)(bm + r) * DMODEL + k0 + a_c4);
            __nv_bfloat16 hx = __float2bfloat16(v.x), hy = __float2bfloat16(v.y);
            __nv_bfloat16 hz = __float2bfloat16(v.z), hw = __float2bfloat16(v.w);
            __nv_bfloat16 lx = __float2bfloat16(v.x - __bfloat162float(hx));
            __nv_bfloat16 ly = __float2bfloat16(v.y - __bfloat162float(hy));
            __nv_bfloat16 lz = __float2bfloat16(v.z - __bfloat162float(hz));
            __nv_bfloat16 lw = __float2bfloat16(v.w - __bfloat162float(hw));
            __nv_bfloat162* ph = (__nv_bfloat162*)&AsH[r * AS + a_c4];
            __nv_bfloat162* pl = (__nv_bfloat162*)&AsL[r * AS + a_c4];
            ph[0] = __nv_bfloat162(hx, hy); ph[1] = __nv_bfloat162(hz, hw);
            pl[0] = __nv_bfloat162(lx, ly); pl[1] = __nv_bfloat162(lz, lw);
        }
#pragma unroll
        for (int it = 0; it < 4; it++) {
            int r = w_row + it * 8;
            float4 v = *(const float4*)(W + (size_t)(k0 + r) * DMODEL + bn + w_c4);
            __nv_bfloat16 hx = __float2bfloat16(v.x), hy = __float2bfloat16(v.y);
            __nv_bfloat16 hz = __float2bfloat16(v.z), hw = __float2bfloat16(v.w);
            __nv_bfloat16 lx = __float2bfloat16(v.x - __bfloat162float(hx));
            __nv_bfloat16 ly = __float2bfloat16(v.y - __bfloat162float(hy));
            __nv_bfloat16 lz = __float2bfloat16(v.z - __bfloat162float(hz));
            __nv_bfloat16 lw = __float2bfloat16(v.w - __bfloat162float(hw));
            __nv_bfloat162* ph = (__nv_bfloat162*)&WsH[r * WS + w_c4];
            __nv_bfloat162* pl = (__nv_bfloat162*)&WsL[r * WS + w_c4];
            ph[0] = __nv_bfloat162(hx, hy); ph[1] = __nv_bfloat162(hz, hw);
            pl[0] = __nv_bfloat162(lx, ly); pl[1] = __nv_bfloat162(lz, lw);
        }
        __syncthreads();

#pragma unroll
        for (int ks = 0; ks < 2; ks++) {
            const int k16 = ks * 16;
            unsigned ah[4][4], al[4][4], bh[4][2], bl[4][2];
            const int ar = lane & 15, ac = (lane >> 4) * 8;
#pragma unroll
            for (int mi = 0; mi < 4; mi++) {
                unsigned adH = smem_u32(&AsH[(wm + mi * 16 + ar) * AS + k16 + ac]);
                unsigned adL = smem_u32(&AsL[(wm + mi * 16 + ar) * AS + k16 + ac]);
                ldsm_x4(ah[mi][0], ah[mi][1], ah[mi][2], ah[mi][3], adH);
                ldsm_x4(al[mi][0], al[mi][1], al[mi][2], al[mi][3], adL);
            }
            const int br = lane & 15;
#pragma unroll
            for (int nj = 0; nj < 4; nj++) {
                unsigned bdH = smem_u32(&WsH[(k16 + br) * WS + wn + nj * 8]);
                unsigned bdL = smem_u32(&WsL[(k16 + br) * WS + wn + nj * 8]);
                ldsm_x2t(bh[nj][0], bh[nj][1], bdH);
                ldsm_x2t(bl[nj][0], bl[nj][1], bdL);
            }
#pragma unroll
            for (int mi = 0; mi < 4; mi++)
#pragma unroll
                for (int nj = 0; nj < 4; nj++) {
                    mma_bf16(acc[mi][nj], ah[mi], bh[nj]);
                    mma_bf16(acc[mi][nj], ah[mi], bl[nj]);
                    mma_bf16(acc[mi][nj], al[mi], bh[nj]);
                }
        }
    }

    const int er = lane >> 2, ec = (lane & 3) * 2;
#pragma unroll
    for (int mi = 0; mi < 4; mi++)
#pragma unroll
        for (int nj = 0; nj < 4; nj++) {
            int row = bm + wm + mi * 16 + er;
            int col = bn + wn + nj * 8 + ec;
            float2 bv = *(const float2*)&bias[col];
            float v00 = acc[mi][nj][0] + bv.x, v01 = acc[mi][nj][1] + bv.y;
            float v10 = acc[mi][nj][2] + bv.x, v11 = acc[mi][nj][3] + bv.y;
            if (HALFOUT) {
                *(__half2*)&Ch[(size_t)row * DMODEL + col]       = __floats2half2_rn(v00, v01);
                *(__half2*)&Ch[(size_t)(row + 8) * DMODEL + col] = __floats2half2_rn(v10, v11);
            } else {
                *(float2*)&C[(size_t)row * DMODEL + col]       = make_float2(v00, v01);
                *(float2*)&C[(size_t)(row + 8) * DMODEL + col] = make_float2(v10, v11);
            }
        }
}

// ===========================================================================
// Flash attention v2 (tensor cores, fp16, fp32 acc)
// Block: 256 thr = 8 warps, 128 q-rows (16/warp), kv tiles of 64, dh=128.
// K/V/mask double-buffered via cp.async. P kept in registers (hi+lo fp16).
// grid = (TQL/128, NH, NB)
// ===========================================================================
#define DST 136                      // smem stride in halfs (272B, conflict-free)
#define SQ_BYTES  (128 * DST * 2)    // Q tile
#define SKV_BYTES (64  * DST * 2)    // one K or V buffer

__global__ __launch_bounds__(256, 1) void attn2_kernel()
{
    extern __shared__ __align__(16) char smraw[];
    __half* Qs = (__half*)smraw;
    __half* Ks[2] = { (__half*)(smraw + SQ_BYTES),
                      (__half*)(smraw + SQ_BYTES + SKV_BYTES) };
    __half* Vs[2] = { (__half*)(smraw + SQ_BYTES + 2 * SKV_BYTES),
                      (__half*)(smraw + SQ_BYTES + 3 * SKV_BYTES) };
    unsigned long long* Mb[2] = {
        (unsigned long long*)(smraw + SQ_BYTES + 4 * SKV_BYTES),
        (unsigned long long*)(smraw + SQ_BYTES + 4 * SKV_BYTES + 128 * 8) };

    const int tid  = threadIdx.x;
    const int lane = tid & 31;
    const int wid  = tid >> 5;
    const int wq   = wid * 16;           // warp's q-row base within tile
    const int er   = lane >> 2;
    const int ec   = (lane & 3) * 2;
    const int q0   = blockIdx.x * 128;
    const int h    = blockIdx.y;
    const int b    = blockIdx.z;

    const __half* Qg = g_Qh + (size_t)(b * TQL + q0) * DMODEL + h * HD;
    const __half* Kg = g_Kh + (size_t)(b * TKVL) * DMODEL + h * HD;
    const __half* Vg = g_Vh + (size_t)(b * TKVL) * DMODEL + h * HD;
    const unsigned long long* Mg = g_Mb + (size_t)(b * TQL + q0) * (TKVL / 64);

    // issue cp.async for kv tile 0 into buffer 0
    {
#pragma unroll
        for (int it = 0; it < 4; it++) {
            int c = tid + it * 256;
            int r = c >> 4, c8 = (c & 15) * 8;
            CP_ASYNC16(smem_u32(&Ks[0][r * DST + c8]), Kg + (size_t)r * DMODEL + c8);
            CP_ASYNC16(smem_u32(&Vs[0][r * DST + c8]), Vg + (size_t)r * DMODEL + c8);
        }
        if (tid < 128)
            CP_ASYNC8(smem_u32(&Mb[0][tid]), Mg + (size_t)tid * (TKVL / 64));
        CP_COMMIT();
    }
    // Q tile -> smem (plain loads; barrier below covers it)
#pragma unroll
    for (int it = 0; it < 8; it++) {
        int c = tid + it * 256;
        int r = c >> 4, c8 = (c & 15) * 8;
        *(uint4*)&Qs[r * DST + c8] = *(const uint4*)(Qg + (size_t)r * DMODEL + c8);
    }

    const float YC = 1.4426950408889634f * 0.08838834764831845f; // log2e/sqrt(128)

    float Oacc[16][4];
#pragma unroll
    for (int v = 0; v < 16; v++)
#pragma unroll
        for (int r = 0; r < 4; r++) Oacc[v][r] = 0.0f;
    float m_run[2] = { -12000.0f, -12000.0f };
    float l_run[2] = { 0.0f, 0.0f };

    for (int t = 0; t < TKVL / 64; t++) {
        const int buf = t & 1, nbuf = buf ^ 1;
        if (t + 1 < TKVL / 64) {
            const int kv1 = (t + 1) * 64;
#pragma unroll
            for (int it = 0; it < 4; it++) {
                int c = tid + it * 256;
                int r = c >> 4, c8 = (c & 15) * 8;
                CP_ASYNC16(smem_u32(&Ks[nbuf][r * DST + c8]),
                           Kg + (size_t)(kv1 + r) * DMODEL + c8);
                CP_ASYNC16(smem_u32(&Vs[nbuf][r * DST + c8]),
                           Vg + (size_t)(kv1 + r) * DMODEL + c8);
            }
            if (tid < 128)
                CP_ASYNC8(smem_u32(&Mb[nbuf][tid]),
                          Mg + (size_t)tid * (TKVL / 64) + (kv1 >> 6));
            CP_COMMIT();
            CP_WAIT1();
        } else {
            CP_WAIT0();
        }
        __syncthreads();

        // ---- S = Q K^T : m16 x n64 x k128 per warp
        float sa[8][4];
#pragma unroll
        for (int nj = 0; nj < 8; nj++)
#pragma unroll
            for (int r = 0; r < 4; r++) sa[nj][r] = 0.0f;

#pragma unroll
        for (int kk = 0; kk < 8; kk++) {
            unsigned qa[4];
            ldsm_x4(qa[0], qa[1], qa[2], qa[3],
                    smem_u32(&Qs[(wq + (lane & 15)) * DST + kk * 16 + (lane >> 4) * 8]));
#pragma unroll
            for (int nj = 0; nj < 8; nj++) {
                unsigned kb[2];
                ldsm_x2(kb[0], kb[1],
                        smem_u32(&Ks[buf][(nj * 8 + (lane & 7)) * DST
                                          + kk * 16 + ((lane >> 3) & 1) * 8]));
                mma_f16(sa[nj], qa, kb);
            }
        }

        // ---- online softmax (exp2 poly on fma pipe)
        const unsigned long long mb0 = Mb[buf][wq + er];
        const unsigned long long mb1 = Mb[buf][wq + er + 8];
        float rm0 = -1e30f, rm1 = -1e30f;
#pragma unroll
        for (int nj = 0; nj < 8; nj++) {
            unsigned b0 = (unsigned)(mb0 >> (nj * 8 + ec)) & 3u;
            unsigned b1 = (unsigned)(mb1 >> (nj * 8 + ec)) & 3u;
            float y0 = sa[nj][0] * YC, y1 = sa[nj][1] * YC;
            float y2 = sa[nj][2] * YC, y3 = sa[nj][3] * YC;
            sa[nj][0] = (b0 & 1u) ? y0 : -1e30f;
            sa[nj][1] = (b0 & 2u) ? y1 : -1e30f;
            sa[nj][2] = (b1 & 1u) ? y2 : -1e30f;
            sa[nj][3] = (b1 & 2u) ? y3 : -1e30f;
            rm0 = fmaxf(rm0, fmaxf(sa[nj][0], sa[nj][1]));
            rm1 = fmaxf(rm1, fmaxf(sa[nj][2], sa[nj][3]));
        }
        rm0 = fmaxf(rm0, __shfl_xor_sync(0xffffffffu, rm0, 1));
        rm0 = fmaxf(rm0, __shfl_xor_sync(0xffffffffu, rm0, 2));
        rm1 = fmaxf(rm1, __shfl_xor_sync(0xffffffffu, rm1, 1));
        rm1 = fmaxf(rm1, __shfl_xor_sync(0xffffffffu, rm1, 2));
        float mn0 = fmaxf(fmaxf(m_run[0], rm0), -12000.0f);
        float mn1 = fmaxf(fmaxf(m_run[1], rm1), -12000.0f);
        float al0 = exp2p(m_run[0] - mn0);
        float al1 = exp2p(m_run[1] - mn1);
        m_run[0] = mn0; m_run[1] = mn1;
        l_run[0] *= al0; l_run[1] *= al1;
#pragma unroll
        for (int v = 0; v < 16; v++) {
            Oacc[v][0] *= al0; Oacc[v][1] *= al0;
            Oacc[v][2] *= al1; Oacc[v][3] *= al1;
        }

        unsigned ph[2][8], pl[2][8];
#pragma unroll
        for (int nj = 0; nj < 8; nj++) {
            float p0 = exp2p(sa[nj][0] - mn0);
            float p1 = exp2p(sa[nj][1] - mn0);
            float p2 = exp2p(sa[nj][2] - mn1);
            float p3 = exp2p(sa[nj][3] - mn1);
            l_run[0] += p0 + p1;
            l_run[1] += p2 + p3;
            __half2 h0 = __floats2half2_rn(p0, p1);
            __half2 h1 = __floats2half2_rn(p2, p3);
            float2 b0 = __half22float2(h0);
            float2 b1 = __half22float2(h1);
            ph[0][nj] = *(unsigned*)&h0;
            ph[1][nj] = *(unsigned*)&h1;
            __half2 l0 = __floats2half2_rn(p0 - b0.x, p1 - b0.y);
            __half2 l1 = __floats2half2_rn(p2 - b1.x, p3 - b1.y);
            pl[0][nj] = *(unsigned*)&l0;
            pl[1][nj] = *(unsigned*)&l1;
        }

        // ---- O += P @ V : m16 x n128 x k64, P hi + P lo
#pragma unroll
        for (int kk = 0; kk < 4; kk++) {
            unsigned aH[4] = { ph[0][2 * kk], ph[1][2 * kk],
                               ph[0][2 * kk + 1], ph[1][2 * kk + 1] };
            unsigned aL[4] = { pl[0][2 * kk], pl[1][2 * kk],
                               pl[0][2 * kk + 1], pl[1][2 * kk + 1] };
#pragma unroll
            for (int vj = 0; vj < 16; vj++) {
                unsigned vb[2];
                ldsm_x2t(vb[0], vb[1],
                         smem_u32(&Vs[buf][(kk * 16 + (lane & 15)) * DST + vj * 8]));
                mma_f16(Oacc[vj], aH, vb);
                mma_f16(Oacc[vj], aL, vb);
            }
        }
        __syncthreads();
    }

    // ---- epilogue
    float l0 = l_run[0], l1 = l_run[1];
    l0 += __shfl_xor_sync(0xffffffffu, l0, 1);
    l0 += __shfl_xor_sync(0xffffffffu, l0, 2);
    l1 += __shfl_xor_sync(0xffffffffu, l1, 1);
    l1 += __shfl_xor_sync(0xffffffffu, l1, 2);
    float inv0 = (l0 > 1e-10f) ? (1.0f / l0) : 0.0f;
    float inv1 = (l1 > 1e-10f) ? (1.0f / l1) : 0.0f;
    float* O0 = g_A + (size_t)(b * TQL + q0 + wq + er) * DMODEL + h * HD;
    float* O1 = O0 + 8 * DMODEL;
#pragma unroll
    for (int vj = 0; vj < 16; vj++) {
        *(float2*)&O0[vj * 8 + ec] = make_float2(Oacc[vj][0] * inv0, Oacc[vj][1] * inv0);
        *(float2*)&O1[vj * 8 + ec] = make_float2(Oacc[vj][2] * inv1, Oacc[vj][3] * inv1);
    }
}

// ---------------------------------------------------------------------------
extern "C" void kernel_launch(void* const* d_in, const int* in_sizes, int n_in,
                              void* d_out, int out_size)
{
    (void)in_sizes; (void)n_in; (void)out_size;

    const float* xq   = (const float*)d_in[0];
    const float* xkv  = (const float*)d_in[1];
    const int*   mask = (const int*)d_in[2];     // bool upcast to int32
    const float* Wq = (const float*)d_in[3];
    const float* bq = (const float*)d_in[4];
    const float* Wk = (const float*)d_in[5];
    const float* bk = (const float*)d_in[6];
    const float* Wv = (const float*)d_in[7];
    const float* bv = (const float*)d_in[8];
    const float* Wo = (const float*)d_in[9];
    const float* bo = (const float*)d_in[10];
    float* out = (float*)d_out;

    __half *Qh, *Kh, *Vh;
    float *Ad;
    unsigned long long *Mbp;
    cudaGetSymbolAddress((void**)&Qh,  g_Qh);
    cudaGetSymbolAddress((void**)&Kh,  g_Kh);
    cudaGetSymbolAddress((void**)&Vh,  g_Vh);
    cudaGetSymbolAddress((void**)&Ad,  g_A);
    cudaGetSymbolAddress((void**)&Mbp, g_Mb);

    const int smem_attn = SQ_BYTES + 4 * SKV_BYTES + 2 * 128 * 8;
    static int configured = 0;
    if (!configured) {
        cudaFuncSetAttribute(attn2_kernel,
                             cudaFuncAttributeMaxDynamicSharedMemorySize, smem_attn);
        configured = 1;
    }

    dim3 thr(256);
    mask_pack_kernel<<<1024, thr>>>(mask, (unsigned*)Mbp);
    gemm_bf16x3_kernel<true ><<<dim3(8, 16),  thr>>>(xq,  Wq, bq, nullptr, Qh);
    gemm_bf16x3_kernel<true ><<<dim3(8, 128), thr>>>(xkv, Wk, bk, nullptr, Kh);
    gemm_bf16x3_kernel<true ><<<dim3(8, 128), thr>>>(xkv, Wv, bv, nullptr, Vh);
    attn2_kernel<<<dim3(TQL / 128, NH, NB), thr, smem_attn>>>();
    gemm_bf16x3_kernel<false><<<dim3(8, 16),  thr>>>(Ad, Wo, bo, out, nullptr);
}

// round 9
// speedup vs baseline: 4.2381x; 1.1878x over previous
#include <cuda_runtime.h>
#include <cuda_bf16.h>
#include <cuda_fp16.h>
#include <math.h>
#include <float.h>

#define DMODEL 1024
#define NB     4
#define TQL    512
#define TKVL   4096
#define NH     8
#define HD     128

// --------------------------- device scratch --------------------------------
__device__ __half g_Qh[NB * TQL  * DMODEL];
__device__ __half g_Kh[NB * TKVL * DMODEL];
__device__ __half g_Vh[NB * TKVL * DMODEL];
__device__ float  g_A [NB * TQL  * DMODEL];
__device__ unsigned long long g_Mb[NB * TQL * (TKVL / 64)];

// pre-split operands
__device__ __half g_XqH [NB * TQL  * DMODEL];
__device__ __half g_XqL [NB * TQL  * DMODEL];
__device__ __half g_XkvH[NB * TKVL * DMODEL];
__device__ __half g_XkvL[NB * TKVL * DMODEL];
__device__ __half g_Wqh [DMODEL * DMODEL];
__device__ __half g_Wkh [DMODEL * DMODEL];
__device__ __half g_Wvh [DMODEL * DMODEL];
__device__ __nv_bfloat16 g_WoH[DMODEL * DMODEL];
__device__ __nv_bfloat16 g_WoL[DMODEL * DMODEL];
__device__ __nv_bfloat16 g_AH [NB * TQL * DMODEL];
__device__ __nv_bfloat16 g_AL [NB * TQL * DMODEL];

// ---------------------------- mma helpers ----------------------------------
__device__ __forceinline__ unsigned smem_u32(const void* p) {
    return (unsigned)__cvta_generic_to_shared(p);
}
__device__ __forceinline__ void ldsm_x4(unsigned& r0, unsigned& r1,
                                        unsigned& r2, unsigned& r3, unsigned a) {
    asm volatile("ldmatrix.sync.aligned.m8n8.x4.shared.b16 {%0,%1,%2,%3}, [%4];"
                 : "=r"(r0), "=r"(r1), "=r"(r2), "=r"(r3) : "r"(a));
}
__device__ __forceinline__ void ldsm_x2(unsigned& r0, unsigned& r1, unsigned a) {
    asm volatile("ldmatrix.sync.aligned.m8n8.x2.shared.b16 {%0,%1}, [%2];"
                 : "=r"(r0), "=r"(r1) : "r"(a));
}
__device__ __forceinline__ void ldsm_x2t(unsigned& r0, unsigned& r1, unsigned a) {
    asm volatile("ldmatrix.sync.aligned.m8n8.x2.trans.shared.b16 {%0,%1}, [%2];"
                 : "=r"(r0), "=r"(r1) : "r"(a));
}
__device__ __forceinline__ void mma_bf16(float* d, const unsigned* a, const unsigned* b) {
    asm volatile(
        "mma.sync.aligned.m16n8k16.row.col.f32.bf16.bf16.f32 "
        "{%0,%1,%2,%3}, {%4,%5,%6,%7}, {%8,%9}, {%0,%1,%2,%3};"
        : "+f"(d[0]), "+f"(d[1]), "+f"(d[2]), "+f"(d[3])
        : "r"(a[0]), "r"(a[1]), "r"(a[2]), "r"(a[3]), "r"(b[0]), "r"(b[1]));
}
__device__ __forceinline__ void mma_f16(float* d, const unsigned* a, const unsigned* b) {
    asm volatile(
        "mma.sync.aligned.m16n8k16.row.col.f32.f16.f16.f32 "
        "{%0,%1,%2,%3}, {%4,%5,%6,%7}, {%8,%9}, {%0,%1,%2,%3};"
        : "+f"(d[0]), "+f"(d[1]), "+f"(d[2]), "+f"(d[3])
        : "r"(a[0]), "r"(a[1]), "r"(a[2]), "r"(a[3]), "r"(b[0]), "r"(b[1]));
}
#define CP_ASYNC16(dst, src) \
    asm volatile("cp.async.cg.shared.global [%0], [%1], 16;" :: "r"(dst), "l"(src))
#define CP_ASYNC8(dst, src) \
    asm volatile("cp.async.ca.shared.global [%0], [%1], 8;"  :: "r"(dst), "l"(src))
#define CP_COMMIT()  asm volatile("cp.async.commit_group;")
#define CP_WAIT0()   asm volatile("cp.async.wait_group 0;")
#define CP_WAIT1()   asm volatile("cp.async.wait_group 1;")

// Fast exp2 (deg-5 poly, magic-number round). Relative err ~2e-6.
__device__ __forceinline__ float exp2p(float x) {
    float xx = fmaxf(x, -80.0f);
    float fk = __fadd_rn(xx, 12582912.0f);
    int   n  = __float_as_int(fk);
    float t  = __fsub_rn(fk, 12582912.0f);
    float f  = __fsub_rn(xx, t);
    float p  = 0.0013333558f;
    p = fmaf(p, f, 0.0096181291f);
    p = fmaf(p, f, 0.0555041087f);
    p = fmaf(p, f, 0.2402265070f);
    p = fmaf(p, f, 0.6931471806f);
    p = fmaf(p, f, 1.0f);
    return __int_as_float(__float_as_int(p) + (n << 23));
}

// ======================= pre-split / convert kernels =======================
__global__ __launch_bounds__(256) void split_f16_kernel(
    const float4* __restrict__ x, __half2* __restrict__ hi,
    __half2* __restrict__ lo, int n4)
{
    int i = blockIdx.x * 256 + threadIdx.x;
    if (i >= n4) return;
    float4 v = x[i];
    __half2 h0 = __floats2half2_rn(v.x, v.y);
    __half2 h1 = __floats2half2_rn(v.z, v.w);
    float2 f0 = __half22float2(h0), f1 = __half22float2(h1);
    hi[2 * i]     = h0;
    hi[2 * i + 1] = h1;
    lo[2 * i]     = __floats2half2_rn(v.x - f0.x, v.y - f0.y);
    lo[2 * i + 1] = __floats2half2_rn(v.z - f1.x, v.w - f1.y);
}
__global__ __launch_bounds__(256) void cvt_f16_kernel(
    const float4* __restrict__ x, __half2* __restrict__ out, int n4)
{
    int i = blockIdx.x * 256 + threadIdx.x;
    if (i >= n4) return;
    float4 v = x[i];
    out[2 * i]     = __floats2half2_rn(v.x, v.y);
    out[2 * i + 1] = __floats2half2_rn(v.z, v.w);
}
__global__ __launch_bounds__(256) void split_bf16_kernel(
    const float4* __restrict__ x, __nv_bfloat16* __restrict__ hi,
    __nv_bfloat16* __restrict__ lo, int n4)
{
    int i = blockIdx.x * 256 + threadIdx.x;
    if (i >= n4) return;
    float4 v = x[i];
    __nv_bfloat16 hx = __float2bfloat16(v.x), hy = __float2bfloat16(v.y);
    __nv_bfloat16 hz = __float2bfloat16(v.z), hw = __float2bfloat16(v.w);
    hi[4 * i]     = hx; hi[4 * i + 1] = hy;
    hi[4 * i + 2] = hz; hi[4 * i + 3] = hw;
    lo[4 * i]     = __float2bfloat16(v.x - __bfloat162float(hx));
    lo[4 * i + 1] = __float2bfloat16(v.y - __bfloat162float(hy));
    lo[4 * i + 2] = __float2bfloat16(v.z - __bfloat162float(hz));
    lo[4 * i + 3] = __float2bfloat16(v.w - __bfloat162float(hw));
}

// =========================== mask bit-pack =================================
__global__ __launch_bounds__(256) void mask_pack_kernel(const int* __restrict__ m,
                                                        unsigned* __restrict__ out)
{
    const int lane = threadIdx.x & 31;
    const int wg   = (blockIdx.x * 256 + threadIdx.x) >> 5;
    const int base = wg * 1024;
    unsigned myw = 0;
#pragma unroll
    for (int it = 0; it < 32; it++) {
        int v = m[base + it * 32 + lane];
        unsigned b = __ballot_sync(0xffffffffu, v != 0);
        if (lane == it) myw = b;
    }
    out[wg * 32 + lane] = myw;
}

// ===========================================================================
// fp16x2 GEMM (Q/K/V projections): C = (Ah+Al) @ W + bias, fp16 out.
// Pre-split operands, cp.async 2-stage pipeline, 128x128x32 tiles, 8 warps.
// ===========================================================================
#define AS 40     // A smem row stride (halfs): 80 B, 16B-mult, ldsm conflict-free
#define WS 136    // W smem row stride (halfs): 272 B

#define F16_A_BYTES (128 * AS * 2)            // 10240
#define F16_STAGE   (2 * F16_A_BYTES + 32 * WS * 2)  // AH+AL+W = 29184

__global__ __launch_bounds__(256) void gemm_f16x2_kernel(
    const __half* __restrict__ AH, const __half* __restrict__ AL,
    const __half* __restrict__ W,  const float* __restrict__ bias,
    __half* __restrict__ Ch)
{
    extern __shared__ __align__(16) char smraw[];

    const int tid  = threadIdx.x;
    const int lane = tid & 31;
    const int wid  = tid >> 5;
    const int bm   = blockIdx.y * 128;
    const int bn   = blockIdx.x * 128;
    const int wm   = (wid >> 2) * 64;
    const int wn   = (wid & 3) * 32;

    float acc[4][4][4];
#pragma unroll
    for (int mi = 0; mi < 4; mi++)
#pragma unroll
        for (int nj = 0; nj < 4; nj++)
#pragma unroll
            for (int r = 0; r < 4; r++) acc[mi][nj][r] = 0.0f;

    // cp.async assignments
    const int a_row = tid >> 1,  a_c = (tid & 1) * 16;   // 2x 16B segs per thread
    const int w_row = tid >> 3,  w_c = (tid & 7) * 16;

    const __half* ApH = AH + (size_t)(bm + a_row) * DMODEL + a_c;
    const __half* ApL = AL + (size_t)(bm + a_row) * DMODEL + a_c;
    const __half* Wp  = W  + (size_t)w_row * DMODEL + bn + w_c;

    auto issue = [&](int kt, int st) {
        char* base = smraw + st * F16_STAGE;
        __half* sAH = (__half*)base;
        __half* sAL = (__half*)(base + F16_A_BYTES);
        __half* sW  = (__half*)(base + 2 * F16_A_BYTES);
        const int k0 = kt * 32;
        CP_ASYNC16(smem_u32(&sAH[a_row * AS + a_c]),     ApH + k0);
        CP_ASYNC16(smem_u32(&sAH[a_row * AS + a_c + 8]), ApH + k0 + 8);
        CP_ASYNC16(smem_u32(&sAL[a_row * AS + a_c]),     ApL + k0);
        CP_ASYNC16(smem_u32(&sAL[a_row * AS + a_c + 8]), ApL + k0 + 8);
        CP_ASYNC16(smem_u32(&sW[w_row * WS + w_c]),      Wp + (size_t)k0 * DMODEL);
        CP_ASYNC16(smem_u32(&sW[w_row * WS + w_c + 8]),  Wp + (size_t)k0 * DMODEL + 8);
    };

    issue(0, 0);
    CP_COMMIT();

    const int NT = DMODEL / 32;
    for (int kt = 0; kt < NT; kt++) {
        const int st = kt & 1;
        if (kt + 1 < NT) { issue(kt + 1, st ^ 1); CP_COMMIT(); CP_WAIT1(); }
        else             { CP_WAIT0(); }
        __syncthreads();

        char* base = smraw + st * F16_STAGE;
        __half* sAH = (__half*)base;
        __half* sAL = (__half*)(base + F16_A_BYTES);
        __half* sW  = (__half*)(base + 2 * F16_A_BYTES);

#pragma unroll
        for (int ks = 0; ks < 2; ks++) {
            const int k16 = ks * 16;
            unsigned ah[4][4], al[4][4], bw[4][2];
            const int ar = lane & 15, ac = (lane >> 4) * 8;
#pragma unroll
            for (int mi = 0; mi < 4; mi++) {
                ldsm_x4(ah[mi][0], ah[mi][1], ah[mi][2], ah[mi][3],
                        smem_u32(&sAH[(wm + mi * 16 + ar) * AS + k16 + ac]));
                ldsm_x4(al[mi][0], al[mi][1], al[mi][2], al[mi][3],
                        smem_u32(&sAL[(wm + mi * 16 + ar) * AS + k16 + ac]));
            }
            const int br = lane & 15;
#pragma unroll
            for (int nj = 0; nj < 4; nj++)
                ldsm_x2t(bw[nj][0], bw[nj][1],
                         smem_u32(&sW[(k16 + br) * WS + wn + nj * 8]));
#pragma unroll
            for (int mi = 0; mi < 4; mi++)
#pragma unroll
                for (int nj = 0; nj < 4; nj++) {
                    mma_f16(acc[mi][nj], ah[mi], bw[nj]);
                    mma_f16(acc[mi][nj], al[mi], bw[nj]);
                }
        }
        __syncthreads();
    }

    const int er = lane >> 2, ec = (lane & 3) * 2;
#pragma unroll
    for (int mi = 0; mi < 4; mi++)
#pragma unroll
        for (int nj = 0; nj < 4; nj++) {
            int row = bm + wm + mi * 16 + er;
            int col = bn + wn + nj * 8 + ec;
            float2 bv = *(const float2*)&bias[col];
            *(__half2*)&Ch[(size_t)row * DMODEL + col] =
                __floats2half2_rn(acc[mi][nj][0] + bv.x, acc[mi][nj][1] + bv.y);
            *(__half2*)&Ch[(size_t)(row + 8) * DMODEL + col] =
                __floats2half2_rn(acc[mi][nj][2] + bv.x, acc[mi][nj][3] + bv.y);
        }
}

// ===========================================================================
// bf16x3 GEMM (O projection): pre-split hi/lo both operands, fp32 out.
// ===========================================================================
#define B3_A_BYTES (128 * AS * 2)
#define B3_W_BYTES (32 * WS * 2)
#define B3_STAGE   (2 * B3_A_BYTES + 2 * B3_W_BYTES)   // 37888

__global__ __launch_bounds__(256) void gemm_bf16x3_kernel(
    const __nv_bfloat16* __restrict__ AH, const __nv_bfloat16* __restrict__ AL,
    const __nv_bfloat16* __restrict__ WH, const __nv_bfloat16* __restrict__ WL,
    const float* __restrict__ bias, float* __restrict__ C)
{
    extern __shared__ __align__(16) char smraw[];

    const int tid  = threadIdx.x;
    const int lane = tid & 31;
    const int wid  = tid >> 5;
    const int bm   = blockIdx.y * 128;
    const int bn   = blockIdx.x * 128;
    const int wm   = (wid >> 2) * 64;
    const int wn   = (wid & 3) * 32;

    float acc[4][4][4];
#pragma unroll
    for (int mi = 0; mi < 4; mi++)
#pragma unroll
        for (int nj = 0; nj < 4; nj++)
#pragma unroll
            for (int r = 0; r < 4; r++) acc[mi][nj][r] = 0.0f;

    const int a_row = tid >> 1,  a_c = (tid & 1) * 16;
    const int w_row = tid >> 3,  w_c = (tid & 7) * 16;

    const __nv_bfloat16* ApH = AH + (size_t)(bm + a_row) * DMODEL + a_c;
    const __nv_bfloat16* ApL = AL + (size_t)(bm + a_row) * DMODEL + a_c;
    const __nv_bfloat16* WpH = WH + (size_t)w_row * DMODEL + bn + w_c;
    const __nv_bfloat16* WpL = WL + (size_t)w_row * DMODEL + bn + w_c;

    auto issue = [&](int kt, int st) {
        char* base = smraw + st * B3_STAGE;
        __nv_bfloat16* sAH = (__nv_bfloat16*)base;
        __nv_bfloat16* sAL = (__nv_bfloat16*)(base + B3_A_BYTES);
        __nv_bfloat16* sWH = (__nv_bfloat16*)(base + 2 * B3_A_BYTES);
        __nv_bfloat16* sWL = (__nv_bfloat16*)(base + 2 * B3_A_BYTES + B3_W_BYTES);
        const int k0 = kt * 32;
        CP_ASYNC16(smem_u32(&sAH[a_row * AS + a_c]),     ApH + k0);
        CP_ASYNC16(smem_u32(&sAH[a_row * AS + a_c + 8]), ApH + k0 + 8);
        CP_ASYNC16(smem_u32(&sAL[a_row * AS + a_c]),     ApL + k0);
        CP_ASYNC16(smem_u32(&sAL[a_row * AS + a_c + 8]), ApL + k0 + 8);
        CP_ASYNC16(smem_u32(&sWH[w_row * WS + w_c]),     WpH + (size_t)k0 * DMODEL);
        CP_ASYNC16(smem_u32(&sWH[w_row * WS + w_c + 8]), WpH + (size_t)k0 * DMODEL + 8);
        CP_ASYNC16(smem_u32(&sWL[w_row * WS + w_c]),     WpL + (size_t)k0 * DMODEL);
        CP_ASYNC16(smem_u32(&sWL[w_row * WS + w_c + 8]), WpL + (size_t)k0 * DMODEL + 8);
    };

    issue(0, 0);
    CP_COMMIT();

    const int NT = DMODEL / 32;
    for (int kt = 0; kt < NT; kt++) {
        const int st = kt & 1;
        if (kt + 1 < NT) { issue(kt + 1, st ^ 1); CP_COMMIT(); CP_WAIT1(); }
        else             { CP_WAIT0(); }
        __syncthreads();

        char* base = smraw + st * B3_STAGE;
        __nv_bfloat16* sAH = (__nv_bfloat16*)base;
        __nv_bfloat16* sAL = (__nv_bfloat16*)(base + B3_A_BYTES);
        __nv_bfloat16* sWH = (__nv_bfloat16*)(base + 2 * B3_A_BYTES);
        __nv_bfloat16* sWL = (__nv_bfloat16*)(base + 2 * B3_A_BYTES + B3_W_BYTES);

#pragma unroll
        for (int ks = 0; ks < 2; ks++) {
            const int k16 = ks * 16;
            unsigned ah[4][4], al[4][4], bh[4][2], bl[4][2];
            const int ar = lane & 15, ac = (lane >> 4) * 8;
#pragma unroll
            for (int mi = 0; mi < 4; mi++) {
                ldsm_x4(ah[mi][0], ah[mi][1], ah[mi][2], ah[mi][3],
                        smem_u32(&sAH[(wm + mi * 16 + ar) * AS + k16 + ac]));
                ldsm_x4(al[mi][0], al[mi][1], al[mi][2], al[mi][3],
                        smem_u32(&sAL[(wm + mi * 16 + ar) * AS + k16 + ac]));
            }
            const int br = lane & 15;
#pragma unroll
            for (int nj = 0; nj < 4; nj++) {
                ldsm_x2t(bh[nj][0], bh[nj][1],
                         smem_u32(&sWH[(k16 + br) * WS + wn + nj * 8]));
                ldsm_x2t(bl[nj][0], bl[nj][1],
                         smem_u32(&sWL[(k16 + br) * WS + wn + nj * 8]));
            }
#pragma unroll
            for (int mi = 0; mi < 4; mi++)
#pragma unroll
                for (int nj = 0; nj < 4; nj++) {
                    mma_bf16(acc[mi][nj], ah[mi], bh[nj]);
                    mma_bf16(acc[mi][nj], ah[mi], bl[nj]);
                    mma_bf16(acc[mi][nj], al[mi], bh[nj]);
                }
        }
        __syncthreads();
    }

    const int er = lane >> 2, ec = (lane & 3) * 2;
#pragma unroll
    for (int mi = 0; mi < 4; mi++)
#pragma unroll
        for (int nj = 0; nj < 4; nj++) {
            int row = bm + wm + mi * 16 + er;
            int col = bn + wn + nj * 8 + ec;
            float2 bv = *(const float2*)&bias[col];
            *(float2*)&C[(size_t)row * DMODEL + col] =
                make_float2(acc[mi][nj][0] + bv.x, acc[mi][nj][1] + bv.y);
            *(float2*)&C[(size_t)(row + 8) * DMODEL + col] =
                make_float2(acc[mi][nj][2] + bv.x, acc[mi][nj][3] + bv.y);
        }
}

// ===========================================================================
// Flash attention v2 (tensor cores, fp16, fp32 acc) -- unchanged from R5
// ===========================================================================
#define DST 136
#define SQ_BYTES  (128 * DST * 2)
#define SKV_BYTES (64  * DST * 2)

__global__ __launch_bounds__(256, 1) void attn2_kernel()
{
    extern __shared__ __align__(16) char smraw[];
    __half* Qs = (__half*)smraw;
    __half* Ks[2] = { (__half*)(smraw + SQ_BYTES),
                      (__half*)(smraw + SQ_BYTES + SKV_BYTES) };
    __half* Vs[2] = { (__half*)(smraw + SQ_BYTES + 2 * SKV_BYTES),
                      (__half*)(smraw + SQ_BYTES + 3 * SKV_BYTES) };
    unsigned long long* Mb[2] = {
        (unsigned long long*)(smraw + SQ_BYTES + 4 * SKV_BYTES),
        (unsigned long long*)(smraw + SQ_BYTES + 4 * SKV_BYTES + 128 * 8) };

    const int tid  = threadIdx.x;
    const int lane = tid & 31;
    const int wid  = tid >> 5;
    const int wq   = wid * 16;
    const int er   = lane >> 2;
    const int ec   = (lane & 3) * 2;
    const int q0   = blockIdx.x * 128;
    const int h    = blockIdx.y;
    const int b    = blockIdx.z;

    const __half* Qg = g_Qh + (size_t)(b * TQL + q0) * DMODEL + h * HD;
    const __half* Kg = g_Kh + (size_t)(b * TKVL) * DMODEL + h * HD;
    const __half* Vg = g_Vh + (size_t)(b * TKVL) * DMODEL + h * HD;
    const unsigned long long* Mg = g_Mb + (size_t)(b * TQL + q0) * (TKVL / 64);

    {
#pragma unroll
        for (int it = 0; it < 4; it++) {
            int c = tid + it * 256;
            int r = c >> 4, c8 = (c & 15) * 8;
            CP_ASYNC16(smem_u32(&Ks[0][r * DST + c8]), Kg + (size_t)r * DMODEL + c8);
            CP_ASYNC16(smem_u32(&Vs[0][r * DST + c8]), Vg + (size_t)r * DMODEL + c8);
        }
        if (tid < 128)
            CP_ASYNC8(smem_u32(&Mb[0][tid]), Mg + (size_t)tid * (TKVL / 64));
        CP_COMMIT();
    }
#pragma unroll
    for (int it = 0; it < 8; it++) {
        int c = tid + it * 256;
        int r = c >> 4, c8 = (c & 15) * 8;
        *(uint4*)&Qs[r * DST + c8] = *(const uint4*)(Qg + (size_t)r * DMODEL + c8);
    }

    const float YC = 1.4426950408889634f * 0.08838834764831845f;

    float Oacc[16][4];
#pragma unroll
    for (int v = 0; v < 16; v++)
#pragma unroll
        for (int r = 0; r < 4; r++) Oacc[v][r] = 0.0f;
    float m_run[2] = { -12000.0f, -12000.0f };
    float l_run[2] = { 0.0f, 0.0f };

    for (int t = 0; t < TKVL / 64; t++) {
        const int buf = t & 1, nbuf = buf ^ 1;
        if (t + 1 < TKVL / 64) {
            const int kv1 = (t + 1) * 64;
#pragma unroll
            for (int it = 0; it < 4; it++) {
                int c = tid + it * 256;
                int r = c >> 4, c8 = (c & 15) * 8;
                CP_ASYNC16(smem_u32(&Ks[nbuf][r * DST + c8]),
                           Kg + (size_t)(kv1 + r) * DMODEL + c8);
                CP_ASYNC16(smem_u32(&Vs[nbuf][r * DST + c8]),
                           Vg + (size_t)(kv1 + r) * DMODEL + c8);
            }
            if (tid < 128)
                CP_ASYNC8(smem_u32(&Mb[nbuf][tid]),
                          Mg + (size_t)tid * (TKVL / 64) + (kv1 >> 6));
            CP_COMMIT();
            CP_WAIT1();
        } else {
            CP_WAIT0();
        }
        __syncthreads();

        float sa[8][4];
#pragma unroll
        for (int nj = 0; nj < 8; nj++)
#pragma unroll
            for (int r = 0; r < 4; r++) sa[nj][r] = 0.0f;

#pragma unroll
        for (int kk = 0; kk < 8; kk++) {
            unsigned qa[4];
            ldsm_x4(qa[0], qa[1], qa[2], qa[3],
                    smem_u32(&Qs[(wq + (lane & 15)) * DST + kk * 16 + (lane >> 4) * 8]));
#pragma unroll
            for (int nj = 0; nj < 8; nj++) {
                unsigned kb[2];
                ldsm_x2(kb[0], kb[1],
                        smem_u32(&Ks[buf][(nj * 8 + (lane & 7)) * DST
                                          + kk * 16 + ((lane >> 3) & 1) * 8]));
                mma_f16(sa[nj], qa, kb);
            }
        }

        const unsigned long long mb0 = Mb[buf][wq + er];
        const unsigned long long mb1 = Mb[buf][wq + er + 8];
        float rm0 = -1e30f, rm1 = -1e30f;
#pragma unroll
        for (int nj = 0; nj < 8; nj++) {
            unsigned b0 = (unsigned)(mb0 >> (nj * 8 + ec)) & 3u;
            unsigned b1 = (unsigned)(mb1 >> (nj * 8 + ec)) & 3u;
            float y0 = sa[nj][0] * YC, y1 = sa[nj][1] * YC;
            float y2 = sa[nj][2] * YC, y3 = sa[nj][3] * YC;
            sa[nj][0] = (b0 & 1u) ? y0 : -1e30f;
            sa[nj][1] = (b0 & 2u) ? y1 : -1e30f;
            sa[nj][2] = (b1 & 1u) ? y2 : -1e30f;
            sa[nj][3] = (b1 & 2u) ? y3 : -1e30f;
            rm0 = fmaxf(rm0, fmaxf(sa[nj][0], sa[nj][1]));
            rm1 = fmaxf(rm1, fmaxf(sa[nj][2], sa[nj][3]));
        }
        rm0 = fmaxf(rm0, __shfl_xor_sync(0xffffffffu, rm0, 1));
        rm0 = fmaxf(rm0, __shfl_xor_sync(0xffffffffu, rm0, 2));
        rm1 = fmaxf(rm1, __shfl_xor_sync(0xffffffffu, rm1, 1));
        rm1 = fmaxf(rm1, __shfl_xor_sync(0xffffffffu, rm1, 2));
        float mn0 = fmaxf(fmaxf(m_run[0], rm0), -12000.0f);
        float mn1 = fmaxf(fmaxf(m_run[1], rm1), -12000.0f);
        float al0 = exp2p(m_run[0] - mn0);
        float al1 = exp2p(m_run[1] - mn1);
        m_run[0] = mn0; m_run[1] = mn1;
        l_run[0] *= al0; l_run[1] *= al1;
#pragma unroll
        for (int v = 0; v < 16; v++) {
            Oacc[v][0] *= al0; Oacc[v][1] *= al0;
            Oacc[v][2] *= al1; Oacc[v][3] *= al1;
        }

        unsigned ph[2][8], pl[2][8];
#pragma unroll
        for (int nj = 0; nj < 8; nj++) {
            float p0 = exp2p(sa[nj][0] - mn0);
            float p1 = exp2p(sa[nj][1] - mn0);
            float p2 = exp2p(sa[nj][2] - mn1);
            float p3 = exp2p(sa[nj][3] - mn1);
            l_run[0] += p0 + p1;
            l_run[1] += p2 + p3;
            __half2 h0 = __floats2half2_rn(p0, p1);
            __half2 h1 = __floats2half2_rn(p2, p3);
            float2 b0 = __half22float2(h0);
            float2 b1 = __half22float2(h1);
            ph[0][nj] = *(unsigned*)&h0;
            ph[1][nj] = *(unsigned*)&h1;
            __half2 l0 = __floats2half2_rn(p0 - b0.x, p1 - b0.y);
            __half2 l1 = __floats2half2_rn(p2 - b1.x, p3 - b1.y);
            pl[0][nj] = *(unsigned*)&l0;
            pl[1][nj] = *(unsigned*)&l1;
        }

#pragma unroll
        for (int kk = 0; kk < 4; kk++) {
            unsigned aH[4] = { ph[0][2 * kk], ph[1][2 * kk],
                               ph[0][2 * kk + 1], ph[1][2 * kk + 1] };
            unsigned aL[4] = { pl[0][2 * kk], pl[1][2 * kk],
                               pl[0][2 * kk + 1], pl[1][2 * kk + 1] };
#pragma unroll
            for (int vj = 0; vj < 16; vj++) {
                unsigned vb[2];
                ldsm_x2t(vb[0], vb[1],
                         smem_u32(&Vs[buf][(kk * 16 + (lane & 15)) * DST + vj * 8]));
                mma_f16(Oacc[vj], aH, vb);
                mma_f16(Oacc[vj], aL, vb);
            }
        }
        __syncthreads();
    }

    float l0 = l_run[0], l1 = l_run[1];
    l0 += __shfl_xor_sync(0xffffffffu, l0, 1);
    l0 += __shfl_xor_sync(0xffffffffu, l0, 2);
    l1 += __shfl_xor_sync(0xffffffffu, l1, 1);
    l1 += __shfl_xor_sync(0xffffffffu, l1, 2);
    float inv0 = (l0 > 1e-10f) ? (1.0f / l0) : 0.0f;
    float inv1 = (l1 > 1e-10f) ? (1.0f / l1) : 0.0f;
    float* O0 = g_A + (size_t)(b * TQL + q0 + wq + er) * DMODEL + h * HD;
    float* O1 = O0 + 8 * DMODEL;
#pragma unroll
    for (int vj = 0; vj < 16; vj++) {
        *(float2*)&O0[vj * 8 + ec] = make_float2(Oacc[vj][0] * inv0, Oacc[vj][1] * inv0);
        *(float2*)&O1[vj * 8 + ec] = make_float2(Oacc[vj][2] * inv1, Oacc[vj][3] * inv1);
    }
}

// ---------------------------------------------------------------------------
extern "C" void kernel_launch(void* const* d_in, const int* in_sizes, int n_in,
                              void* d_out, int out_size)
{
    (void)in_sizes; (void)n_in; (void)out_size;

    const float* xq   = (const float*)d_in[0];
    const float* xkv  = (const float*)d_in[1];
    const int*   mask = (const int*)d_in[2];
    const float* Wq = (const float*)d_in[3];
    const float* bq = (const float*)d_in[4];
    const float* Wk = (const float*)d_in[5];
    const float* bk = (const float*)d_in[6];
    const float* Wv = (const float*)d_in[7];
    const float* bv = (const float*)d_in[8];
    const float* Wo = (const float*)d_in[9];
    const float* bo = (const float*)d_in[10];
    float* out = (float*)d_out;

    __half *Qh, *Kh, *Vh, *XqH, *XqL, *XkvH, *XkvL, *Wqh, *Wkh, *Wvh;
    __nv_bfloat16 *WoH, *WoL, *AHp, *ALp;
    float *Ad;
    unsigned long long *Mbp;
    cudaGetSymbolAddress((void**)&Qh,   g_Qh);
    cudaGetSymbolAddress((void**)&Kh,   g_Kh);
    cudaGetSymbolAddress((void**)&Vh,   g_Vh);
    cudaGetSymbolAddress((void**)&Ad,   g_A);
    cudaGetSymbolAddress((void**)&Mbp,  g_Mb);
    cudaGetSymbolAddress((void**)&XqH,  g_XqH);
    cudaGetSymbolAddress((void**)&XqL,  g_XqL);
    cudaGetSymbolAddress((void**)&XkvH, g_XkvH);
    cudaGetSymbolAddress((void**)&XkvL, g_XkvL);
    cudaGetSymbolAddress((void**)&Wqh,  g_Wqh);
    cudaGetSymbolAddress((void**)&Wkh,  g_Wkh);
    cudaGetSymbolAddress((void**)&Wvh,  g_Wvh);
    cudaGetSymbolAddress((void**)&WoH,  g_WoH);
    cudaGetSymbolAddress((void**)&WoL,  g_WoL);
    cudaGetSymbolAddress((void**)&AHp,  g_AH);
    cudaGetSymbolAddress((void**)&ALp,  g_AL);

    const int smem_attn = SQ_BYTES + 4 * SKV_BYTES + 2 * 128 * 8;
    const int smem_f16  = 2 * F16_STAGE;
    const int smem_b3   = 2 * B3_STAGE;
    static int configured = 0;
    if (!configured) {
        cudaFuncSetAttribute(attn2_kernel,
                             cudaFuncAttributeMaxDynamicSharedMemorySize, smem_attn);
        cudaFuncSetAttribute(gemm_f16x2_kernel,
                             cudaFuncAttributeMaxDynamicSharedMemorySize, smem_f16);
        cudaFuncSetAttribute(gemm_bf16x3_kernel,
                             cudaFuncAttributeMaxDynamicSharedMemorySize, smem_b3);
        configured = 1;
    }

    dim3 thr(256);
    const int nW4  = DMODEL * DMODEL / 4;          // 262144
    const int nXq4 = NB * TQL * DMODEL / 4;        // 524288
    const int nXk4 = NB * TKVL * DMODEL / 4;       // 4194304

    mask_pack_kernel<<<1024, thr>>>(mask, (unsigned*)Mbp);
    split_f16_kernel<<<nXq4 / 256, thr>>>((const float4*)xq,  (__half2*)XqH,  (__half2*)XqL,  nXq4);
    split_f16_kernel<<<nXk4 / 256, thr>>>((const float4*)xkv, (__half2*)XkvH, (__half2*)XkvL, nXk4);
    cvt_f16_kernel<<<nW4 / 256, thr>>>((const float4*)Wq, (__half2*)Wqh, nW4);
    cvt_f16_kernel<<<nW4 / 256, thr>>>((const float4*)Wk, (__half2*)Wkh, nW4);
    cvt_f16_kernel<<<nW4 / 256, thr>>>((const float4*)Wv, (__half2*)Wvh, nW4);
    split_bf16_kernel<<<nW4 / 256, thr>>>((const float4*)Wo, WoH, WoL, nW4);

    gemm_f16x2_kernel<<<dim3(8, 16),  thr, smem_f16>>>(XqH,  XqL,  Wqh, bq, Qh);
    gemm_f16x2_kernel<<<dim3(8, 128), thr, smem_f16>>>(XkvH, XkvL, Wkh, bk, Kh);
    gemm_f16x2_kernel<<<dim3(8, 128), thr, smem_f16>>>(XkvH, XkvL, Wvh, bv, Vh);

    attn2_kernel<<<dim3(TQL / 128, NH, NB), thr, smem_attn>>>();

    split_bf16_kernel<<<nXq4 / 256, thr>>>((const float4*)Ad, AHp, ALp, nXq4);
    gemm_bf16x3_kernel<<<dim3(8, 16), thr, smem_b3>>>(AHp, ALp, WoH, WoL, bo, out);
}

// round 11
// speedup vs baseline: 5.5980x; 1.3209x over previous
#include <cuda_runtime.h>
#include <cuda_bf16.h>
#include <cuda_fp16.h>
#include <math.h>
#include <float.h>

#define DMODEL 1024
#define NB     4
#define TQL    512
#define TKVL   4096
#define NH     8
#define HD     128

// --------------------------- device scratch --------------------------------
__device__ __half g_Qh[NB * TQL  * DMODEL];
__device__ __half g_Kh[NB * TKVL * DMODEL];
__device__ __half g_Vh[NB * TKVL * DMODEL];
__device__ float  g_A [NB * TQL  * DMODEL];
__device__ unsigned long long g_Mb[NB * TQL * (TKVL / 64)];

// pre-converted operands
__device__ __half g_Xqh [NB * TQL  * DMODEL];
__device__ __half g_Xkvh[NB * TKVL * DMODEL];
__device__ __half g_Wqh [DMODEL * DMODEL];
__device__ __half g_Wkh [DMODEL * DMODEL];
__device__ __half g_Wvh [DMODEL * DMODEL];
__device__ __nv_bfloat16 g_WoH[DMODEL * DMODEL];
__device__ __nv_bfloat16 g_WoL[DMODEL * DMODEL];
__device__ __nv_bfloat16 g_AH [NB * TQL * DMODEL];
__device__ __nv_bfloat16 g_AL [NB * TQL * DMODEL];

// ---------------------------- mma helpers ----------------------------------
__device__ __forceinline__ unsigned smem_u32(const void* p) {
    return (unsigned)__cvta_generic_to_shared(p);
}
__device__ __forceinline__ void ldsm_x4(unsigned& r0, unsigned& r1,
                                        unsigned& r2, unsigned& r3, unsigned a) {
    asm volatile("ldmatrix.sync.aligned.m8n8.x4.shared.b16 {%0,%1,%2,%3}, [%4];"
                 : "=r"(r0), "=r"(r1), "=r"(r2), "=r"(r3) : "r"(a));
}
__device__ __forceinline__ void ldsm_x2(unsigned& r0, unsigned& r1, unsigned a) {
    asm volatile("ldmatrix.sync.aligned.m8n8.x2.shared.b16 {%0,%1}, [%2];"
                 : "=r"(r0), "=r"(r1) : "r"(a));
}
__device__ __forceinline__ void ldsm_x2t(unsigned& r0, unsigned& r1, unsigned a) {
    asm volatile("ldmatrix.sync.aligned.m8n8.x2.trans.shared.b16 {%0,%1}, [%2];"
                 : "=r"(r0), "=r"(r1) : "r"(a));
}
__device__ __forceinline__ void mma_bf16(float* d, const unsigned* a, const unsigned* b) {
    asm volatile(
        "mma.sync.aligned.m16n8k16.row.col.f32.bf16.bf16.f32 "
        "{%0,%1,%2,%3}, {%4,%5,%6,%7}, {%8,%9}, {%0,%1,%2,%3};"
        : "+f"(d[0]), "+f"(d[1]), "+f"(d[2]), "+f"(d[3])
        : "r"(a[0]), "r"(a[1]), "r"(a[2]), "r"(a[3]), "r"(b[0]), "r"(b[1]));
}
__device__ __forceinline__ void mma_f16(float* d, const unsigned* a, const unsigned* b) {
    asm volatile(
        "mma.sync.aligned.m16n8k16.row.col.f32.f16.f16.f32 "
        "{%0,%1,%2,%3}, {%4,%5,%6,%7}, {%8,%9}, {%0,%1,%2,%3};"
        : "+f"(d[0]), "+f"(d[1]), "+f"(d[2]), "+f"(d[3])
        : "r"(a[0]), "r"(a[1]), "r"(a[2]), "r"(a[3]), "r"(b[0]), "r"(b[1]));
}
#define CP_ASYNC16(dst, src) \
    asm volatile("cp.async.cg.shared.global [%0], [%1], 16;" :: "r"(dst), "l"(src))
#define CP_ASYNC8(dst, src) \
    asm volatile("cp.async.ca.shared.global [%0], [%1], 8;"  :: "r"(dst), "l"(src))
#define CP_COMMIT()  asm volatile("cp.async.commit_group;")
#define CP_WAIT0()   asm volatile("cp.async.wait_group 0;")
#define CP_WAIT1()   asm volatile("cp.async.wait_group 1;")

// Fast exp2 (deg-5 poly, magic-number round). Relative err ~2e-6.
__device__ __forceinline__ float exp2p(float x) {
    float xx = fmaxf(x, -80.0f);
    float fk = __fadd_rn(xx, 12582912.0f);
    int   n  = __float_as_int(fk);
    float t  = __fsub_rn(fk, 12582912.0f);
    float f  = __fsub_rn(xx, t);
    float p  = 0.0013333558f;
    p = fmaf(p, f, 0.0096181291f);
    p = fmaf(p, f, 0.0555041087f);
    p = fmaf(p, f, 0.2402265070f);
    p = fmaf(p, f, 0.6931471806f);
    p = fmaf(p, f, 1.0f);
    return __int_as_float(__float_as_int(p) + (n << 23));
}

// ======================= convert / split kernels ===========================
__global__ __launch_bounds__(256) void cvt_f16_kernel(
    const float4* __restrict__ x, __half2* __restrict__ out, int n4)
{
    int i = blockIdx.x * 256 + threadIdx.x;
    int stride = gridDim.x * 256;
    for (; i < n4; i += stride) {
        float4 v = x[i];
        out[2 * i]     = __floats2half2_rn(v.x, v.y);
        out[2 * i + 1] = __floats2half2_rn(v.z, v.w);
    }
}
__global__ __launch_bounds__(256) void split_bf16_kernel(
    const float4* __restrict__ x, __nv_bfloat16* __restrict__ hi,
    __nv_bfloat16* __restrict__ lo, int n4)
{
    int i = blockIdx.x * 256 + threadIdx.x;
    if (i >= n4) return;
    float4 v = x[i];
    __nv_bfloat16 hx = __float2bfloat16(v.x), hy = __float2bfloat16(v.y);
    __nv_bfloat16 hz = __float2bfloat16(v.z), hw = __float2bfloat16(v.w);
    hi[4 * i]     = hx; hi[4 * i + 1] = hy;
    hi[4 * i + 2] = hz; hi[4 * i + 3] = hw;
    lo[4 * i]     = __float2bfloat16(v.x - __bfloat162float(hx));
    lo[4 * i + 1] = __float2bfloat16(v.y - __bfloat162float(hy));
    lo[4 * i + 2] = __float2bfloat16(v.z - __bfloat162float(hz));
    lo[4 * i + 3] = __float2bfloat16(v.w - __bfloat162float(hw));
}

// =========================== mask bit-pack =================================
__global__ __launch_bounds__(256) void mask_pack_kernel(const int* __restrict__ m,
                                                        unsigned* __restrict__ out)
{
    const int lane = threadIdx.x & 31;
    const int wg   = (blockIdx.x * 256 + threadIdx.x) >> 5;
    const int base = wg * 1024;
    unsigned myw = 0;
#pragma unroll
    for (int it = 0; it < 32; it++) {
        int v = m[base + it * 32 + lane];
        unsigned b = __ballot_sync(0xffffffffu, v != 0);
        if (lane == it) myw = b;
    }
    out[wg * 32 + lane] = myw;
}

// ===========================================================================
// fp16 GEMM (Q/K/V projections): C = A @ W + bias, fp16 in/out, fp32 acc.
// cp.async 2-stage pipeline, 128x128x32 tiles, 8 warps (64x32 per warp).
// ===========================================================================
#define AS 40     // A smem row stride (halfs): 80 B
#define WS 136    // W smem row stride (halfs): 272 B

#define F16_A_BYTES (128 * AS * 2)                 // 10240
#define F16_STAGE   (F16_A_BYTES + 32 * WS * 2)    // A + W = 18944

__global__ __launch_bounds__(256) void gemm_f16_kernel(
    const __half* __restrict__ A, const __half* __restrict__ W,
    const float* __restrict__ bias, __half* __restrict__ Ch)
{
    extern __shared__ __align__(16) char smraw[];

    const int tid  = threadIdx.x;
    const int lane = tid & 31;
    const int wid  = tid >> 5;
    const int bm   = blockIdx.y * 128;
    const int bn   = blockIdx.x * 128;
    const int wm   = (wid >> 2) * 64;
    const int wn   = (wid & 3) * 32;

    float acc[4][4][4];
#pragma unroll
    for (int mi = 0; mi < 4; mi++)
#pragma unroll
        for (int nj = 0; nj < 4; nj++)
#pragma unroll
            for (int r = 0; r < 4; r++) acc[mi][nj][r] = 0.0f;

    const int a_row = tid >> 1,  a_c = (tid & 1) * 16;
    const int w_row = tid >> 3,  w_c = (tid & 7) * 16;

    const __half* Ap = A + (size_t)(bm + a_row) * DMODEL + a_c;
    const __half* Wp = W + (size_t)w_row * DMODEL + bn + w_c;

    auto issue = [&](int kt, int st) {
        char* base = smraw + st * F16_STAGE;
        __half* sA = (__half*)base;
        __half* sW = (__half*)(base + F16_A_BYTES);
        const int k0 = kt * 32;
        CP_ASYNC16(smem_u32(&sA[a_row * AS + a_c]),     Ap + k0);
        CP_ASYNC16(smem_u32(&sA[a_row * AS + a_c + 8]), Ap + k0 + 8);
        CP_ASYNC16(smem_u32(&sW[w_row * WS + w_c]),     Wp + (size_t)k0 * DMODEL);
        CP_ASYNC16(smem_u32(&sW[w_row * WS + w_c + 8]), Wp + (size_t)k0 * DMODEL + 8);
    };

    issue(0, 0);
    CP_COMMIT();

    const int NT = DMODEL / 32;
    for (int kt = 0; kt < NT; kt++) {
        const int st = kt & 1;
        if (kt + 1 < NT) { issue(kt + 1, st ^ 1); CP_COMMIT(); CP_WAIT1(); }
        else             { CP_WAIT0(); }
        __syncthreads();

        char* base = smraw + st * F16_STAGE;
        __half* sA = (__half*)base;
        __half* sW = (__half*)(base + F16_A_BYTES);

#pragma unroll
        for (int ks = 0; ks < 2; ks++) {
            const int k16 = ks * 16;
            unsigned ah[4][4], bw[4][2];
            const int ar = lane & 15, ac = (lane >> 4) * 8;
#pragma unroll
            for (int mi = 0; mi < 4; mi++)
                ldsm_x4(ah[mi][0], ah[mi][1], ah[mi][2], ah[mi][3],
                        smem_u32(&sA[(wm + mi * 16 + ar) * AS + k16 + ac]));
            const int br = lane & 15;
#pragma unroll
            for (int nj = 0; nj < 4; nj++)
                ldsm_x2t(bw[nj][0], bw[nj][1],
                         smem_u32(&sW[(k16 + br) * WS + wn + nj * 8]));
#pragma unroll
            for (int mi = 0; mi < 4; mi++)
#pragma unroll
                for (int nj = 0; nj < 4; nj++)
                    mma_f16(acc[mi][nj], ah[mi], bw[nj]);
        }
        __syncthreads();
    }

    const int er = lane >> 2, ec = (lane & 3) * 2;
#pragma unroll
    for (int mi = 0; mi < 4; mi++)
#pragma unroll
        for (int nj = 0; nj < 4; nj++) {
            int row = bm + wm + mi * 16 + er;
            int col = bn + wn + nj * 8 + ec;
            float2 bv = *(const float2*)&bias[col];
            *(__half2*)&Ch[(size_t)row * DMODEL + col] =
                __floats2half2_rn(acc[mi][nj][0] + bv.x, acc[mi][nj][1] + bv.y);
            *(__half2*)&Ch[(size_t)(row + 8) * DMODEL + col] =
                __floats2half2_rn(acc[mi][nj][2] + bv.x, acc[mi][nj][3] + bv.y);
        }
}

// ===========================================================================
// bf16x3 GEMM (O projection): pre-split hi/lo both operands, fp32 out.
// ===========================================================================
#define B3_A_BYTES (128 * AS * 2)
#define B3_W_BYTES (32 * WS * 2)
#define B3_STAGE   (2 * B3_A_BYTES + 2 * B3_W_BYTES)

__global__ __launch_bounds__(256) void gemm_bf16x3_kernel(
    const __nv_bfloat16* __restrict__ AH, const __nv_bfloat16* __restrict__ AL,
    const __nv_bfloat16* __restrict__ WH, const __nv_bfloat16* __restrict__ WL,
    const float* __restrict__ bias, float* __restrict__ C)
{
    extern __shared__ __align__(16) char smraw[];

    const int tid  = threadIdx.x;
    const int lane = tid & 31;
    const int wid  = tid >> 5;
    const int bm   = blockIdx.y * 128;
    const int bn   = blockIdx.x * 128;
    const int wm   = (wid >> 2) * 64;
    const int wn   = (wid & 3) * 32;

    float acc[4][4][4];
#pragma unroll
    for (int mi = 0; mi < 4; mi++)
#pragma unroll
        for (int nj = 0; nj < 4; nj++)
#pragma unroll
            for (int r = 0; r < 4; r++) acc[mi][nj][r] = 0.0f;

    const int a_row = tid >> 1,  a_c = (tid & 1) * 16;
    const int w_row = tid >> 3,  w_c = (tid & 7) * 16;

    const __nv_bfloat16* ApH = AH + (size_t)(bm + a_row) * DMODEL + a_c;
    const __nv_bfloat16* ApL = AL + (size_t)(bm + a_row) * DMODEL + a_c;
    const __nv_bfloat16* WpH = WH + (size_t)w_row * DMODEL + bn + w_c;
    const __nv_bfloat16* WpL = WL + (size_t)w_row * DMODEL + bn + w_c;

    auto issue = [&](int kt, int st) {
        char* base = smraw + st * B3_STAGE;
        __nv_bfloat16* sAH = (__nv_bfloat16*)base;
        __nv_bfloat16* sAL = (__nv_bfloat16*)(base + B3_A_BYTES);
        __nv_bfloat16* sWH = (__nv_bfloat16*)(base + 2 * B3_A_BYTES);
        __nv_bfloat16* sWL = (__nv_bfloat16*)(base + 2 * B3_A_BYTES + B3_W_BYTES);
        const int k0 = kt * 32;
        CP_ASYNC16(smem_u32(&sAH[a_row * AS + a_c]),     ApH + k0);
        CP_ASYNC16(smem_u32(&sAH[a_row * AS + a_c + 8]), ApH + k0 + 8);
        CP_ASYNC16(smem_u32(&sAL[a_row * AS + a_c]),     ApL + k0);
        CP_ASYNC16(smem_u32(&sAL[a_row * AS + a_c + 8]), ApL + k0 + 8);
        CP_ASYNC16(smem_u32(&sWH[w_row * WS + w_c]),     WpH + (size_t)k0 * DMODEL);
        CP_ASYNC16(smem_u32(&sWH[w_row * WS + w_c + 8]), WpH + (size_t)k0 * DMODEL + 8);
        CP_ASYNC16(smem_u32(&sWL[w_row * WS + w_c]),     WpL + (size_t)k0 * DMODEL);
        CP_ASYNC16(smem_u32(&sWL[w_row * WS + w_c + 8]), WpL + (size_t)k0 * DMODEL + 8);
    };

    issue(0, 0);
    CP_COMMIT();

    const int NT = DMODEL / 32;
    for (int kt = 0; kt < NT; kt++) {
        const int st = kt & 1;
        if (kt + 1 < NT) { issue(kt + 1, st ^ 1); CP_COMMIT(); CP_WAIT1(); }
        else             { CP_WAIT0(); }
        __syncthreads();

        char* base = smraw + st * B3_STAGE;
        __nv_bfloat16* sAH = (__nv_bfloat16*)base;
        __nv_bfloat16* sAL = (__nv_bfloat16*)(base + B3_A_BYTES);
        __nv_bfloat16* sWH = (__nv_bfloat16*)(base + 2 * B3_A_BYTES);
        __nv_bfloat16* sWL = (__nv_bfloat16*)(base + 2 * B3_A_BYTES + B3_W_BYTES);

#pragma unroll
        for (int ks = 0; ks < 2; ks++) {
            const int k16 = ks * 16;
            unsigned ah[4][4], al[4][4], bh[4][2], bl[4][2];
            const int ar = lane & 15, ac = (lane >> 4) * 8;
#pragma unroll
            for (int mi = 0; mi < 4; mi++) {
                ldsm_x4(ah[mi][0], ah[mi][1], ah[mi][2], ah[mi][3],
                        smem_u32(&sAH[(wm + mi * 16 + ar) * AS + k16 + ac]));
                ldsm_x4(al[mi][0], al[mi][1], al[mi][2], al[mi][3],
                        smem_u32(&sAL[(wm + mi * 16 + ar) * AS + k16 + ac]));
            }
            const int br = lane & 15;
#pragma unroll
            for (int nj = 0; nj < 4; nj++) {
                ldsm_x2t(bh[nj][0], bh[nj][1],
                         smem_u32(&sWH[(k16 + br) * WS + wn + nj * 8]));
                ldsm_x2t(bl[nj][0], bl[nj][1],
                         smem_u32(&sWL[(k16 + br) * WS + wn + nj * 8]));
            }
#pragma unroll
            for (int mi = 0; mi < 4; mi++)
#pragma unroll
                for (int nj = 0; nj < 4; nj++) {
                    mma_bf16(acc[mi][nj], ah[mi], bh[nj]);
                    mma_bf16(acc[mi][nj], ah[mi], bl[nj]);
                    mma_bf16(acc[mi][nj], al[mi], bh[nj]);
                }
        }
        __syncthreads();
    }

    const int er = lane >> 2, ec = (lane & 3) * 2;
#pragma unroll
    for (int mi = 0; mi < 4; mi++)
#pragma unroll
        for (int nj = 0; nj < 4; nj++) {
            int row = bm + wm + mi * 16 + er;
            int col = bn + wn + nj * 8 + ec;
            float2 bv = *(const float2*)&bias[col];
            *(float2*)&C[(size_t)row * DMODEL + col] =
                make_float2(acc[mi][nj][0] + bv.x, acc[mi][nj][1] + bv.y);
            *(float2*)&C[(size_t)(row + 8) * DMODEL + col] =
                make_float2(acc[mi][nj][2] + bv.x, acc[mi][nj][3] + bv.y);
        }
}

// ===========================================================================
// Flash attention v2 (tensor cores, fp16, fp32 acc)
// ===========================================================================
#define DST 136
#define SQ_BYTES  (128 * DST * 2)
#define SKV_BYTES (64  * DST * 2)

__global__ __launch_bounds__(256, 1) void attn2_kernel()
{
    extern __shared__ __align__(16) char smraw[];
    __half* Qs = (__half*)smraw;
    __half* Ks[2] = { (__half*)(smraw + SQ_BYTES),
                      (__half*)(smraw + SQ_BYTES + SKV_BYTES) };
    __half* Vs[2] = { (__half*)(smraw + SQ_BYTES + 2 * SKV_BYTES),
                      (__half*)(smraw + SQ_BYTES + 3 * SKV_BYTES) };
    unsigned long long* Mb[2] = {
        (unsigned long long*)(smraw + SQ_BYTES + 4 * SKV_BYTES),
        (unsigned long long*)(smraw + SQ_BYTES + 4 * SKV_BYTES + 128 * 8) };

    const int tid  = threadIdx.x;
    const int lane = tid & 31;
    const int wid  = tid >> 5;
    const int wq   = wid * 16;
    const int er   = lane >> 2;
    const int ec   = (lane & 3) * 2;
    const int q0   = blockIdx.x * 128;
    const int h    = blockIdx.y;
    const int b    = blockIdx.z;

    const __half* Qg = g_Qh + (size_t)(b * TQL + q0) * DMODEL + h * HD;
    const __half* Kg = g_Kh + (size_t)(b * TKVL) * DMODEL + h * HD;
    const __half* Vg = g_Vh + (size_t)(b * TKVL) * DMODEL + h * HD;
    const unsigned long long* Mg = g_Mb + (size_t)(b * TQL + q0) * (TKVL / 64);

    {
#pragma unroll
        for (int it = 0; it < 4; it++) {
            int c = tid + it * 256;
            int r = c >> 4, c8 = (c & 15) * 8;
            CP_ASYNC16(smem_u32(&Ks[0][r * DST + c8]), Kg + (size_t)r * DMODEL + c8);
            CP_ASYNC16(smem_u32(&Vs[0][r * DST + c8]), Vg + (size_t)r * DMODEL + c8);
        }
        if (tid < 128)
            CP_ASYNC8(smem_u32(&Mb[0][tid]), Mg + (size_t)tid * (TKVL / 64));
        CP_COMMIT();
    }
#pragma unroll
    for (int it = 0; it < 8; it++) {
        int c = tid + it * 256;
        int r = c >> 4, c8 = (c & 15) * 8;
        *(uint4*)&Qs[r * DST + c8] = *(const uint4*)(Qg + (size_t)r * DMODEL + c8);
    }

    const float YC = 1.4426950408889634f * 0.08838834764831845f;

    float Oacc[16][4];
#pragma unroll
    for (int v = 0; v < 16; v++)
#pragma unroll
        for (int r = 0; r < 4; r++) Oacc[v][r] = 0.0f;
    float m_run[2] = { -12000.0f, -12000.0f };
    float l_run[2] = { 0.0f, 0.0f };

    for (int t = 0; t < TKVL / 64; t++) {
        const int buf = t & 1, nbuf = buf ^ 1;
        if (t + 1 < TKVL / 64) {
            const int kv1 = (t + 1) * 64;
#pragma unroll
            for (int it = 0; it < 4; it++) {
                int c = tid + it * 256;
                int r = c >> 4, c8 = (c & 15) * 8;
                CP_ASYNC16(smem_u32(&Ks[nbuf][r * DST + c8]),
                           Kg + (size_t)(kv1 + r) * DMODEL + c8);
                CP_ASYNC16(smem_u32(&Vs[nbuf][r * DST + c8]),
                           Vg + (size_t)(kv1 + r) * DMODEL + c8);
            }
            if (tid < 128)
                CP_ASYNC8(smem_u32(&Mb[nbuf][tid]),
                          Mg + (size_t)tid * (TKVL / 64) + (kv1 >> 6));
            CP_COMMIT();
            CP_WAIT1();
        } else {
            CP_WAIT0();
        }
        __syncthreads();

        float sa[8][4];
#pragma unroll
        for (int nj = 0; nj < 8; nj++)
#pragma unroll
            for (int r = 0; r < 4; r++) sa[nj][r] = 0.0f;

#pragma unroll
        for (int kk = 0; kk < 8; kk++) {
            unsigned qa[4];
            ldsm_x4(qa[0], qa[1], qa[2], qa[3],
                    smem_u32(&Qs[(wq + (lane & 15)) * DST + kk * 16 + (lane >> 4) * 8]));
#pragma unroll
            for (int nj = 0; nj < 8; nj++) {
                unsigned kb[2];
                ldsm_x2(kb[0], kb[1],
                        smem_u32(&Ks[buf][(nj * 8 + (lane & 7)) * DST
                                          + kk * 16 + ((lane >> 3) & 1) * 8]));
                mma_f16(sa[nj], qa, kb);
            }
        }

        const unsigned long long mb0 = Mb[buf][wq + er];
        const unsigned long long mb1 = Mb[buf][wq + er + 8];
        float rm0 = -1e30f, rm1 = -1e30f;
#pragma unroll
        for (int nj = 0; nj < 8; nj++) {
            unsigned b0 = (unsigned)(mb0 >> (nj * 8 + ec)) & 3u;
            unsigned b1 = (unsigned)(mb1 >> (nj * 8 + ec)) & 3u;
            float y0 = sa[nj][0] * YC, y1 = sa[nj][1] * YC;
            float y2 = sa[nj][2] * YC, y3 = sa[nj][3] * YC;
            sa[nj][0] = (b0 & 1u) ? y0 : -1e30f;
            sa[nj][1] = (b0 & 2u) ? y1 : -1e30f;
            sa[nj][2] = (b1 & 1u) ? y2 : -1e30f;
            sa[nj][3] = (b1 & 2u) ? y3 : -1e30f;
            rm0 = fmaxf(rm0, fmaxf(sa[nj][0], sa[nj][1]));
            rm1 = fmaxf(rm1, fmaxf(sa[nj][2], sa[nj][3]));
        }
        rm0 = fmaxf(rm0, __shfl_xor_sync(0xffffffffu, rm0, 1));
        rm0 = fmaxf(rm0, __shfl_xor_sync(0xffffffffu, rm0, 2));
        rm1 = fmaxf(rm1, __shfl_xor_sync(0xffffffffu, rm1, 1));
        rm1 = fmaxf(rm1, __shfl_xor_sync(0xffffffffu, rm1, 2));
        float mn0 = fmaxf(fmaxf(m_run[0], rm0), -12000.0f);
        float mn1 = fmaxf(fmaxf(m_run[1], rm1), -12000.0f);
        float al0 = exp2p(m_run[0] - mn0);
        float al1 = exp2p(m_run[1] - mn1);
        m_run[0] = mn0; m_run[1] = mn1;
        l_run[0] *= al0; l_run[1] *= al1;
#pragma unroll
        for (int v = 0; v < 16; v++) {
            Oacc[v][0] *= al0; Oacc[v][1] *= al0;
            Oacc[v][2] *= al1; Oacc[v][3] *= al1;
        }

        unsigned ph[2][8], pl[2][8];
#pragma unroll
        for (int nj = 0; nj < 8; nj++) {
            float p0 = exp2p(sa[nj][0] - mn0);
            float p1 = exp2p(sa[nj][1] - mn0);
            float p2 = exp2p(sa[nj][2] - mn1);
            float p3 = exp2p(sa[nj][3] - mn1);
            l_run[0] += p0 + p1;
            l_run[1] += p2 + p3;
            __half2 h0 = __floats2half2_rn(p0, p1);
            __half2 h1 = __floats2half2_rn(p2, p3);
            float2 b0 = __half22float2(h0);
            float2 b1 = __half22float2(h1);
            ph[0][nj] = *(unsigned*)&h0;
            ph[1][nj] = *(unsigned*)&h1;
            __half2 l0 = __floats2half2_rn(p0 - b0.x, p1 - b0.y);
            __half2 l1 = __floats2half2_rn(p2 - b1.x, p3 - b1.y);
            pl[0][nj] = *(unsigned*)&l0;
            pl[1][nj] = *(unsigned*)&l1;
        }

#pragma unroll
        for (int kk = 0; kk < 4; kk++) {
            unsigned aH[4] = { ph[0][2 * kk], ph[1][2 * kk],
                               ph[0][2 * kk + 1], ph[1][2 * kk + 1] };
            unsigned aL[4] = { pl[0][2 * kk], pl[1][2 * kk],
                               pl[0][2 * kk + 1], pl[1][2 * kk + 1] };
#pragma unroll
            for (int vj = 0; vj < 16; vj++) {
                unsigned vb[2];
                ldsm_x2t(vb[0], vb[1],
                         smem_u32(&Vs[buf][(kk * 16 + (lane & 15)) * DST + vj * 8]));
                mma_f16(Oacc[vj], aH, vb);
                mma_f16(Oacc[vj], aL, vb);
            }
        }
        __syncthreads();
    }

    float l0 = l_run[0], l1 = l_run[1];
    l0 += __shfl_xor_sync(0xffffffffu, l0, 1);
    l0 += __shfl_xor_sync(0xffffffffu, l0, 2);
    l1 += __shfl_xor_sync(0xffffffffu, l1, 1);
    l1 += __shfl_xor_sync(0xffffffffu, l1, 2);
    float inv0 = (l0 > 1e-10f) ? (1.0f / l0) : 0.0f;
    float inv1 = (l1 > 1e-10f) ? (1.0f / l1) : 0.0f;
    float* O0 = g_A + (size_t)(b * TQL + q0 + wq + er) * DMODEL + h * HD;
    float* O1 = O0 + 8 * DMODEL;
#pragma unroll
    for (int vj = 0; vj < 16; vj++) {
        *(float2*)&O0[vj * 8 + ec] = make_float2(Oacc[vj][0] * inv0, Oacc[vj][1] * inv0);
        *(float2*)&O1[vj * 8 + ec] = make_float2(Oacc[vj][2] * inv1, Oacc[vj][3] * inv1);
    }
}

// ---------------------------------------------------------------------------
extern "C" void kernel_launch(void* const* d_in, const int* in_sizes, int n_in,
                              void* d_out, int out_size)
{
    (void)in_sizes; (void)n_in; (void)out_size;

    const float* xq   = (const float*)d_in[0];
    const float* xkv  = (const float*)d_in[1];
    const int*   mask = (const int*)d_in[2];
    const float* Wq = (const float*)d_in[3];
    const float* bq = (const float*)d_in[4];
    const float* Wk = (const float*)d_in[5];
    const float* bk = (const float*)d_in[6];
    const float* Wv = (const float*)d_in[7];
    const float* bv = (const float*)d_in[8];
    const float* Wo = (const float*)d_in[9];
    const float* bo = (const float*)d_in[10];
    float* out = (float*)d_out;

    __half *Qh, *Kh, *Vh, *Xqh, *Xkvh, *Wqh, *Wkh, *Wvh;
    __nv_bfloat16 *WoH, *WoL, *AHp, *ALp;
    float *Ad;
    unsigned long long *Mbp;
    cudaGetSymbolAddress((void**)&Qh,   g_Qh);
    cudaGetSymbolAddress((void**)&Kh,   g_Kh);
    cudaGetSymbolAddress((void**)&Vh,   g_Vh);
    cudaGetSymbolAddress((void**)&Ad,   g_A);
    cudaGetSymbolAddress((void**)&Mbp,  g_Mb);
    cudaGetSymbolAddress((void**)&Xqh,  g_Xqh);
    cudaGetSymbolAddress((void**)&Xkvh, g_Xkvh);
    cudaGetSymbolAddress((void**)&Wqh,  g_Wqh);
    cudaGetSymbolAddress((void**)&Wkh,  g_Wkh);
    cudaGetSymbolAddress((void**)&Wvh,  g_Wvh);
    cudaGetSymbolAddress((void**)&WoH,  g_WoH);
    cudaGetSymbolAddress((void**)&WoL,  g_WoL);
    cudaGetSymbolAddress((void**)&AHp,  g_AH);
    cudaGetSymbolAddress((void**)&ALp,  g_AL);

    const int smem_attn = SQ_BYTES + 4 * SKV_BYTES + 2 * 128 * 8;
    const int smem_f16  = 2 * F16_STAGE;
    const int smem_b3   = 2 * B3_STAGE;
    static int configured = 0;
    if (!configured) {
        cudaFuncSetAttribute(attn2_kernel,
                             cudaFuncAttributeMaxDynamicSharedMemorySize, smem_attn);
        cudaFuncSetAttribute(gemm_f16_kernel,
                             cudaFuncAttributeMaxDynamicSharedMemorySize, smem_f16);
        cudaFuncSetAttribute(gemm_bf16x3_kernel,
                             cudaFuncAttributeMaxDynamicSharedMemorySize, smem_b3);
        configured = 1;
    }

    dim3 thr(256);
    const int nW4  = DMODEL * DMODEL / 4;          // 262144
    const int nXq4 = NB * TQL * DMODEL / 4;        // 524288
    const int nXk4 = NB * TKVL * DMODEL / 4;       // 4194304

    mask_pack_kernel<<<1024, thr>>>(mask, (unsigned*)Mbp);
    cvt_f16_kernel<<<1024, thr>>>((const float4*)xq,  (__half2*)Xqh,  nXq4);
    cvt_f16_kernel<<<2048, thr>>>((const float4*)xkv, (__half2*)Xkvh, nXk4);
    cvt_f16_kernel<<<512,  thr>>>((const float4*)Wq, (__half2*)Wqh, nW4);
    cvt_f16_kernel<<<512,  thr>>>((const float4*)Wk, (__half2*)Wkh, nW4);
    cvt_f16_kernel<<<512,  thr>>>((const float4*)Wv, (__half2*)Wvh, nW4);
    split_bf16_kernel<<<nW4 / 256, thr>>>((const float4*)Wo, WoH, WoL, nW4);

    gemm_f16_kernel<<<dim3(8, 16),  thr, smem_f16>>>(Xqh,  Wqh, bq, Qh);
    gemm_f16_kernel<<<dim3(8, 128), thr, smem_f16>>>(Xkvh, Wkh, bk, Kh);
    gemm_f16_kernel<<<dim3(8, 128), thr, smem_f16>>>(Xkvh, Wvh, bv, Vh);

    attn2_kernel<<<dim3(TQL / 128, NH, NB), thr, smem_attn>>>();

    split_bf16_kernel<<<nXq4 / 256, thr>>>((const float4*)Ad, AHp, ALp, nXq4);
    gemm_bf16x3_kernel<<<dim3(8, 16), thr, smem_b3>>>(AHp, ALp, WoH, WoL, bo, out);
}

// round 12
// speedup vs baseline: 6.0157x; 1.0746x over previous
#include <cuda_runtime.h>
#include <cuda_bf16.h>
#include <cuda_fp16.h>
#include <math.h>
#include <float.h>

#define DMODEL 1024
#define NB     4
#define TQL    512
#define TKVL   4096
#define NH     8
#define HD     128

// --------------------------- device scratch --------------------------------
__device__ __half g_Qh[NB * TQL  * DMODEL];
__device__ __half g_Kh[NB * TKVL * DMODEL];
__device__ __half g_Vh[NB * TKVL * DMODEL];
__device__ float  g_A [NB * TQL  * DMODEL];
__device__ unsigned long long g_Mb[NB * TQL * (TKVL / 64)];

// pre-converted operands
__device__ __half g_Xqh [NB * TQL  * DMODEL];
__device__ __half g_Xkvh[NB * TKVL * DMODEL];
__device__ __half g_Wqh [DMODEL * DMODEL];
__device__ __half g_Wkh [DMODEL * DMODEL];
__device__ __half g_Wvh [DMODEL * DMODEL];
__device__ __nv_bfloat16 g_WoH[DMODEL * DMODEL];
__device__ __nv_bfloat16 g_WoL[DMODEL * DMODEL];
__device__ __nv_bfloat16 g_AH [NB * TQL * DMODEL];
__device__ __nv_bfloat16 g_AL [NB * TQL * DMODEL];

// ---------------------------- mma helpers ----------------------------------
__device__ __forceinline__ unsigned smem_u32(const void* p) {
    return (unsigned)__cvta_generic_to_shared(p);
}
__device__ __forceinline__ void ldsm_x4(unsigned& r0, unsigned& r1,
                                        unsigned& r2, unsigned& r3, unsigned a) {
    asm volatile("ldmatrix.sync.aligned.m8n8.x4.shared.b16 {%0,%1,%2,%3}, [%4];"
                 : "=r"(r0), "=r"(r1), "=r"(r2), "=r"(r3) : "r"(a));
}
__device__ __forceinline__ void ldsm_x2(unsigned& r0, unsigned& r1, unsigned a) {
    asm volatile("ldmatrix.sync.aligned.m8n8.x2.shared.b16 {%0,%1}, [%2];"
                 : "=r"(r0), "=r"(r1) : "r"(a));
}
__device__ __forceinline__ void ldsm_x2t(unsigned& r0, unsigned& r1, unsigned a) {
    asm volatile("ldmatrix.sync.aligned.m8n8.x2.trans.shared.b16 {%0,%1}, [%2];"
                 : "=r"(r0), "=r"(r1) : "r"(a));
}
__device__ __forceinline__ void mma_bf16(float* d, const unsigned* a, const unsigned* b) {
    asm volatile(
        "mma.sync.aligned.m16n8k16.row.col.f32.bf16.bf16.f32 "
        "{%0,%1,%2,%3}, {%4,%5,%6,%7}, {%8,%9}, {%0,%1,%2,%3};"
        : "+f"(d[0]), "+f"(d[1]), "+f"(d[2]), "+f"(d[3])
        : "r"(a[0]), "r"(a[1]), "r"(a[2]), "r"(a[3]), "r"(b[0]), "r"(b[1]));
}
__device__ __forceinline__ void mma_f16(float* d, const unsigned* a, const unsigned* b) {
    asm volatile(
        "mma.sync.aligned.m16n8k16.row.col.f32.f16.f16.f32 "
        "{%0,%1,%2,%3}, {%4,%5,%6,%7}, {%8,%9}, {%0,%1,%2,%3};"
        : "+f"(d[0]), "+f"(d[1]), "+f"(d[2]), "+f"(d[3])
        : "r"(a[0]), "r"(a[1]), "r"(a[2]), "r"(a[3]), "r"(b[0]), "r"(b[1]));
}
#define CP_ASYNC16(dst, src) \
    asm volatile("cp.async.cg.shared.global [%0], [%1], 16;" :: "r"(dst), "l"(src))
#define CP_ASYNC8(dst, src) \
    asm volatile("cp.async.ca.shared.global [%0], [%1], 8;"  :: "r"(dst), "l"(src))
#define CP_COMMIT()  asm volatile("cp.async.commit_group;")
#define CP_WAIT0()   asm volatile("cp.async.wait_group 0;")
#define CP_WAIT1()   asm volatile("cp.async.wait_group 1;")

// Fast exp2 (deg-5 poly, magic-number round). Relative err ~2e-6.
__device__ __forceinline__ float exp2p(float x) {
    float xx = fmaxf(x, -80.0f);
    float fk = __fadd_rn(xx, 12582912.0f);
    int   n  = __float_as_int(fk);
    float t  = __fsub_rn(fk, 12582912.0f);
    float f  = __fsub_rn(xx, t);
    float p  = 0.0013333558f;
    p = fmaf(p, f, 0.0096181291f);
    p = fmaf(p, f, 0.0555041087f);
    p = fmaf(p, f, 0.2402265070f);
    p = fmaf(p, f, 0.6931471806f);
    p = fmaf(p, f, 1.0f);
    return __int_as_float(__float_as_int(p) + (n << 23));
}

// ======================= convert / split kernels ===========================
__device__ __forceinline__ uint4 pack_f16x8(float4 a, float4 b) {
    __half2 h0 = __floats2half2_rn(a.x, a.y), h1 = __floats2half2_rn(a.z, a.w);
    __half2 h2 = __floats2half2_rn(b.x, b.y), h3 = __floats2half2_rn(b.z, b.w);
    uint4 u;
    u.x = *(unsigned*)&h0; u.y = *(unsigned*)&h1;
    u.z = *(unsigned*)&h2; u.w = *(unsigned*)&h3;
    return u;
}

// 8 floats per thread, 16B stores
__global__ __launch_bounds__(256) void cvt_f16_kernel(
    const float4* __restrict__ x, uint4* __restrict__ out, int n8)
{
    int i = blockIdx.x * 256 + threadIdx.x;
    int stride = gridDim.x * 256;
    for (; i < n8; i += stride)
        out[i] = pack_f16x8(x[2 * i], x[2 * i + 1]);
}

// three weight matrices in one launch
__global__ __launch_bounds__(256) void cvt3_f16_kernel(
    const float4* __restrict__ w0, const float4* __restrict__ w1,
    const float4* __restrict__ w2,
    uint4* __restrict__ o0, uint4* __restrict__ o1, uint4* __restrict__ o2,
    int n8)
{
    int i = blockIdx.x * 256 + threadIdx.x;
    int stride = gridDim.x * 256;
    int total = 3 * n8;
    for (; i < total; i += stride) {
        int m = i / n8, j = i - m * n8;
        const float4* w = (m == 0) ? w0 : (m == 1) ? w1 : w2;
        uint4* o = (m == 0) ? o0 : (m == 1) ? o1 : o2;
        o[j] = pack_f16x8(w[2 * j], w[2 * j + 1]);
    }
}

// bf16 hi/lo split, 8 floats per thread, 16B stores
__global__ __launch_bounds__(256) void split_bf16_kernel(
    const float4* __restrict__ x, uint4* __restrict__ hi,
    uint4* __restrict__ lo, int n8)
{
    int i = blockIdx.x * 256 + threadIdx.x;
    int stride = gridDim.x * 256;
    for (; i < n8; i += stride) {
        float4 a = x[2 * i], b = x[2 * i + 1];
        float v[8] = { a.x, a.y, a.z, a.w, b.x, b.y, b.z, b.w };
        __nv_bfloat16 h[8], l[8];
#pragma unroll
        for (int k = 0; k < 8; k++) {
            h[k] = __float2bfloat16(v[k]);
            l[k] = __float2bfloat16(v[k] - __bfloat162float(h[k]));
        }
        uint4 uh, ul;
        __nv_bfloat162 t;
        t = __nv_bfloat162(h[0], h[1]); uh.x = *(unsigned*)&t;
        t = __nv_bfloat162(h[2], h[3]); uh.y = *(unsigned*)&t;
        t = __nv_bfloat162(h[4], h[5]); uh.z = *(unsigned*)&t;
        t = __nv_bfloat162(h[6], h[7]); uh.w = *(unsigned*)&t;
        t = __nv_bfloat162(l[0], l[1]); ul.x = *(unsigned*)&t;
        t = __nv_bfloat162(l[2], l[3]); ul.y = *(unsigned*)&t;
        t = __nv_bfloat162(l[4], l[5]); ul.z = *(unsigned*)&t;
        t = __nv_bfloat162(l[6], l[7]); ul.w = *(unsigned*)&t;
        hi[i] = uh;
        lo[i] = ul;
    }
}

// =========================== mask bit-pack =================================
__global__ __launch_bounds__(256) void mask_pack_kernel(const int* __restrict__ m,
                                                        unsigned* __restrict__ out)
{
    const int lane = threadIdx.x & 31;
    const int wg   = (blockIdx.x * 256 + threadIdx.x) >> 5;
    const int base = wg * 1024;
    unsigned myw = 0;
#pragma unroll
    for (int it = 0; it < 32; it++) {
        int v = m[base + it * 32 + lane];
        unsigned b = __ballot_sync(0xffffffffu, v != 0);
        if (lane == it) myw = b;
    }
    out[wg * 32 + lane] = myw;
}

// ===========================================================================
// fp16 GEMM (Q/K/V projections): C = A @ W + bias, fp16 in/out, fp32 acc.
// cp.async 2-stage pipeline, 128x128x32 tiles, 8 warps (64x32 per warp).
// ===========================================================================
#define AS 40     // A smem row stride (halfs): 80 B
#define WS 136    // W smem row stride (halfs): 272 B

#define F16_A_BYTES (128 * AS * 2)                 // 10240
#define F16_STAGE   (F16_A_BYTES + 32 * WS * 2)    // A + W = 18944

__global__ __launch_bounds__(256) void gemm_f16_kernel(
    const __half* __restrict__ A, const __half* __restrict__ W,
    const float* __restrict__ bias, __half* __restrict__ Ch)
{
    extern __shared__ __align__(16) char smraw[];

    const int tid  = threadIdx.x;
    const int lane = tid & 31;
    const int wid  = tid >> 5;
    const int bm   = blockIdx.y * 128;
    const int bn   = blockIdx.x * 128;
    const int wm   = (wid >> 2) * 64;
    const int wn   = (wid & 3) * 32;

    float acc[4][4][4];
#pragma unroll
    for (int mi = 0; mi < 4; mi++)
#pragma unroll
        for (int nj = 0; nj < 4; nj++)
#pragma unroll
            for (int r = 0; r < 4; r++) acc[mi][nj][r] = 0.0f;

    const int a_row = tid >> 1,  a_c = (tid & 1) * 16;
    const int w_row = tid >> 3,  w_c = (tid & 7) * 16;

    const __half* Ap = A + (size_t)(bm + a_row) * DMODEL + a_c;
    const __half* Wp = W + (size_t)w_row * DMODEL + bn + w_c;

    auto issue = [&](int kt, int st) {
        char* base = smraw + st * F16_STAGE;
        __half* sA = (__half*)base;
        __half* sW = (__half*)(base + F16_A_BYTES);
        const int k0 = kt * 32;
        CP_ASYNC16(smem_u32(&sA[a_row * AS + a_c]),     Ap + k0);
        CP_ASYNC16(smem_u32(&sA[a_row * AS + a_c + 8]), Ap + k0 + 8);
        CP_ASYNC16(smem_u32(&sW[w_row * WS + w_c]),     Wp + (size_t)k0 * DMODEL);
        CP_ASYNC16(smem_u32(&sW[w_row * WS + w_c + 8]), Wp + (size_t)k0 * DMODEL + 8);
    };

    issue(0, 0);
    CP_COMMIT();

    const int NT = DMODEL / 32;
    for (int kt = 0; kt < NT; kt++) {
        const int st = kt & 1;
        if (kt + 1 < NT) { issue(kt + 1, st ^ 1); CP_COMMIT(); CP_WAIT1(); }
        else             { CP_WAIT0(); }
        __syncthreads();

        char* base = smraw + st * F16_STAGE;
        __half* sA = (__half*)base;
        __half* sW = (__half*)(base + F16_A_BYTES);

#pragma unroll
        for (int ks = 0; ks < 2; ks++) {
            const int k16 = ks * 16;
            unsigned ah[4][4], bw[4][2];
            const int ar = lane & 15, ac = (lane >> 4) * 8;
#pragma unroll
            for (int mi = 0; mi < 4; mi++)
                ldsm_x4(ah[mi][0], ah[mi][1], ah[mi][2], ah[mi][3],
                        smem_u32(&sA[(wm + mi * 16 + ar) * AS + k16 + ac]));
            const int br = lane & 15;
#pragma unroll
            for (int nj = 0; nj < 4; nj++)
                ldsm_x2t(bw[nj][0], bw[nj][1],
                         smem_u32(&sW[(k16 + br) * WS + wn + nj * 8]));
#pragma unroll
            for (int mi = 0; mi < 4; mi++)
#pragma unroll
                for (int nj = 0; nj < 4; nj++)
                    mma_f16(acc[mi][nj], ah[mi], bw[nj]);
        }
        __syncthreads();
    }

    const int er = lane >> 2, ec = (lane & 3) * 2;
#pragma unroll
    for (int mi = 0; mi < 4; mi++)
#pragma unroll
        for (int nj = 0; nj < 4; nj++) {
            int row = bm + wm + mi * 16 + er;
            int col = bn + wn + nj * 8 + ec;
            float2 bv = *(const float2*)&bias[col];
            *(__half2*)&Ch[(size_t)row * DMODEL + col] =
                __floats2half2_rn(acc[mi][nj][0] + bv.x, acc[mi][nj][1] + bv.y);
            *(__half2*)&Ch[(size_t)(row + 8) * DMODEL + col] =
                __floats2half2_rn(acc[mi][nj][2] + bv.x, acc[mi][nj][3] + bv.y);
        }
}

// ===========================================================================
// bf16x3 GEMM (O projection): pre-split hi/lo both operands, fp32 out.
// ===========================================================================
#define B3_A_BYTES (128 * AS * 2)
#define B3_W_BYTES (32 * WS * 2)
#define B3_STAGE   (2 * B3_A_BYTES + 2 * B3_W_BYTES)

__global__ __launch_bounds__(256) void gemm_bf16x3_kernel(
    const __nv_bfloat16* __restrict__ AH, const __nv_bfloat16* __restrict__ AL,
    const __nv_bfloat16* __restrict__ WH, const __nv_bfloat16* __restrict__ WL,
    const float* __restrict__ bias, float* __restrict__ C)
{
    extern __shared__ __align__(16) char smraw[];

    const int tid  = threadIdx.x;
    const int lane = tid & 31;
    const int wid  = tid >> 5;
    const int bm   = blockIdx.y * 128;
    const int bn   = blockIdx.x * 128;
    const int wm   = (wid >> 2) * 64;
    const int wn   = (wid & 3) * 32;

    float acc[4][4][4];
#pragma unroll
    for (int mi = 0; mi < 4; mi++)
#pragma unroll
        for (int nj = 0; nj < 4; nj++)
#pragma unroll
            for (int r = 0; r < 4; r++) acc[mi][nj][r] = 0.0f;

    const int a_row = tid >> 1,  a_c = (tid & 1) * 16;
    const int w_row = tid >> 3,  w_c = (tid & 7) * 16;

    const __nv_bfloat16* ApH = AH + (size_t)(bm + a_row) * DMODEL + a_c;
    const __nv_bfloat16* ApL = AL + (size_t)(bm + a_row) * DMODEL + a_c;
    const __nv_bfloat16* WpH = WH + (size_t)w_row * DMODEL + bn + w_c;
    const __nv_bfloat16* WpL = WL + (size_t)w_row * DMODEL + bn + w_c;

    auto issue = [&](int kt, int st) {
        char* base = smraw + st * B3_STAGE;
        __nv_bfloat16* sAH = (__nv_bfloat16*)base;
        __nv_bfloat16* sAL = (__nv_bfloat16*)(base + B3_A_BYTES);
        __nv_bfloat16* sWH = (__nv_bfloat16*)(base + 2 * B3_A_BYTES);
        __nv_bfloat16* sWL = (__nv_bfloat16*)(base + 2 * B3_A_BYTES + B3_W_BYTES);
        const int k0 = kt * 32;
        CP_ASYNC16(smem_u32(&sAH[a_row * AS + a_c]),     ApH + k0);
        CP_ASYNC16(smem_u32(&sAH[a_row * AS + a_c + 8]), ApH + k0 + 8);
        CP_ASYNC16(smem_u32(&sAL[a_row * AS + a_c]),     ApL + k0);
        CP_ASYNC16(smem_u32(&sAL[a_row * AS + a_c + 8]), ApL + k0 + 8);
        CP_ASYNC16(smem_u32(&sWH[w_row * WS + w_c]),     WpH + (size_t)k0 * DMODEL);
        CP_ASYNC16(smem_u32(&sWH[w_row * WS + w_c + 8]), WpH + (size_t)k0 * DMODEL + 8);
        CP_ASYNC16(smem_u32(&sWL[w_row * WS + w_c]),     WpL + (size_t)k0 * DMODEL);
        CP_ASYNC16(smem_u32(&sWL[w_row * WS + w_c + 8]), WpL + (size_t)k0 * DMODEL + 8);
    };

    issue(0, 0);
    CP_COMMIT();

    const int NT = DMODEL / 32;
    for (int kt = 0; kt < NT; kt++) {
        const int st = kt & 1;
        if (kt + 1 < NT) { issue(kt + 1, st ^ 1); CP_COMMIT(); CP_WAIT1(); }
        else             { CP_WAIT0(); }
        __syncthreads();

        char* base = smraw + st * B3_STAGE;
        __nv_bfloat16* sAH = (__nv_bfloat16*)base;
        __nv_bfloat16* sAL = (__nv_bfloat16*)(base + B3_A_BYTES);
        __nv_bfloat16* sWH = (__nv_bfloat16*)(base + 2 * B3_A_BYTES);
        __nv_bfloat16* sWL = (__nv_bfloat16*)(base + 2 * B3_A_BYTES + B3_W_BYTES);

#pragma unroll
        for (int ks = 0; ks < 2; ks++) {
            const int k16 = ks * 16;
            unsigned ah[4][4], al[4][4], bh[4][2], bl[4][2];
            const int ar = lane & 15, ac = (lane >> 4) * 8;
#pragma unroll
            for (int mi = 0; mi < 4; mi++) {
                ldsm_x4(ah[mi][0], ah[mi][1], ah[mi][2], ah[mi][3],
                        smem_u32(&sAH[(wm + mi * 16 + ar) * AS + k16 + ac]));
                ldsm_x4(al[mi][0], al[mi][1], al[mi][2], al[mi][3],
                        smem_u32(&sAL[(wm + mi * 16 + ar) * AS + k16 + ac]));
            }
            const int br = lane & 15;
#pragma unroll
            for (int nj = 0; nj < 4; nj++) {
                ldsm_x2t(bh[nj][0], bh[nj][1],
                         smem_u32(&sWH[(k16 + br) * WS + wn + nj * 8]));
                ldsm_x2t(bl[nj][0], bl[nj][1],
                         smem_u32(&sWL[(k16 + br) * WS + wn + nj * 8]));
            }
#pragma unroll
            for (int mi = 0; mi < 4; mi++)
#pragma unroll
                for (int nj = 0; nj < 4; nj++) {
                    mma_bf16(acc[mi][nj], ah[mi], bh[nj]);
                    mma_bf16(acc[mi][nj], ah[mi], bl[nj]);
                    mma_bf16(acc[mi][nj], al[mi], bh[nj]);
                }
        }
        __syncthreads();
    }

    const int er = lane >> 2, ec = (lane & 3) * 2;
#pragma unroll
    for (int mi = 0; mi < 4; mi++)
#pragma unroll
        for (int nj = 0; nj < 4; nj++) {
            int row = bm + wm + mi * 16 + er;
            int col = bn + wn + nj * 8 + ec;
            float2 bv = *(const float2*)&bias[col];
            *(float2*)&C[(size_t)row * DMODEL + col] =
                make_float2(acc[mi][nj][0] + bv.x, acc[mi][nj][1] + bv.y);
            *(float2*)&C[(size_t)(row + 8) * DMODEL + col] =
                make_float2(acc[mi][nj][2] + bv.x, acc[mi][nj][3] + bv.y);
        }
}

// ===========================================================================
// Flash attention v2 (tensor cores, fp16, fp32 acc). P in single fp16.
// ===========================================================================
#define DST 136
#define SQ_BYTES  (128 * DST * 2)
#define SKV_BYTES (64  * DST * 2)

__global__ __launch_bounds__(256, 1) void attn2_kernel()
{
    extern __shared__ __align__(16) char smraw[];
    __half* Qs = (__half*)smraw;
    __half* Ks[2] = { (__half*)(smraw + SQ_BYTES),
                      (__half*)(smraw + SQ_BYTES + SKV_BYTES) };
    __half* Vs[2] = { (__half*)(smraw + SQ_BYTES + 2 * SKV_BYTES),
                      (__half*)(smraw + SQ_BYTES + 3 * SKV_BYTES) };
    unsigned long long* Mb[2] = {
        (unsigned long long*)(smraw + SQ_BYTES + 4 * SKV_BYTES),
        (unsigned long long*)(smraw + SQ_BYTES + 4 * SKV_BYTES + 128 * 8) };

    const int tid  = threadIdx.x;
    const int lane = tid & 31;
    const int wid  = tid >> 5;
    const int wq   = wid * 16;
    const int er   = lane >> 2;
    const int ec   = (lane & 3) * 2;
    const int q0   = blockIdx.x * 128;
    const int h    = blockIdx.y;
    const int b    = blockIdx.z;

    const __half* Qg = g_Qh + (size_t)(b * TQL + q0) * DMODEL + h * HD;
    const __half* Kg = g_Kh + (size_t)(b * TKVL) * DMODEL + h * HD;
    const __half* Vg = g_Vh + (size_t)(b * TKVL) * DMODEL + h * HD;
    const unsigned long long* Mg = g_Mb + (size_t)(b * TQL + q0) * (TKVL / 64);

    {
#pragma unroll
        for (int it = 0; it < 4; it++) {
            int c = tid + it * 256;
            int r = c >> 4, c8 = (c & 15) * 8;
            CP_ASYNC16(smem_u32(&Ks[0][r * DST + c8]), Kg + (size_t)r * DMODEL + c8);
            CP_ASYNC16(smem_u32(&Vs[0][r * DST + c8]), Vg + (size_t)r * DMODEL + c8);
        }
        if (tid < 128)
            CP_ASYNC8(smem_u32(&Mb[0][tid]), Mg + (size_t)tid * (TKVL / 64));
        CP_COMMIT();
    }
#pragma unroll
    for (int it = 0; it < 8; it++) {
        int c = tid + it * 256;
        int r = c >> 4, c8 = (c & 15) * 8;
        *(uint4*)&Qs[r * DST + c8] = *(const uint4*)(Qg + (size_t)r * DMODEL + c8);
    }

    const float YC = 1.4426950408889634f * 0.08838834764831845f;

    float Oacc[16][4];
#pragma unroll
    for (int v = 0; v < 16; v++)
#pragma unroll
        for (int r = 0; r < 4; r++) Oacc[v][r] = 0.0f;
    float m_run[2] = { -12000.0f, -12000.0f };
    float l_run[2] = { 0.0f, 0.0f };

    for (int t = 0; t < TKVL / 64; t++) {
        const int buf = t & 1, nbuf = buf ^ 1;
        if (t + 1 < TKVL / 64) {
            const int kv1 = (t + 1) * 64;
#pragma unroll
            for (int it = 0; it < 4; it++) {
                int c = tid + it * 256;
                int r = c >> 4, c8 = (c & 15) * 8;
                CP_ASYNC16(smem_u32(&Ks[nbuf][r * DST + c8]),
                           Kg + (size_t)(kv1 + r) * DMODEL + c8);
                CP_ASYNC16(smem_u32(&Vs[nbuf][r * DST + c8]),
                           Vg + (size_t)(kv1 + r) * DMODEL + c8);
            }
            if (tid < 128)
                CP_ASYNC8(smem_u32(&Mb[nbuf][tid]),
                          Mg + (size_t)tid * (TKVL / 64) + (kv1 >> 6));
            CP_COMMIT();
            CP_WAIT1();
        } else {
            CP_WAIT0();
        }
        __syncthreads();

        float sa[8][4];
#pragma unroll
        for (int nj = 0; nj < 8; nj++)
#pragma unroll
            for (int r = 0; r < 4; r++) sa[nj][r] = 0.0f;

#pragma unroll
        for (int kk = 0; kk < 8; kk++) {
            unsigned qa[4];
            ldsm_x4(qa[0], qa[1], qa[2], qa[3],
                    smem_u32(&Qs[(wq + (lane & 15)) * DST + kk * 16 + (lane >> 4) * 8]));
#pragma unroll
            for (int nj = 0; nj < 8; nj++) {
                unsigned kb[2];
                ldsm_x2(kb[0], kb[1],
                        smem_u32(&Ks[buf][(nj * 8 + (lane & 7)) * DST
                                          + kk * 16 + ((lane >> 3) & 1) * 8]));
                mma_f16(sa[nj], qa, kb);
            }
        }

        const unsigned long long mb0 = Mb[buf][wq + er];
        const unsigned long long mb1 = Mb[buf][wq + er + 8];
        float rm0 = -1e30f, rm1 = -1e30f;
#pragma unroll
        for (int nj = 0; nj < 8; nj++) {
            unsigned b0 = (unsigned)(mb0 >> (nj * 8 + ec)) & 3u;
            unsigned b1 = (unsigned)(mb1 >> (nj * 8 + ec)) & 3u;
            float y0 = sa[nj][0] * YC, y1 = sa[nj][1] * YC;
            float y2 = sa[nj][2] * YC, y3 = sa[nj][3] * YC;
            sa[nj][0] = (b0 & 1u) ? y0 : -1e30f;
            sa[nj][1] = (b0 & 2u) ? y1 : -1e30f;
            sa[nj][2] = (b1 & 1u) ? y2 : -1e30f;
            sa[nj][3] = (b1 & 2u) ? y3 : -1e30f;
            rm0 = fmaxf(rm0, fmaxf(sa[nj][0], sa[nj][1]));
            rm1 = fmaxf(rm1, fmaxf(sa[nj][2], sa[nj][3]));
        }
        rm0 = fmaxf(rm0, __shfl_xor_sync(0xffffffffu, rm0, 1));
        rm0 = fmaxf(rm0, __shfl_xor_sync(0xffffffffu, rm0, 2));
        rm1 = fmaxf(rm1, __shfl_xor_sync(0xffffffffu, rm1, 1));
        rm1 = fmaxf(rm1, __shfl_xor_sync(0xffffffffu, rm1, 2));
        float mn0 = fmaxf(fmaxf(m_run[0], rm0), -12000.0f);
        float mn1 = fmaxf(fmaxf(m_run[1], rm1), -12000.0f);
        float al0 = exp2p(m_run[0] - mn0);
        float al1 = exp2p(m_run[1] - mn1);
        m_run[0] = mn0; m_run[1] = mn1;
        l_run[0] *= al0; l_run[1] *= al1;
#pragma unroll
        for (int v = 0; v < 16; v++) {
            Oacc[v][0] *= al0; Oacc[v][1] *= al0;
            Oacc[v][2] *= al1; Oacc[v][3] *= al1;
        }

        unsigned ph[2][8];
#pragma unroll
        for (int nj = 0; nj < 8; nj++) {
            float p0 = exp2p(sa[nj][0] - mn0);
            float p1 = exp2p(sa[nj][1] - mn0);
            float p2 = exp2p(sa[nj][2] - mn1);
            float p3 = exp2p(sa[nj][3] - mn1);
            l_run[0] += p0 + p1;
            l_run[1] += p2 + p3;
            __half2 h0 = __floats2half2_rn(p0, p1);
            __half2 h1 = __floats2half2_rn(p2, p3);
            ph[0][nj] = *(unsigned*)&h0;
            ph[1][nj] = *(unsigned*)&h1;
        }

#pragma unroll
        for (int kk = 0; kk < 4; kk++) {
            unsigned aH[4] = { ph[0][2 * kk], ph[1][2 * kk],
                               ph[0][2 * kk + 1], ph[1][2 * kk + 1] };
#pragma unroll
            for (int vj = 0; vj < 16; vj++) {
                unsigned vb[2];
                ldsm_x2t(vb[0], vb[1],
                         smem_u32(&Vs[buf][(kk * 16 + (lane & 15)) * DST + vj * 8]));
                mma_f16(Oacc[vj], aH, vb);
            }
        }
        __syncthreads();
    }

    float l0 = l_run[0], l1 = l_run[1];
    l0 += __shfl_xor_sync(0xffffffffu, l0, 1);
    l0 += __shfl_xor_sync(0xffffffffu, l0, 2);
    l1 += __shfl_xor_sync(0xffffffffu, l1, 1);
    l1 += __shfl_xor_sync(0xffffffffu, l1, 2);
    float inv0 = (l0 > 1e-10f) ? (1.0f / l0) : 0.0f;
    float inv1 = (l1 > 1e-10f) ? (1.0f / l1) : 0.0f;
    float* O0 = g_A + (size_t)(b * TQL + q0 + wq + er) * DMODEL + h * HD;
    float* O1 = O0 + 8 * DMODEL;
#pragma unroll
    for (int vj = 0; vj < 16; vj++) {
        *(float2*)&O0[vj * 8 + ec] = make_float2(Oacc[vj][0] * inv0, Oacc[vj][1] * inv0);
        *(float2*)&O1[vj * 8 + ec] = make_float2(Oacc[vj][2] * inv1, Oacc[vj][3] * inv1);
    }
}

// ---------------------------------------------------------------------------
extern "C" void kernel_launch(void* const* d_in, const int* in_sizes, int n_in,
                              void* d_out, int out_size)
{
    (void)in_sizes; (void)n_in; (void)out_size;

    const float* xq   = (const float*)d_in[0];
    const float* xkv  = (const float*)d_in[1];
    const int*   mask = (const int*)d_in[2];
    const float* Wq = (const float*)d_in[3];
    const float* bq = (const float*)d_in[4];
    const float* Wk = (const float*)d_in[5];
    const float* bk = (const float*)d_in[6];
    const float* Wv = (const float*)d_in[7];
    const float* bv = (const float*)d_in[8];
    const float* Wo = (const float*)d_in[9];
    const float* bo = (const float*)d_in[10];
    float* out = (float*)d_out;

    __half *Qh, *Kh, *Vh, *Xqh, *Xkvh, *Wqh, *Wkh, *Wvh;
    __nv_bfloat16 *WoH, *WoL, *AHp, *ALp;
    float *Ad;
    unsigned long long *Mbp;
    cudaGetSymbolAddress((void**)&Qh,   g_Qh);
    cudaGetSymbolAddress((void**)&Kh,   g_Kh);
    cudaGetSymbolAddress((void**)&Vh,   g_Vh);
    cudaGetSymbolAddress((void**)&Ad,   g_A);
    cudaGetSymbolAddress((void**)&Mbp,  g_Mb);
    cudaGetSymbolAddress((void**)&Xqh,  g_Xqh);
    cudaGetSymbolAddress((void**)&Xkvh, g_Xkvh);
    cudaGetSymbolAddress((void**)&Wqh,  g_Wqh);
    cudaGetSymbolAddress((void**)&Wkh,  g_Wkh);
    cudaGetSymbolAddress((void**)&Wvh,  g_Wvh);
    cudaGetSymbolAddress((void**)&WoH,  g_WoH);
    cudaGetSymbolAddress((void**)&WoL,  g_WoL);
    cudaGetSymbolAddress((void**)&AHp,  g_AH);
    cudaGetSymbolAddress((void**)&ALp,  g_AL);

    const int smem_attn = SQ_BYTES + 4 * SKV_BYTES + 2 * 128 * 8;
    const int smem_f16  = 2 * F16_STAGE;
    const int smem_b3   = 2 * B3_STAGE;
    static int configured = 0;
    if (!configured) {
        cudaFuncSetAttribute(attn2_kernel,
                             cudaFuncAttributeMaxDynamicSharedMemorySize, smem_attn);
        cudaFuncSetAttribute(gemm_f16_kernel,
                             cudaFuncAttributeMaxDynamicSharedMemorySize, smem_f16);
        cudaFuncSetAttribute(gemm_bf16x3_kernel,
                             cudaFuncAttributeMaxDynamicSharedMemorySize, smem_b3);
        configured = 1;
    }

    dim3 thr(256);
    const int nW8  = DMODEL * DMODEL / 8;          // 131072
    const int nXq8 = NB * TQL * DMODEL / 8;        // 262144
    const int nXk8 = NB * TKVL * DMODEL / 8;       // 2097152

    mask_pack_kernel<<<1024, thr>>>(mask, (unsigned*)Mbp);
    cvt_f16_kernel<<<1024, thr>>>((const float4*)xq,  (uint4*)Xqh,  nXq8);
    cvt_f16_kernel<<<2048, thr>>>((const float4*)xkv, (uint4*)Xkvh, nXk8);
    cvt3_f16_kernel<<<1536, thr>>>((const float4*)Wq, (const float4*)Wk,
                                   (const float4*)Wv,
                                   (uint4*)Wqh, (uint4*)Wkh, (uint4*)Wvh, nW8);
    split_bf16_kernel<<<512, thr>>>((const float4*)Wo, (uint4*)WoH, (uint4*)WoL, nW8);

    gemm_f16_kernel<<<dim3(8, 16),  thr, smem_f16>>>(Xqh,  Wqh, bq, Qh);
    gemm_f16_kernel<<<dim3(8, 128), thr, smem_f16>>>(Xkvh, Wkh, bk, Kh);
    gemm_f16_kernel<<<dim3(8, 128), thr, smem_f16>>>(Xkvh, Wvh, bv, Vh);

    attn2_kernel<<<dim3(TQL / 128, NH, NB), thr, smem_attn>>>();

    split_bf16_kernel<<<1024, thr>>>((const float4*)Ad, (uint4*)AHp, (uint4*)ALp, nXq8);
    gemm_bf16x3_kernel<<<dim3(8, 16), thr, smem_b3>>>(AHp, ALp, WoH, WoL, bo, out);
}

// round 13
// speedup vs baseline: 6.2005x; 1.0307x over previous
#include <cuda_runtime.h>
#include <cuda_bf16.h>
#include <cuda_fp16.h>
#include <math.h>
#include <float.h>

#define DMODEL 1024
#define NB     4
#define TQL    512
#define TKVL   4096
#define NH     8
#define HD     128

// --------------------------- device scratch --------------------------------
__device__ __half g_Qh[NB * TQL  * DMODEL];
__device__ __half g_Kh[NB * TKVL * DMODEL];
__device__ __half g_Vh[NB * TKVL * DMODEL];
__device__ float  g_A [NB * TQL  * DMODEL];
__device__ unsigned long long g_Mb[NB * TQL * (TKVL / 64)];

// pre-converted operands
__device__ __half g_Xqh [NB * TQL  * DMODEL];
__device__ __half g_Xkvh[NB * TKVL * DMODEL];
__device__ __half g_Wqh [DMODEL * DMODEL];
__device__ __half g_Wkh [DMODEL * DMODEL];
__device__ __half g_Wvh [DMODEL * DMODEL];
__device__ __nv_bfloat16 g_WoH[DMODEL * DMODEL];
__device__ __nv_bfloat16 g_WoL[DMODEL * DMODEL];
__device__ __nv_bfloat16 g_AH [NB * TQL * DMODEL];
__device__ __nv_bfloat16 g_AL [NB * TQL * DMODEL];

// ---------------------------- mma helpers ----------------------------------
__device__ __forceinline__ unsigned smem_u32(const void* p) {
    return (unsigned)__cvta_generic_to_shared(p);
}
__device__ __forceinline__ void ldsm_x4(unsigned& r0, unsigned& r1,
                                        unsigned& r2, unsigned& r3, unsigned a) {
    asm volatile("ldmatrix.sync.aligned.m8n8.x4.shared.b16 {%0,%1,%2,%3}, [%4];"
                 : "=r"(r0), "=r"(r1), "=r"(r2), "=r"(r3) : "r"(a));
}
__device__ __forceinline__ void ldsm_x4t(unsigned& r0, unsigned& r1,
                                         unsigned& r2, unsigned& r3, unsigned a) {
    asm volatile("ldmatrix.sync.aligned.m8n8.x4.trans.shared.b16 {%0,%1,%2,%3}, [%4];"
                 : "=r"(r0), "=r"(r1), "=r"(r2), "=r"(r3) : "r"(a));
}
__device__ __forceinline__ void mma_bf16(float* d, const unsigned* a, const unsigned* b) {
    asm volatile(
        "mma.sync.aligned.m16n8k16.row.col.f32.bf16.bf16.f32 "
        "{%0,%1,%2,%3}, {%4,%5,%6,%7}, {%8,%9}, {%0,%1,%2,%3};"
        : "+f"(d[0]), "+f"(d[1]), "+f"(d[2]), "+f"(d[3])
        : "r"(a[0]), "r"(a[1]), "r"(a[2]), "r"(a[3]), "r"(b[0]), "r"(b[1]));
}
__device__ __forceinline__ void mma_f16(float* d, const unsigned* a, const unsigned* b) {
    asm volatile(
        "mma.sync.aligned.m16n8k16.row.col.f32.f16.f16.f32 "
        "{%0,%1,%2,%3}, {%4,%5,%6,%7}, {%8,%9}, {%0,%1,%2,%3};"
        : "+f"(d[0]), "+f"(d[1]), "+f"(d[2]), "+f"(d[3])
        : "r"(a[0]), "r"(a[1]), "r"(a[2]), "r"(a[3]), "r"(b[0]), "r"(b[1]));
}
#define CP_ASYNC16(dst, src) \
    asm volatile("cp.async.cg.shared.global [%0], [%1], 16;" :: "r"(dst), "l"(src))
#define CP_ASYNC8(dst, src) \
    asm volatile("cp.async.ca.shared.global [%0], [%1], 8;"  :: "r"(dst), "l"(src))
#define CP_COMMIT()  asm volatile("cp.async.commit_group;")
#define CP_WAIT0()   asm volatile("cp.async.wait_group 0;")
#define CP_WAIT1()   asm volatile("cp.async.wait_group 1;")

// Hardware exp2 (MUFU.EX2): one issue slot, pipe runs in background.
__device__ __forceinline__ float ex2(float x) {
    float y;
    asm("ex2.approx.f32 %0, %1;" : "=f"(y) : "f"(x));
    return y;
}

// ======================= convert / split kernels ===========================
__device__ __forceinline__ uint4 pack_f16x8(float4 a, float4 b) {
    __half2 h0 = __floats2half2_rn(a.x, a.y), h1 = __floats2half2_rn(a.z, a.w);
    __half2 h2 = __floats2half2_rn(b.x, b.y), h3 = __floats2half2_rn(b.z, b.w);
    uint4 u;
    u.x = *(unsigned*)&h0; u.y = *(unsigned*)&h1;
    u.z = *(unsigned*)&h2; u.w = *(unsigned*)&h3;
    return u;
}

__global__ __launch_bounds__(256) void cvt_f16_kernel(
    const float4* __restrict__ x, uint4* __restrict__ out, int n8)
{
    int i = blockIdx.x * 256 + threadIdx.x;
    int stride = gridDim.x * 256;
    for (; i < n8; i += stride)
        out[i] = pack_f16x8(x[2 * i], x[2 * i + 1]);
}

__global__ __launch_bounds__(256) void cvt3_f16_kernel(
    const float4* __restrict__ w0, const float4* __restrict__ w1,
    const float4* __restrict__ w2,
    uint4* __restrict__ o0, uint4* __restrict__ o1, uint4* __restrict__ o2,
    int n8)
{
    int i = blockIdx.x * 256 + threadIdx.x;
    int stride = gridDim.x * 256;
    int total = 3 * n8;
    for (; i < total; i += stride) {
        int m = i / n8, j = i - m * n8;
        const float4* w = (m == 0) ? w0 : (m == 1) ? w1 : w2;
        uint4* o = (m == 0) ? o0 : (m == 1) ? o1 : o2;
        o[j] = pack_f16x8(w[2 * j], w[2 * j + 1]);
    }
}

__global__ __launch_bounds__(256) void split_bf16_kernel(
    const float4* __restrict__ x, uint4* __restrict__ hi,
    uint4* __restrict__ lo, int n8)
{
    int i = blockIdx.x * 256 + threadIdx.x;
    int stride = gridDim.x * 256;
    for (; i < n8; i += stride) {
        float4 a = x[2 * i], b = x[2 * i + 1];
        float v[8] = { a.x, a.y, a.z, a.w, b.x, b.y, b.z, b.w };
        __nv_bfloat16 h[8], l[8];
#pragma unroll
        for (int k = 0; k < 8; k++) {
            h[k] = __float2bfloat16(v[k]);
            l[k] = __float2bfloat16(v[k] - __bfloat162float(h[k]));
        }
        uint4 uh, ul;
        __nv_bfloat162 t;
        t = __nv_bfloat162(h[0], h[1]); uh.x = *(unsigned*)&t;
        t = __nv_bfloat162(h[2], h[3]); uh.y = *(unsigned*)&t;
        t = __nv_bfloat162(h[4], h[5]); uh.z = *(unsigned*)&t;
        t = __nv_bfloat162(h[6], h[7]); uh.w = *(unsigned*)&t;
        t = __nv_bfloat162(l[0], l[1]); ul.x = *(unsigned*)&t;
        t = __nv_bfloat162(l[2], l[3]); ul.y = *(unsigned*)&t;
        t = __nv_bfloat162(l[4], l[5]); ul.z = *(unsigned*)&t;
        t = __nv_bfloat162(l[6], l[7]); ul.w = *(unsigned*)&t;
        hi[i] = uh;
        lo[i] = ul;
    }
}

// =========================== mask bit-pack =================================
__global__ __launch_bounds__(256) void mask_pack_kernel(const int* __restrict__ m,
                                                        unsigned* __restrict__ out)
{
    const int lane = threadIdx.x & 31;
    const int wg   = (blockIdx.x * 256 + threadIdx.x) >> 5;
    const int base = wg * 1024;
    unsigned myw = 0;
#pragma unroll
    for (int it = 0; it < 32; it++) {
        int v = m[base + it * 32 + lane];
        unsigned b = __ballot_sync(0xffffffffu, v != 0);
        if (lane == it) myw = b;
    }
    out[wg * 32 + lane] = myw;
}

// ===========================================================================
// fp16 GEMM (Q/K/V projections): C = A @ W + bias, fp16 in/out, fp32 acc.
// ===========================================================================
#define AS 40
#define WS 136

#define F16_A_BYTES (128 * AS * 2)
#define F16_STAGE   (F16_A_BYTES + 32 * WS * 2)

__global__ __launch_bounds__(256) void gemm_f16_kernel(
    const __half* __restrict__ A, const __half* __restrict__ W,
    const float* __restrict__ bias, __half* __restrict__ Ch)
{
    extern __shared__ __align__(16) char smraw[];

    const int tid  = threadIdx.x;
    const int lane = tid & 31;
    const int wid  = tid >> 5;
    const int bm   = blockIdx.y * 128;
    const int bn   = blockIdx.x * 128;
    const int wm   = (wid >> 2) * 64;
    const int wn   = (wid & 3) * 32;

    float acc[4][4][4];
#pragma unroll
    for (int mi = 0; mi < 4; mi++)
#pragma unroll
        for (int nj = 0; nj < 4; nj++)
#pragma unroll
            for (int r = 0; r < 4; r++) acc[mi][nj][r] = 0.0f;

    const int a_row = tid >> 1,  a_c = (tid & 1) * 16;
    const int w_row = tid >> 3,  w_c = (tid & 7) * 16;

    const __half* Ap = A + (size_t)(bm + a_row) * DMODEL + a_c;
    const __half* Wp = W + (size_t)w_row * DMODEL + bn + w_c;

    auto issue = [&](int kt, int st) {
        char* base = smraw + st * F16_STAGE;
        __half* sA = (__half*)base;
        __half* sW = (__half*)(base + F16_A_BYTES);
        const int k0 = kt * 32;
        CP_ASYNC16(smem_u32(&sA[a_row * AS + a_c]),     Ap + k0);
        CP_ASYNC16(smem_u32(&sA[a_row * AS + a_c + 8]), Ap + k0 + 8);
        CP_ASYNC16(smem_u32(&sW[w_row * WS + w_c]),     Wp + (size_t)k0 * DMODEL);
        CP_ASYNC16(smem_u32(&sW[w_row * WS + w_c + 8]), Wp + (size_t)k0 * DMODEL + 8);
    };

    issue(0, 0);
    CP_COMMIT();

    const int NT = DMODEL / 32;
    for (int kt = 0; kt < NT; kt++) {
        const int st = kt & 1;
        if (kt + 1 < NT) { issue(kt + 1, st ^ 1); CP_COMMIT(); CP_WAIT1(); }
        else             { CP_WAIT0(); }
        __syncthreads();

        char* base = smraw + st * F16_STAGE;
        __half* sA = (__half*)base;
        __half* sW = (__half*)(base + F16_A_BYTES);

#pragma unroll
        for (int ks = 0; ks < 2; ks++) {
            const int k16 = ks * 16;
            unsigned ah[4][4], bw[4][2];
            const int ar = lane & 15, ac = (lane >> 4) * 8;
#pragma unroll
            for (int mi = 0; mi < 4; mi++)
                ldsm_x4(ah[mi][0], ah[mi][1], ah[mi][2], ah[mi][3],
                        smem_u32(&sA[(wm + mi * 16 + ar) * AS + k16 + ac]));
            // W fragments: two n8 tiles per ldsm.x4.trans
#pragma unroll
            for (int njp = 0; njp < 2; njp++) {
                unsigned t0, t1, t2, t3;
                ldsm_x4t(t0, t1, t2, t3,
                         smem_u32(&sW[(k16 + (lane & 15)) * WS
                                      + wn + (njp * 2 + (lane >> 4)) * 8]));
                bw[2 * njp][0] = t0; bw[2 * njp][1] = t1;
                bw[2 * njp + 1][0] = t2; bw[2 * njp + 1][1] = t3;
            }
#pragma unroll
            for (int mi = 0; mi < 4; mi++)
#pragma unroll
                for (int nj = 0; nj < 4; nj++)
                    mma_f16(acc[mi][nj], ah[mi], bw[nj]);
        }
        __syncthreads();
    }

    const int er = lane >> 2, ec = (lane & 3) * 2;
#pragma unroll
    for (int mi = 0; mi < 4; mi++)
#pragma unroll
        for (int nj = 0; nj < 4; nj++) {
            int row = bm + wm + mi * 16 + er;
            int col = bn + wn + nj * 8 + ec;
            float2 bv = *(const float2*)&bias[col];
            *(__half2*)&Ch[(size_t)row * DMODEL + col] =
                __floats2half2_rn(acc[mi][nj][0] + bv.x, acc[mi][nj][1] + bv.y);
            *(__half2*)&Ch[(size_t)(row + 8) * DMODEL + col] =
                __floats2half2_rn(acc[mi][nj][2] + bv.x, acc[mi][nj][3] + bv.y);
        }
}

// ===========================================================================
// bf16x3 GEMM (O projection): pre-split hi/lo both operands, fp32 out.
// ===========================================================================
#define B3_A_BYTES (128 * AS * 2)
#define B3_W_BYTES (32 * WS * 2)
#define B3_STAGE   (2 * B3_A_BYTES + 2 * B3_W_BYTES)

__global__ __launch_bounds__(256) void gemm_bf16x3_kernel(
    const __nv_bfloat16* __restrict__ AH, const __nv_bfloat16* __restrict__ AL,
    const __nv_bfloat16* __restrict__ WH, const __nv_bfloat16* __restrict__ WL,
    const float* __restrict__ bias, float* __restrict__ C)
{
    extern __shared__ __align__(16) char smraw[];

    const int tid  = threadIdx.x;
    const int lane = tid & 31;
    const int wid  = tid >> 5;
    const int bm   = blockIdx.y * 128;
    const int bn   = blockIdx.x * 128;
    const int wm   = (wid >> 2) * 64;
    const int wn   = (wid & 3) * 32;

    float acc[4][4][4];
#pragma unroll
    for (int mi = 0; mi < 4; mi++)
#pragma unroll
        for (int nj = 0; nj < 4; nj++)
#pragma unroll
            for (int r = 0; r < 4; r++) acc[mi][nj][r] = 0.0f;

    const int a_row = tid >> 1,  a_c = (tid & 1) * 16;
    const int w_row = tid >> 3,  w_c = (tid & 7) * 16;

    const __nv_bfloat16* ApH = AH + (size_t)(bm + a_row) * DMODEL + a_c;
    const __nv_bfloat16* ApL = AL + (size_t)(bm + a_row) * DMODEL + a_c;
    const __nv_bfloat16* WpH = WH + (size_t)w_row * DMODEL + bn + w_c;
    const __nv_bfloat16* WpL = WL + (size_t)w_row * DMODEL + bn + w_c;

    auto issue = [&](int kt, int st) {
        char* base = smraw + st * B3_STAGE;
        __nv_bfloat16* sAH = (__nv_bfloat16*)base;
        __nv_bfloat16* sAL = (__nv_bfloat16*)(base + B3_A_BYTES);
        __nv_bfloat16* sWH = (__nv_bfloat16*)(base + 2 * B3_A_BYTES);
        __nv_bfloat16* sWL = (__nv_bfloat16*)(base + 2 * B3_A_BYTES + B3_W_BYTES);
        const int k0 = kt * 32;
        CP_ASYNC16(smem_u32(&sAH[a_row * AS + a_c]),     ApH + k0);
        CP_ASYNC16(smem_u32(&sAH[a_row * AS + a_c + 8]), ApH + k0 + 8);
        CP_ASYNC16(smem_u32(&sAL[a_row * AS + a_c]),     ApL + k0);
        CP_ASYNC16(smem_u32(&sAL[a_row * AS + a_c + 8]), ApL + k0 + 8);
        CP_ASYNC16(smem_u32(&sWH[w_row * WS + w_c]),     WpH + (size_t)k0 * DMODEL);
        CP_ASYNC16(smem_u32(&sWH[w_row * WS + w_c + 8]), WpH + (size_t)k0 * DMODEL + 8);
        CP_ASYNC16(smem_u32(&sWL[w_row * WS + w_c]),     WpL + (size_t)k0 * DMODEL);
        CP_ASYNC16(smem_u32(&sWL[w_row * WS + w_c + 8]), WpL + (size_t)k0 * DMODEL + 8);
    };

    issue(0, 0);
    CP_COMMIT();

    const int NT = DMODEL / 32;
    for (int kt = 0; kt < NT; kt++) {
        const int st = kt & 1;
        if (kt + 1 < NT) { issue(kt + 1, st ^ 1); CP_COMMIT(); CP_WAIT1(); }
        else             { CP_WAIT0(); }
        __syncthreads();

        char* base = smraw + st * B3_STAGE;
        __nv_bfloat16* sAH = (__nv_bfloat16*)base;
        __nv_bfloat16* sAL = (__nv_bfloat16*)(base + B3_A_BYTES);
        __nv_bfloat16* sWH = (__nv_bfloat16*)(base + 2 * B3_A_BYTES);
        __nv_bfloat16* sWL = (__nv_bfloat16*)(base + 2 * B3_A_BYTES + B3_W_BYTES);

#pragma unroll
        for (int ks = 0; ks < 2; ks++) {
            const int k16 = ks * 16;
            unsigned ah[4][4], al[4][4], bh[4][2], bl[4][2];
            const int ar = lane & 15, ac = (lane >> 4) * 8;
#pragma unroll
            for (int mi = 0; mi < 4; mi++) {
                ldsm_x4(ah[mi][0], ah[mi][1], ah[mi][2], ah[mi][3],
                        smem_u32(&sAH[(wm + mi * 16 + ar) * AS + k16 + ac]));
                ldsm_x4(al[mi][0], al[mi][1], al[mi][2], al[mi][3],
                        smem_u32(&sAL[(wm + mi * 16 + ar) * AS + k16 + ac]));
            }
#pragma unroll
            for (int njp = 0; njp < 2; njp++) {
                unsigned t0, t1, t2, t3;
                ldsm_x4t(t0, t1, t2, t3,
                         smem_u32(&sWH[(k16 + (lane & 15)) * WS
                                       + wn + (njp * 2 + (lane >> 4)) * 8]));
                bh[2 * njp][0] = t0; bh[2 * njp][1] = t1;
                bh[2 * njp + 1][0] = t2; bh[2 * njp + 1][1] = t3;
                ldsm_x4t(t0, t1, t2, t3,
                         smem_u32(&sWL[(k16 + (lane & 15)) * WS
                                       + wn + (njp * 2 + (lane >> 4)) * 8]));
                bl[2 * njp][0] = t0; bl[2 * njp][1] = t1;
                bl[2 * njp + 1][0] = t2; bl[2 * njp + 1][1] = t3;
            }
#pragma unroll
            for (int mi = 0; mi < 4; mi++)
#pragma unroll
                for (int nj = 0; nj < 4; nj++) {
                    mma_bf16(acc[mi][nj], ah[mi], bh[nj]);
                    mma_bf16(acc[mi][nj], ah[mi], bl[nj]);
                    mma_bf16(acc[mi][nj], al[mi], bh[nj]);
                }
        }
        __syncthreads();
    }

    const int er = lane >> 2, ec = (lane & 3) * 2;
#pragma unroll
    for (int mi = 0; mi < 4; mi++)
#pragma unroll
        for (int nj = 0; nj < 4; nj++) {
            int row = bm + wm + mi * 16 + er;
            int col = bn + wn + nj * 8 + ec;
            float2 bv = *(const float2*)&bias[col];
            *(float2*)&C[(size_t)row * DMODEL + col] =
                make_float2(acc[mi][nj][0] + bv.x, acc[mi][nj][1] + bv.y);
            *(float2*)&C[(size_t)(row + 8) * DMODEL + col] =
                make_float2(acc[mi][nj][2] + bv.x, acc[mi][nj][3] + bv.y);
        }
}

// ===========================================================================
// Flash attention v2 (tensor cores, fp16, fp32 acc). P single fp16.
// MUFU ex2 softmax; paired ldsm for K and V fragments.
// ===========================================================================
#define DST 136
#define SQ_BYTES  (128 * DST * 2)
#define SKV_BYTES (64  * DST * 2)

__global__ __launch_bounds__(256, 1) void attn2_kernel()
{
    extern __shared__ __align__(16) char smraw[];
    __half* Qs = (__half*)smraw;
    __half* Ks[2] = { (__half*)(smraw + SQ_BYTES),
                      (__half*)(smraw + SQ_BYTES + SKV_BYTES) };
    __half* Vs[2] = { (__half*)(smraw + SQ_BYTES + 2 * SKV_BYTES),
                      (__half*)(smraw + SQ_BYTES + 3 * SKV_BYTES) };
    unsigned long long* Mb[2] = {
        (unsigned long long*)(smraw + SQ_BYTES + 4 * SKV_BYTES),
        (unsigned long long*)(smraw + SQ_BYTES + 4 * SKV_BYTES + 128 * 8) };

    const int tid  = threadIdx.x;
    const int lane = tid & 31;
    const int wid  = tid >> 5;
    const int wq   = wid * 16;
    const int er   = lane >> 2;
    const int ec   = (lane & 3) * 2;
    const int q0   = blockIdx.x * 128;
    const int h    = blockIdx.y;
    const int b    = blockIdx.z;

    const __half* Qg = g_Qh + (size_t)(b * TQL + q0) * DMODEL + h * HD;
    const __half* Kg = g_Kh + (size_t)(b * TKVL) * DMODEL + h * HD;
    const __half* Vg = g_Vh + (size_t)(b * TKVL) * DMODEL + h * HD;
    const unsigned long long* Mg = g_Mb + (size_t)(b * TQL + q0) * (TKVL / 64);

    {
#pragma unroll
        for (int it = 0; it < 4; it++) {
            int c = tid + it * 256;
            int r = c >> 4, c8 = (c & 15) * 8;
            CP_ASYNC16(smem_u32(&Ks[0][r * DST + c8]), Kg + (size_t)r * DMODEL + c8);
            CP_ASYNC16(smem_u32(&Vs[0][r * DST + c8]), Vg + (size_t)r * DMODEL + c8);
        }
        if (tid < 128)
            CP_ASYNC8(smem_u32(&Mb[0][tid]), Mg + (size_t)tid * (TKVL / 64));
        CP_COMMIT();
    }
#pragma unroll
    for (int it = 0; it < 8; it++) {
        int c = tid + it * 256;
        int r = c >> 4, c8 = (c & 15) * 8;
        *(uint4*)&Qs[r * DST + c8] = *(const uint4*)(Qg + (size_t)r * DMODEL + c8);
    }

    const float YC = 1.4426950408889634f * 0.08838834764831845f;

    float Oacc[16][4];
#pragma unroll
    for (int v = 0; v < 16; v++)
#pragma unroll
        for (int r = 0; r < 4; r++) Oacc[v][r] = 0.0f;
    float m_run[2] = { -12000.0f, -12000.0f };
    float l_run[2] = { 0.0f, 0.0f };

    for (int t = 0; t < TKVL / 64; t++) {
        const int buf = t & 1, nbuf = buf ^ 1;
        if (t + 1 < TKVL / 64) {
            const int kv1 = (t + 1) * 64;
#pragma unroll
            for (int it = 0; it < 4; it++) {
                int c = tid + it * 256;
                int r = c >> 4, c8 = (c & 15) * 8;
                CP_ASYNC16(smem_u32(&Ks[nbuf][r * DST + c8]),
                           Kg + (size_t)(kv1 + r) * DMODEL + c8);
                CP_ASYNC16(smem_u32(&Vs[nbuf][r * DST + c8]),
                           Vg + (size_t)(kv1 + r) * DMODEL + c8);
            }
            if (tid < 128)
                CP_ASYNC8(smem_u32(&Mb[nbuf][tid]),
                          Mg + (size_t)tid * (TKVL / 64) + (kv1 >> 6));
            CP_COMMIT();
            CP_WAIT1();
        } else {
            CP_WAIT0();
        }
        __syncthreads();

        float sa[8][4];
#pragma unroll
        for (int nj = 0; nj < 8; nj++)
#pragma unroll
            for (int r = 0; r < 4; r++) sa[nj][r] = 0.0f;

        // ---- S = Q K^T : paired K fragments (two n8 tiles per ldsm.x4)
#pragma unroll
        for (int kk = 0; kk < 8; kk++) {
            unsigned qa[4];
            ldsm_x4(qa[0], qa[1], qa[2], qa[3],
                    smem_u32(&Qs[(wq + (lane & 15)) * DST + kk * 16 + (lane >> 4) * 8]));
#pragma unroll
            for (int njp = 0; njp < 4; njp++) {
                unsigned kb[4];
                ldsm_x4(kb[0], kb[1], kb[2], kb[3],
                        smem_u32(&Ks[buf][((njp * 2 + ((lane >> 4) & 1)) * 8
                                           + (lane & 7)) * DST
                                          + kk * 16 + ((lane >> 3) & 1) * 8]));
                mma_f16(sa[2 * njp],     qa, kb);
                mma_f16(sa[2 * njp + 1], qa, kb + 2);
            }
        }

        const unsigned long long mb0 = Mb[buf][wq + er];
        const unsigned long long mb1 = Mb[buf][wq + er + 8];
        float rm0 = -1e30f, rm1 = -1e30f;
#pragma unroll
        for (int nj = 0; nj < 8; nj++) {
            unsigned b0 = (unsigned)(mb0 >> (nj * 8 + ec)) & 3u;
            unsigned b1 = (unsigned)(mb1 >> (nj * 8 + ec)) & 3u;
            float y0 = sa[nj][0] * YC, y1 = sa[nj][1] * YC;
            float y2 = sa[nj][2] * YC, y3 = sa[nj][3] * YC;
            sa[nj][0] = (b0 & 1u) ? y0 : -1e30f;
            sa[nj][1] = (b0 & 2u) ? y1 : -1e30f;
            sa[nj][2] = (b1 & 1u) ? y2 : -1e30f;
            sa[nj][3] = (b1 & 2u) ? y3 : -1e30f;
            rm0 = fmaxf(rm0, fmaxf(sa[nj][0], sa[nj][1]));
            rm1 = fmaxf(rm1, fmaxf(sa[nj][2], sa[nj][3]));
        }
        rm0 = fmaxf(rm0, __shfl_xor_sync(0xffffffffu, rm0, 1));
        rm0 = fmaxf(rm0, __shfl_xor_sync(0xffffffffu, rm0, 2));
        rm1 = fmaxf(rm1, __shfl_xor_sync(0xffffffffu, rm1, 1));
        rm1 = fmaxf(rm1, __shfl_xor_sync(0xffffffffu, rm1, 2));
        float mn0 = fmaxf(fmaxf(m_run[0], rm0), -12000.0f);
        float mn1 = fmaxf(fmaxf(m_run[1], rm1), -12000.0f);
        float al0 = ex2(m_run[0] - mn0);
        float al1 = ex2(m_run[1] - mn1);
        m_run[0] = mn0; m_run[1] = mn1;
        l_run[0] *= al0; l_run[1] *= al1;
#pragma unroll
        for (int v = 0; v < 16; v++) {
            Oacc[v][0] *= al0; Oacc[v][1] *= al0;
            Oacc[v][2] *= al1; Oacc[v][3] *= al1;
        }

        unsigned ph[2][8];
#pragma unroll
        for (int nj = 0; nj < 8; nj++) {
            float p0 = ex2(sa[nj][0] - mn0);
            float p1 = ex2(sa[nj][1] - mn0);
            float p2 = ex2(sa[nj][2] - mn1);
            float p3 = ex2(sa[nj][3] - mn1);
            l_run[0] += p0 + p1;
            l_run[1] += p2 + p3;
            __half2 h0 = __floats2half2_rn(p0, p1);
            __half2 h1 = __floats2half2_rn(p2, p3);
            ph[0][nj] = *(unsigned*)&h0;
            ph[1][nj] = *(unsigned*)&h1;
        }

        // ---- O += P @ V : paired V fragments (two n8 tiles per ldsm.x4.trans)
#pragma unroll
        for (int kk = 0; kk < 4; kk++) {
            unsigned aH[4] = { ph[0][2 * kk], ph[1][2 * kk],
                               ph[0][2 * kk + 1], ph[1][2 * kk + 1] };
#pragma unroll
            for (int vjp = 0; vjp < 8; vjp++) {
                unsigned vb[4];
                ldsm_x4t(vb[0], vb[1], vb[2], vb[3],
                         smem_u32(&Vs[buf][(kk * 16 + (lane & 15)) * DST
                                           + (vjp * 2 + (lane >> 4)) * 8]));
                mma_f16(Oacc[2 * vjp],     aH, vb);
                mma_f16(Oacc[2 * vjp + 1], aH, vb + 2);
            }
        }
        __syncthreads();
    }

    float l0 = l_run[0], l1 = l_run[1];
    l0 += __shfl_xor_sync(0xffffffffu, l0, 1);
    l0 += __shfl_xor_sync(0xffffffffu, l0, 2);
    l1 += __shfl_xor_sync(0xffffffffu, l1, 1);
    l1 += __shfl_xor_sync(0xffffffffu, l1, 2);
    float inv0 = (l0 > 1e-10f) ? (1.0f / l0) : 0.0f;
    float inv1 = (l1 > 1e-10f) ? (1.0f / l1) : 0.0f;
    float* O0 = g_A + (size_t)(b * TQL + q0 + wq + er) * DMODEL + h * HD;
    float* O1 = O0 + 8 * DMODEL;
#pragma unroll
    for (int vj = 0; vj < 16; vj++) {
        *(float2*)&O0[vj * 8 + ec] = make_float2(Oacc[vj][0] * inv0, Oacc[vj][1] * inv0);
        *(float2*)&O1[vj * 8 + ec] = make_float2(Oacc[vj][2] * inv1, Oacc[vj][3] * inv1);
    }
}

// ---------------------------------------------------------------------------
extern "C" void kernel_launch(void* const* d_in, const int* in_sizes, int n_in,
                              void* d_out, int out_size)
{
    (void)in_sizes; (void)n_in; (void)out_size;

    const float* xq   = (const float*)d_in[0];
    const float* xkv  = (const float*)d_in[1];
    const int*   mask = (const int*)d_in[2];
    const float* Wq = (const float*)d_in[3];
    const float* bq = (const float*)d_in[4];
    const float* Wk = (const float*)d_in[5];
    const float* bk = (const float*)d_in[6];
    const float* Wv = (const float*)d_in[7];
    const float* bv = (const float*)d_in[8];
    const float* Wo = (const float*)d_in[9];
    const float* bo = (const float*)d_in[10];
    float* out = (float*)d_out;

    __half *Qh, *Kh, *Vh, *Xqh, *Xkvh, *Wqh, *Wkh, *Wvh;
    __nv_bfloat16 *WoH, *WoL, *AHp, *ALp;
    float *Ad;
    unsigned long long *Mbp;
    cudaGetSymbolAddress((void**)&Qh,   g_Qh);
    cudaGetSymbolAddress((void**)&Kh,   g_Kh);
    cudaGetSymbolAddress((void**)&Vh,   g_Vh);
    cudaGetSymbolAddress((void**)&Ad,   g_A);
    cudaGetSymbolAddress((void**)&Mbp,  g_Mb);
    cudaGetSymbolAddress((void**)&Xqh,  g_Xqh);
    cudaGetSymbolAddress((void**)&Xkvh, g_Xkvh);
    cudaGetSymbolAddress((void**)&Wqh,  g_Wqh);
    cudaGetSymbolAddress((void**)&Wkh,  g_Wkh);
    cudaGetSymbolAddress((void**)&Wvh,  g_Wvh);
    cudaGetSymbolAddress((void**)&WoH,  g_WoH);
    cudaGetSymbolAddress((void**)&WoL,  g_WoL);
    cudaGetSymbolAddress((void**)&AHp,  g_AH);
    cudaGetSymbolAddress((void**)&ALp,  g_AL);

    const int smem_attn = SQ_BYTES + 4 * SKV_BYTES + 2 * 128 * 8;
    const int smem_f16  = 2 * F16_STAGE;
    const int smem_b3   = 2 * B3_STAGE;
    static int configured = 0;
    if (!configured) {
        cudaFuncSetAttribute(attn2_kernel,
                             cudaFuncAttributeMaxDynamicSharedMemorySize, smem_attn);
        cudaFuncSetAttribute(gemm_f16_kernel,
                             cudaFuncAttributeMaxDynamicSharedMemorySize, smem_f16);
        cudaFuncSetAttribute(gemm_bf16x3_kernel,
                             cudaFuncAttributeMaxDynamicSharedMemorySize, smem_b3);
        configured = 1;
    }

    dim3 thr(256);
    const int nW8  = DMODEL * DMODEL / 8;          // 131072
    const int nXq8 = NB * TQL * DMODEL / 8;        // 262144
    const int nXk8 = NB * TKVL * DMODEL / 8;       // 2097152

    mask_pack_kernel<<<1024, thr>>>(mask, (unsigned*)Mbp);
    cvt_f16_kernel<<<1024, thr>>>((const float4*)xq,  (uint4*)Xqh,  nXq8);
    cvt_f16_kernel<<<2048, thr>>>((const float4*)xkv, (uint4*)Xkvh, nXk8);
    cvt3_f16_kernel<<<1536, thr>>>((const float4*)Wq, (const float4*)Wk,
                                   (const float4*)Wv,
                                   (uint4*)Wqh, (uint4*)Wkh, (uint4*)Wvh, nW8);
    split_bf16_kernel<<<512, thr>>>((const float4*)Wo, (uint4*)WoH, (uint4*)WoL, nW8);

    gemm_f16_kernel<<<dim3(8, 16),  thr, smem_f16>>>(Xqh,  Wqh, bq, Qh);
    gemm_f16_kernel<<<dim3(8, 128), thr, smem_f16>>>(Xkvh, Wkh, bk, Kh);
    gemm_f16_kernel<<<dim3(8, 128), thr, smem_f16>>>(Xkvh, Wvh, bv, Vh);

    attn2_kernel<<<dim3(TQL / 128, NH, NB), thr, smem_attn>>>();

    split_bf16_kernel<<<1024, thr>>>((const float4*)Ad, (uint4*)AHp, (uint4*)ALp, nXq8);
    gemm_bf16x3_kernel<<<dim3(8, 16), thr, smem_b3>>>(AHp, ALp, WoH, WoL, bo, out);
}

// round 16
// speedup vs baseline: 6.3296x; 1.0208x over previous
#include <cuda_runtime.h>
#include <cuda_bf16.h>
#include <cuda_fp16.h>
#include <stdint.h>
#include <math.h>
#include <float.h>

#define DMODEL 1024
#define NB     4
#define TQL    512
#define TKVL   4096
#define NH     8
#define HD     128

// --------------------------- device scratch --------------------------------
__device__ __half g_Qh[NB * TQL  * DMODEL];
__device__ __half g_Kh[NB * TKVL * DMODEL];
__device__ __half g_Vh[NB * TKVL * DMODEL];
__device__ unsigned long long g_Mb[NB * TQL * (TKVL / 64)];

// pre-converted operands
__device__ __half g_Xqh [NB * TQL  * DMODEL];
__device__ __half g_Xkvh[NB * TKVL * DMODEL];
__device__ __half g_Wqh [DMODEL * DMODEL];
__device__ __half g_Wkh [DMODEL * DMODEL];
__device__ __half g_Wvh [DMODEL * DMODEL];
__device__ __nv_bfloat16 g_WoH[DMODEL * DMODEL];
__device__ __nv_bfloat16 g_WoL[DMODEL * DMODEL];
__device__ __nv_bfloat16 g_AH [NB * TQL * DMODEL];
__device__ __nv_bfloat16 g_AL [NB * TQL * DMODEL];

// ---------------------------- mma helpers ----------------------------------
__device__ __forceinline__ unsigned smem_u32(const void* p) {
    return (unsigned)__cvta_generic_to_shared(p);
}
__device__ __forceinline__ void ldsm_x4(unsigned& r0, unsigned& r1,
                                        unsigned& r2, unsigned& r3, unsigned a) {
    asm volatile("ldmatrix.sync.aligned.m8n8.x4.shared.b16 {%0,%1,%2,%3}, [%4];"
                 : "=r"(r0), "=r"(r1), "=r"(r2), "=r"(r3) : "r"(a));
}
__device__ __forceinline__ void ldsm_x4t(unsigned& r0, unsigned& r1,
                                         unsigned& r2, unsigned& r3, unsigned a) {
    asm volatile("ldmatrix.sync.aligned.m8n8.x4.trans.shared.b16 {%0,%1,%2,%3}, [%4];"
                 : "=r"(r0), "=r"(r1), "=r"(r2), "=r"(r3) : "r"(a));
}
__device__ __forceinline__ void mma_bf16(float* d, const unsigned* a, const unsigned* b) {
    asm volatile(
        "mma.sync.aligned.m16n8k16.row.col.f32.bf16.bf16.f32 "
        "{%0,%1,%2,%3}, {%4,%5,%6,%7}, {%8,%9}, {%0,%1,%2,%3};"
        : "+f"(d[0]), "+f"(d[1]), "+f"(d[2]), "+f"(d[3])
        : "r"(a[0]), "r"(a[1]), "r"(a[2]), "r"(a[3]), "r"(b[0]), "r"(b[1]));
}
__device__ __forceinline__ void mma_f16(float* d, const unsigned* a, const unsigned* b) {
    asm volatile(
        "mma.sync.aligned.m16n8k16.row.col.f32.f16.f16.f32 "
        "{%0,%1,%2,%3}, {%4,%5,%6,%7}, {%8,%9}, {%0,%1,%2,%3};"
        : "+f"(d[0]), "+f"(d[1]), "+f"(d[2]), "+f"(d[3])
        : "r"(a[0]), "r"(a[1]), "r"(a[2]), "r"(a[3]), "r"(b[0]), "r"(b[1]));
}
#define CP_ASYNC16(dst, src) \
    asm volatile("cp.async.cg.shared.global [%0], [%1], 16;" :: "r"(dst), "l"(src))
#define CP_ASYNC8(dst, src) \
    asm volatile("cp.async.ca.shared.global [%0], [%1], 8;"  :: "r"(dst), "l"(src))
#define CP_COMMIT()  asm volatile("cp.async.commit_group;")
#define CP_WAIT0()   asm volatile("cp.async.wait_group 0;")
#define CP_WAIT1()   asm volatile("cp.async.wait_group 1;")

__device__ __forceinline__ float ex2(float x) {
    float y;
    asm("ex2.approx.f32 %0, %1;" : "=f"(y) : "f"(x));
    return y;
}

// ======================= convert / split kernels ===========================
__device__ __forceinline__ uint4 pack_f16x8(float4 a, float4 b) {
    __half2 h0 = __floats2half2_rn(a.x, a.y), h1 = __floats2half2_rn(a.z, a.w);
    __half2 h2 = __floats2half2_rn(b.x, b.y), h3 = __floats2half2_rn(b.z, b.w);
    uint4 u;
    u.x = *(unsigned*)&h0; u.y = *(unsigned*)&h1;
    u.z = *(unsigned*)&h2; u.w = *(unsigned*)&h3;
    return u;
}
__global__ __launch_bounds__(256) void cvt_f16_kernel(
    const float4* __restrict__ x, uint4* __restrict__ out, int n8)
{
    int i = blockIdx.x * 256 + threadIdx.x;
    int stride = gridDim.x * 256;
    for (; i < n8; i += stride)
        out[i] = pack_f16x8(x[2 * i], x[2 * i + 1]);
}
__global__ __launch_bounds__(256) void cvt3_f16_kernel(
    const float4* __restrict__ w0, const float4* __restrict__ w1,
    const float4* __restrict__ w2,
    uint4* __restrict__ o0, uint4* __restrict__ o1, uint4* __restrict__ o2,
    int n8)
{
    int i = blockIdx.x * 256 + threadIdx.x;
    int stride = gridDim.x * 256;
    int total = 3 * n8;
    for (; i < total; i += stride) {
        int m = i / n8, j = i - m * n8;
        const float4* w = (m == 0) ? w0 : (m == 1) ? w1 : w2;
        uint4* o = (m == 0) ? o0 : (m == 1) ? o1 : o2;
        o[j] = pack_f16x8(w[2 * j], w[2 * j + 1]);
    }
}
__global__ __launch_bounds__(256) void split_bf16_kernel(
    const float4* __restrict__ x, uint4* __restrict__ hi,
    uint4* __restrict__ lo, int n8)
{
    int i = blockIdx.x * 256 + threadIdx.x;
    int stride = gridDim.x * 256;
    for (; i < n8; i += stride) {
        float4 a = x[2 * i], b = x[2 * i + 1];
        float v[8] = { a.x, a.y, a.z, a.w, b.x, b.y, b.z, b.w };
        __nv_bfloat16 h[8], l[8];
#pragma unroll
        for (int k = 0; k < 8; k++) {
            h[k] = __float2bfloat16(v[k]);
            l[k] = __float2bfloat16(v[k] - __bfloat162float(h[k]));
        }
        uint4 uh, ul;
        __nv_bfloat162 t;
        t = __nv_bfloat162(h[0], h[1]); uh.x = *(unsigned*)&t;
        t = __nv_bfloat162(h[2], h[3]); uh.y = *(unsigned*)&t;
        t = __nv_bfloat162(h[4], h[5]); uh.z = *(unsigned*)&t;
        t = __nv_bfloat162(h[6], h[7]); uh.w = *(unsigned*)&t;
        t = __nv_bfloat162(l[0], l[1]); ul.x = *(unsigned*)&t;
        t = __nv_bfloat162(l[2], l[3]); ul.y = *(unsigned*)&t;
        t = __nv_bfloat162(l[4], l[5]); ul.z = *(unsigned*)&t;
        t = __nv_bfloat162(l[6], l[7]); ul.w = *(unsigned*)&t;
        hi[i] = uh;
        lo[i] = ul;
    }
}

// =========================== mask bit-pack =================================
__global__ __launch_bounds__(256) void mask_pack_kernel(const int* __restrict__ m,
                                                        unsigned* __restrict__ out)
{
    const int lane = threadIdx.x & 31;
    const int wg   = (blockIdx.x * 256 + threadIdx.x) >> 5;
    const int base = wg * 1024;
    unsigned myw = 0;
#pragma unroll
    for (int it = 0; it < 32; it++) {
        int v = m[base + it * 32 + lane];
        unsigned b = __ballot_sync(0xffffffffu, v != 0);
        if (lane == it) myw = b;
    }
    out[wg * 32 + lane] = myw;
}

// ===========================================================================
// fp16 GEMM (Q projection): C = A @ W + bias, fp16 in/out, fp32 acc.
// ===========================================================================
#define AS 40
#define WS 136

#define F16_A_BYTES (128 * AS * 2)
#define F16_W_BYTES (32 * WS * 2)
#define F16_STAGE   (F16_A_BYTES + F16_W_BYTES)

__global__ __launch_bounds__(256) void gemm_f16_kernel(
    const __half* __restrict__ A, const __half* __restrict__ W,
    const float* __restrict__ bias, __half* __restrict__ Ch)
{
    extern __shared__ __align__(16) char smraw[];

    const int tid  = threadIdx.x;
    const int lane = tid & 31;
    const int wid  = tid >> 5;
    const int bm   = blockIdx.y * 128;
    const int bn   = blockIdx.x * 128;
    const int wm   = (wid >> 2) * 64;
    const int wn   = (wid & 3) * 32;

    float acc[4][4][4];
#pragma unroll
    for (int mi = 0; mi < 4; mi++)
#pragma unroll
        for (int nj = 0; nj < 4; nj++)
#pragma unroll
            for (int r = 0; r < 4; r++) acc[mi][nj][r] = 0.0f;

    const int a_row = tid >> 1,  a_c = (tid & 1) * 16;
    const int w_row = tid >> 3,  w_c = (tid & 7) * 16;

    const __half* Ap = A + (size_t)(bm + a_row) * DMODEL + a_c;
    const __half* Wp = W + (size_t)w_row * DMODEL + bn + w_c;

    auto issue = [&](int kt, int st) {
        char* base = smraw + st * F16_STAGE;
        __half* sA = (__half*)base;
        __half* sW = (__half*)(base + F16_A_BYTES);
        const int k0 = kt * 32;
        CP_ASYNC16(smem_u32(&sA[a_row * AS + a_c]),     Ap + k0);
        CP_ASYNC16(smem_u32(&sA[a_row * AS + a_c + 8]), Ap + k0 + 8);
        CP_ASYNC16(smem_u32(&sW[w_row * WS + w_c]),     Wp + (size_t)k0 * DMODEL);
        CP_ASYNC16(smem_u32(&sW[w_row * WS + w_c + 8]), Wp + (size_t)k0 * DMODEL + 8);
    };

    issue(0, 0);
    CP_COMMIT();

    const int NT = DMODEL / 32;
    for (int kt = 0; kt < NT; kt++) {
        const int st = kt & 1;
        if (kt + 1 < NT) { issue(kt + 1, st ^ 1); CP_COMMIT(); CP_WAIT1(); }
        else             { CP_WAIT0(); }
        __syncthreads();

        char* base = smraw + st * F16_STAGE;
        __half* sA = (__half*)base;
        __half* sW = (__half*)(base + F16_A_BYTES);

#pragma unroll
        for (int ks = 0; ks < 2; ks++) {
            const int k16 = ks * 16;
            unsigned ah[4][4], bw[4][2];
            const int ar = lane & 15, ac = (lane >> 4) * 8;
#pragma unroll
            for (int mi = 0; mi < 4; mi++)
                ldsm_x4(ah[mi][0], ah[mi][1], ah[mi][2], ah[mi][3],
                        smem_u32(&sA[(wm + mi * 16 + ar) * AS + k16 + ac]));
#pragma unroll
            for (int njp = 0; njp < 2; njp++) {
                unsigned t0, t1, t2, t3;
                ldsm_x4t(t0, t1, t2, t3,
                         smem_u32(&sW[(k16 + (lane & 15)) * WS
                                      + wn + (njp * 2 + (lane >> 4)) * 8]));
                bw[2 * njp][0] = t0; bw[2 * njp][1] = t1;
                bw[2 * njp + 1][0] = t2; bw[2 * njp + 1][1] = t3;
            }
#pragma unroll
            for (int mi = 0; mi < 4; mi++)
#pragma unroll
                for (int nj = 0; nj < 4; nj++)
                    mma_f16(acc[mi][nj], ah[mi], bw[nj]);
        }
        __syncthreads();
    }

    const int er = lane >> 2, ec = (lane & 3) * 2;
#pragma unroll
    for (int mi = 0; mi < 4; mi++)
#pragma unroll
        for (int nj = 0; nj < 4; nj++) {
            int row = bm + wm + mi * 16 + er;
            int col = bn + wn + nj * 8 + ec;
            float2 bv = *(const float2*)&bias[col];
            *(__half2*)&Ch[(size_t)row * DMODEL + col] =
                __floats2half2_rn(acc[mi][nj][0] + bv.x, acc[mi][nj][1] + bv.y);
            *(__half2*)&Ch[(size_t)(row + 8) * DMODEL + col] =
                __floats2half2_rn(acc[mi][nj][2] + bv.x, acc[mi][nj][3] + bv.y);
        }
}

// ===========================================================================
// Fused K+V projection GEMM: one A tile feeds both W_k and W_v.
// Per CTA: 128x128 output tile of BOTH K and V. 8 warps, 64x32 per warp each.
// ===========================================================================
#define FKV_STAGE (F16_A_BYTES + 2 * F16_W_BYTES)   // 10240 + 17408 = 27648

__global__ __launch_bounds__(256) void gemm_fkv_kernel(
    const __half* __restrict__ A,
    const __half* __restrict__ Wk, const __half* __restrict__ Wv,
    const float* __restrict__ biask, const float* __restrict__ biasv,
    __half* __restrict__ Ck, __half* __restrict__ Cv)
{
    extern __shared__ __align__(16) char smraw[];

    const int tid  = threadIdx.x;
    const int lane = tid & 31;
    const int wid  = tid >> 5;
    const int bm   = blockIdx.y * 128;
    const int bn   = blockIdx.x * 128;
    const int wm   = (wid >> 2) * 64;
    const int wn   = (wid & 3) * 32;

    float accK[4][4][4], accV[4][4][4];
#pragma unroll
    for (int mi = 0; mi < 4; mi++)
#pragma unroll
        for (int nj = 0; nj < 4; nj++)
#pragma unroll
            for (int r = 0; r < 4; r++) { accK[mi][nj][r] = 0.0f; accV[mi][nj][r] = 0.0f; }

    const int a_row = tid >> 1,  a_c = (tid & 1) * 16;
    const int w_row = tid >> 3,  w_c = (tid & 7) * 16;

    const __half* Ap  = A  + (size_t)(bm + a_row) * DMODEL + a_c;
    const __half* Wkp = Wk + (size_t)w_row * DMODEL + bn + w_c;
    const __half* Wvp = Wv + (size_t)w_row * DMODEL + bn + w_c;

    auto issue = [&](int kt, int st) {
        char* base = smraw + st * FKV_STAGE;
        __half* sA  = (__half*)base;
        __half* sWk = (__half*)(base + F16_A_BYTES);
        __half* sWv = (__half*)(base + F16_A_BYTES + F16_W_BYTES);
        const int k0 = kt * 32;
        CP_ASYNC16(smem_u32(&sA[a_row * AS + a_c]),      Ap + k0);
        CP_ASYNC16(smem_u32(&sA[a_row * AS + a_c + 8]),  Ap + k0 + 8);
        CP_ASYNC16(smem_u32(&sWk[w_row * WS + w_c]),     Wkp + (size_t)k0 * DMODEL);
        CP_ASYNC16(smem_u32(&sWk[w_row * WS + w_c + 8]), Wkp + (size_t)k0 * DMODEL + 8);
        CP_ASYNC16(smem_u32(&sWv[w_row * WS + w_c]),     Wvp + (size_t)k0 * DMODEL);
        CP_ASYNC16(smem_u32(&sWv[w_row * WS + w_c + 8]), Wvp + (size_t)k0 * DMODEL + 8);
    };

    issue(0, 0);
    CP_COMMIT();

    const int NT = DMODEL / 32;
    for (int kt = 0; kt < NT; kt++) {
        const int st = kt & 1;
        if (kt + 1 < NT) { issue(kt + 1, st ^ 1); CP_COMMIT(); CP_WAIT1(); }
        else             { CP_WAIT0(); }
        __syncthreads();

        char* base = smraw + st * FKV_STAGE;
        __half* sA  = (__half*)base;
        __half* sWk = (__half*)(base + F16_A_BYTES);
        __half* sWv = (__half*)(base + F16_A_BYTES + F16_W_BYTES);

#pragma unroll
        for (int ks = 0; ks < 2; ks++) {
            const int k16 = ks * 16;
            unsigned ah[4][4], bk[4][2], bv[4][2];
            const int ar = lane & 15, ac = (lane >> 4) * 8;
#pragma unroll
            for (int mi = 0; mi < 4; mi++)
                ldsm_x4(ah[mi][0], ah[mi][1], ah[mi][2], ah[mi][3],
                        smem_u32(&sA[(wm + mi * 16 + ar) * AS + k16 + ac]));
#pragma unroll
            for (int njp = 0; njp < 2; njp++) {
                unsigned t0, t1, t2, t3;
                ldsm_x4t(t0, t1, t2, t3,
                         smem_u32(&sWk[(k16 + (lane & 15)) * WS
                                       + wn + (njp * 2 + (lane >> 4)) * 8]));
                bk[2 * njp][0] = t0; bk[2 * njp][1] = t1;
                bk[2 * njp + 1][0] = t2; bk[2 * njp + 1][1] = t3;
                ldsm_x4t(t0, t1, t2, t3,
                         smem_u32(&sWv[(k16 + (lane & 15)) * WS
                                       + wn + (njp * 2 + (lane >> 4)) * 8]));
                bv[2 * njp][0] = t0; bv[2 * njp][1] = t1;
                bv[2 * njp + 1][0] = t2; bv[2 * njp + 1][1] = t3;
            }
#pragma unroll
            for (int mi = 0; mi < 4; mi++)
#pragma unroll
                for (int nj = 0; nj < 4; nj++) {
                    mma_f16(accK[mi][nj], ah[mi], bk[nj]);
                    mma_f16(accV[mi][nj], ah[mi], bv[nj]);
                }
        }
        __syncthreads();
    }

    const int er = lane >> 2, ec = (lane & 3) * 2;
#pragma unroll
    for (int mi = 0; mi < 4; mi++)
#pragma unroll
        for (int nj = 0; nj < 4; nj++) {
            int row = bm + wm + mi * 16 + er;
            int col = bn + wn + nj * 8 + ec;
            float2 bk2 = *(const float2*)&biask[col];
            float2 bv2 = *(const float2*)&biasv[col];
            *(__half2*)&Ck[(size_t)row * DMODEL + col] =
                __floats2half2_rn(accK[mi][nj][0] + bk2.x, accK[mi][nj][1] + bk2.y);
            *(__half2*)&Ck[(size_t)(row + 8) * DMODEL + col] =
                __floats2half2_rn(accK[mi][nj][2] + bk2.x, accK[mi][nj][3] + bk2.y);
            *(__half2*)&Cv[(size_t)row * DMODEL + col] =
                __floats2half2_rn(accV[mi][nj][0] + bv2.x, accV[mi][nj][1] + bv2.y);
            *(__half2*)&Cv[(size_t)(row + 8) * DMODEL + col] =
                __floats2half2_rn(accV[mi][nj][2] + bv2.x, accV[mi][nj][3] + bv2.y);
        }
}

// ===========================================================================
// bf16x3 GEMM (O projection): pre-split hi/lo both operands, fp32 out.
// ===========================================================================
#define B3_A_BYTES (128 * AS * 2)
#define B3_W_BYTES (32 * WS * 2)
#define B3_STAGE   (2 * B3_A_BYTES + 2 * B3_W_BYTES)

__global__ __launch_bounds__(256) void gemm_bf16x3_kernel(
    const __nv_bfloat16* __restrict__ AH, const __nv_bfloat16* __restrict__ AL,
    const __nv_bfloat16* __restrict__ WH, const __nv_bfloat16* __restrict__ WL,
    const float* __restrict__ bias, float* __restrict__ C)
{
    extern __shared__ __align__(16) char smraw[];

    const int tid  = threadIdx.x;
    const int lane = tid & 31;
    const int wid  = tid >> 5;
    const int bm   = blockIdx.y * 128;
    const int bn   = blockIdx.x * 128;
    const int wm   = (wid >> 2) * 64;
    const int wn   = (wid & 3) * 32;

    float acc[4][4][4];
#pragma unroll
    for (int mi = 0; mi < 4; mi++)
#pragma unroll
        for (int nj = 0; nj < 4; nj++)
#pragma unroll
            for (int r = 0; r < 4; r++) acc[mi][nj][r] = 0.0f;

    const int a_row = tid >> 1,  a_c = (tid & 1) * 16;
    const int w_row = tid >> 3,  w_c = (tid & 7) * 16;

    const __nv_bfloat16* ApH = AH + (size_t)(bm + a_row) * DMODEL + a_c;
    const __nv_bfloat16* ApL = AL + (size_t)(bm + a_row) * DMODEL + a_c;
    const __nv_bfloat16* WpH = WH + (size_t)w_row * DMODEL + bn + w_c;
    const __nv_bfloat16* WpL = WL + (size_t)w_row * DMODEL + bn + w_c;

    auto issue = [&](int kt, int st) {
        char* base = smraw + st * B3_STAGE;
        __nv_bfloat16* sAH = (__nv_bfloat16*)base;
        __nv_bfloat16* sAL = (__nv_bfloat16*)(base + B3_A_BYTES);
        __nv_bfloat16* sWH = (__nv_bfloat16*)(base + 2 * B3_A_BYTES);
        __nv_bfloat16* sWL = (__nv_bfloat16*)(base + 2 * B3_A_BYTES + B3_W_BYTES);
        const int k0 = kt * 32;
        CP_ASYNC16(smem_u32(&sAH[a_row * AS + a_c]),     ApH + k0);
        CP_ASYNC16(smem_u32(&sAH[a_row * AS + a_c + 8]), ApH + k0 + 8);
        CP_ASYNC16(smem_u32(&sAL[a_row * AS + a_c]),     ApL + k0);
        CP_ASYNC16(smem_u32(&sAL[a_row * AS + a_c + 8]), ApL + k0 + 8);
        CP_ASYNC16(smem_u32(&sWH[w_row * WS + w_c]),     WpH + (size_t)k0 * DMODEL);
        CP_ASYNC16(smem_u32(&sWH[w_row * WS + w_c + 8]), WpH + (size_t)k0 * DMODEL + 8);
        CP_ASYNC16(smem_u32(&sWL[w_row * WS + w_c]),     WpL + (size_t)k0 * DMODEL);
        CP_ASYNC16(smem_u32(&sWL[w_row * WS + w_c + 8]), WpL + (size_t)k0 * DMODEL + 8);
    };

    issue(0, 0);
    CP_COMMIT();

    const int NT = DMODEL / 32;
    for (int kt = 0; kt < NT; kt++) {
        const int st = kt & 1;
        if (kt + 1 < NT) { issue(kt + 1, st ^ 1); CP_COMMIT(); CP_WAIT1(); }
        else             { CP_WAIT0(); }
        __syncthreads();

        char* base = smraw + st * B3_STAGE;
        __nv_bfloat16* sAH = (__nv_bfloat16*)base;
        __nv_bfloat16* sAL = (__nv_bfloat16*)(base + B3_A_BYTES);
        __nv_bfloat16* sWH = (__nv_bfloat16*)(base + 2 * B3_A_BYTES);
        __nv_bfloat16* sWL = (__nv_bfloat16*)(base + 2 * B3_A_BYTES + B3_W_BYTES);

#pragma unroll
        for (int ks = 0; ks < 2; ks++) {
            const int k16 = ks * 16;
            unsigned ah[4][4], al[4][4], bh[4][2], bl[4][2];
            const int ar = lane & 15, ac = (lane >> 4) * 8;
#pragma unroll
            for (int mi = 0; mi < 4; mi++) {
                ldsm_x4(ah[mi][0], ah[mi][1], ah[mi][2], ah[mi][3],
                        smem_u32(&sAH[(wm + mi * 16 + ar) * AS + k16 + ac]));
                ldsm_x4(al[mi][0], al[mi][1], al[mi][2], al[mi][3],
                        smem_u32(&sAL[(wm + mi * 16 + ar) * AS + k16 + ac]));
            }
#pragma unroll
            for (int njp = 0; njp < 2; njp++) {
                unsigned t0, t1, t2, t3;
                ldsm_x4t(t0, t1, t2, t3,
                         smem_u32(&sWH[(k16 + (lane & 15)) * WS
                                       + wn + (njp * 2 + (lane >> 4)) * 8]));
                bh[2 * njp][0] = t0; bh[2 * njp][1] = t1;
                bh[2 * njp + 1][0] = t2; bh[2 * njp + 1][1] = t3;
                ldsm_x4t(t0, t1, t2, t3,
                         smem_u32(&sWL[(k16 + (lane & 15)) * WS
                                       + wn + (njp * 2 + (lane >> 4)) * 8]));
                bl[2 * njp][0] = t0; bl[2 * njp][1] = t1;
                bl[2 * njp + 1][0] = t2; bl[2 * njp + 1][1] = t3;
            }
#pragma unroll
            for (int mi = 0; mi < 4; mi++)
#pragma unroll
                for (int nj = 0; nj < 4; nj++) {
                    mma_bf16(acc[mi][nj], ah[mi], bh[nj]);
                    mma_bf16(acc[mi][nj], ah[mi], bl[nj]);
                    mma_bf16(acc[mi][nj], al[mi], bh[nj]);
                }
        }
        __syncthreads();
    }

    const int er = lane >> 2, ec = (lane & 3) * 2;
#pragma unroll
    for (int mi = 0; mi < 4; mi++)
#pragma unroll
        for (int nj = 0; nj < 4; nj++) {
            int row = bm + wm + mi * 16 + er;
            int col = bn + wn + nj * 8 + ec;
            float2 bv = *(const float2*)&bias[col];
            *(float2*)&C[(size_t)row * DMODEL + col] =
                make_float2(acc[mi][nj][0] + bv.x, acc[mi][nj][1] + bv.y);
            *(float2*)&C[(size_t)(row + 8) * DMODEL + col] =
                make_float2(acc[mi][nj][2] + bv.x, acc[mi][nj][3] + bv.y);
        }
}

// ===========================================================================
// Flash attention v2 (tensor cores, fp16, fp32 acc). P single fp16.
// MUFU ex2 softmax; paired ldsm; epilogue writes bf16 hi/lo split directly.
// ===========================================================================
#define DST 136
#define SQ_BYTES  (128 * DST * 2)
#define SKV_BYTES (64  * DST * 2)

__global__ __launch_bounds__(256, 1) void attn2_kernel()
{
    extern __shared__ __align__(16) char smraw[];
    __half* Qs = (__half*)smraw;
    __half* Ks[2] = { (__half*)(smraw + SQ_BYTES),
                      (__half*)(smraw + SQ_BYTES + SKV_BYTES) };
    __half* Vs[2] = { (__half*)(smraw + SQ_BYTES + 2 * SKV_BYTES),
                      (__half*)(smraw + SQ_BYTES + 3 * SKV_BYTES) };
    unsigned long long* Mb[2] = {
        (unsigned long long*)(smraw + SQ_BYTES + 4 * SKV_BYTES),
        (unsigned long long*)(smraw + SQ_BYTES + 4 * SKV_BYTES + 128 * 8) };

    const int tid  = threadIdx.x;
    const int lane = tid & 31;
    const int wid  = tid >> 5;
    const int wq   = wid * 16;
    const int er   = lane >> 2;
    const int ec   = (lane & 3) * 2;
    const int q0   = blockIdx.x * 128;
    const int h    = blockIdx.y;
    const int b    = blockIdx.z;

    const __half* Qg = g_Qh + (size_t)(b * TQL + q0) * DMODEL + h * HD;
    const __half* Kg = g_Kh + (size_t)(b * TKVL) * DMODEL + h * HD;
    const __half* Vg = g_Vh + (size_t)(b * TKVL) * DMODEL + h * HD;
    const unsigned long long* Mg = g_Mb + (size_t)(b * TQL + q0) * (TKVL / 64);

    {
#pragma unroll
        for (int it = 0; it < 4; it++) {
            int c = tid + it * 256;
            int r = c >> 4, c8 = (c & 15) * 8;
            CP_ASYNC16(smem_u32(&Ks[0][r * DST + c8]), Kg + (size_t)r * DMODEL + c8);
            CP_ASYNC16(smem_u32(&Vs[0][r * DST + c8]), Vg + (size_t)r * DMODEL + c8);
        }
        if (tid < 128)
            CP_ASYNC8(smem_u32(&Mb[0][tid]), Mg + (size_t)tid * (TKVL / 64));
        CP_COMMIT();
    }
#pragma unroll
    for (int it = 0; it < 8; it++) {
        int c = tid + it * 256;
        int r = c >> 4, c8 = (c & 15) * 8;
        *(uint4*)&Qs[r * DST + c8] = *(const uint4*)(Qg + (size_t)r * DMODEL + c8);
    }

    const float YC = 1.4426950408889634f * 0.08838834764831845f;

    float Oacc[16][4];
#pragma unroll
    for (int v = 0; v < 16; v++)
#pragma unroll
        for (int r = 0; r < 4; r++) Oacc[v][r] = 0.0f;
    float m_run[2] = { -12000.0f, -12000.0f };
    float l_run[2] = { 0.0f, 0.0f };

    for (int t = 0; t < TKVL / 64; t++) {
        const int buf = t & 1, nbuf = buf ^ 1;
        if (t + 1 < TKVL / 64) {
            const int kv1 = (t + 1) * 64;
#pragma unroll
            for (int it = 0; it < 4; it++) {
                int c = tid + it * 256;
                int r = c >> 4, c8 = (c & 15) * 8;
                CP_ASYNC16(smem_u32(&Ks[nbuf][r * DST + c8]),
                           Kg + (size_t)(kv1 + r) * DMODEL + c8);
                CP_ASYNC16(smem_u32(&Vs[nbuf][r * DST + c8]),
                           Vg + (size_t)(kv1 + r) * DMODEL + c8);
            }
            if (tid < 128)
                CP_ASYNC8(smem_u32(&Mb[nbuf][tid]),
                          Mg + (size_t)tid * (TKVL / 64) + (kv1 >> 6));
            CP_COMMIT();
            CP_WAIT1();
        } else {
            CP_WAIT0();
        }
        __syncthreads();

        float sa[8][4];
#pragma unroll
        for (int nj = 0; nj < 8; nj++)
#pragma unroll
            for (int r = 0; r < 4; r++) sa[nj][r] = 0.0f;

#pragma unroll
        for (int kk = 0; kk < 8; kk++) {
            unsigned qa[4];
            ldsm_x4(qa[0], qa[1], qa[2], qa[3],
                    smem_u32(&Qs[(wq + (lane & 15)) * DST + kk * 16 + (lane >> 4) * 8]));
#pragma unroll
            for (int njp = 0; njp < 4; njp++) {
                unsigned kb[4];
                ldsm_x4(kb[0], kb[1], kb[2], kb[3],
                        smem_u32(&Ks[buf][((njp * 2 + ((lane >> 4) & 1)) * 8
                                           + (lane & 7)) * DST
                                          + kk * 16 + ((lane >> 3) & 1) * 8]));
                mma_f16(sa[2 * njp],     qa, kb);
                mma_f16(sa[2 * njp + 1], qa, kb + 2);
            }
        }

        const unsigned long long mb0 = Mb[buf][wq + er];
        const unsigned long long mb1 = Mb[buf][wq + er + 8];
        float rm0 = -1e30f, rm1 = -1e30f;
#pragma unroll
        for (int nj = 0; nj < 8; nj++) {
            unsigned b0 = (unsigned)(mb0 >> (nj * 8 + ec)) & 3u;
            unsigned b1 = (unsigned)(mb1 >> (nj * 8 + ec)) & 3u;
            float y0 = sa[nj][0] * YC, y1 = sa[nj][1] * YC;
            float y2 = sa[nj][2] * YC, y3 = sa[nj][3] * YC;
            sa[nj][0] = (b0 & 1u) ? y0 : -1e30f;
            sa[nj][1] = (b0 & 2u) ? y1 : -1e30f;
            sa[nj][2] = (b1 & 1u) ? y2 : -1e30f;
            sa[nj][3] = (b1 & 2u) ? y3 : -1e30f;
            rm0 = fmaxf(rm0, fmaxf(sa[nj][0], sa[nj][1]));
            rm1 = fmaxf(rm1, fmaxf(sa[nj][2], sa[nj][3]));
        }
        rm0 = fmaxf(rm0, __shfl_xor_sync(0xffffffffu, rm0, 1));
        rm0 = fmaxf(rm0, __shfl_xor_sync(0xffffffffu, rm0, 2));
        rm1 = fmaxf(rm1, __shfl_xor_sync(0xffffffffu, rm1, 1));
        rm1 = fmaxf(rm1, __shfl_xor_sync(0xffffffffu, rm1, 2));
        float mn0 = fmaxf(fmaxf(m_run[0], rm0), -12000.0f);
        float mn1 = fmaxf(fmaxf(m_run[1], rm1), -12000.0f);
        float al0 = ex2(m_run[0] - mn0);
        float al1 = ex2(m_run[1] - mn1);
        m_run[0] = mn0; m_run[1] = mn1;
        l_run[0] *= al0; l_run[1] *= al1;
#pragma unroll
        for (int v = 0; v < 16; v++) {
            Oacc[v][0] *= al0; Oacc[v][1] *= al0;
            Oacc[v][2] *= al1; Oacc[v][3] *= al1;
        }

        unsigned ph[2][8];
#pragma unroll
        for (int nj = 0; nj < 8; nj++) {
            float p0 = ex2(sa[nj][0] - mn0);
            float p1 = ex2(sa[nj][1] - mn0);
            float p2 = ex2(sa[nj][2] - mn1);
            float p3 = ex2(sa[nj][3] - mn1);
            l_run[0] += p0 + p1;
            l_run[1] += p2 + p3;
            __half2 h0 = __floats2half2_rn(p0, p1);
            __half2 h1 = __floats2half2_rn(p2, p3);
            ph[0][nj] = *(unsigned*)&h0;
            ph[1][nj] = *(unsigned*)&h1;
        }

#pragma unroll
        for (int kk = 0; kk < 4; kk++) {
            unsigned aH[4] = { ph[0][2 * kk], ph[1][2 * kk],
                               ph[0][2 * kk + 1], ph[1][2 * kk + 1] };
#pragma unroll
            for (int vjp = 0; vjp < 8; vjp++) {
                unsigned vb[4];
                ldsm_x4t(vb[0], vb[1], vb[2], vb[3],
                         smem_u32(&Vs[buf][(kk * 16 + (lane & 15)) * DST
                                           + (vjp * 2 + (lane >> 4)) * 8]));
                mma_f16(Oacc[2 * vjp],     aH, vb);
                mma_f16(Oacc[2 * vjp + 1], aH, vb + 2);
            }
        }
        __syncthreads();
    }

    float l0 = l_run[0], l1 = l_run[1];
    l0 += __shfl_xor_sync(0xffffffffu, l0, 1);
    l0 += __shfl_xor_sync(0xffffffffu, l0, 2);
    l1 += __shfl_xor_sync(0xffffffffu, l1, 1);
    l1 += __shfl_xor_sync(0xffffffffu, l1, 2);
    float inv0 = (l0 > 1e-10f) ? (1.0f / l0) : 0.0f;
    float inv1 = (l1 > 1e-10f) ? (1.0f / l1) : 0.0f;

    // epilogue: write bf16 hi/lo split of O directly (feeds O-projection)
    size_t base0 = (size_t)(b * TQL + q0 + wq + er) * DMODEL + h * HD;
    size_t base1 = base0 + 8 * DMODEL;
#pragma unroll
    for (int vj = 0; vj < 16; vj++) {
        float v0 = Oacc[vj][0] * inv0, v1 = Oacc[vj][1] * inv0;
        float v2 = Oacc[vj][2] * inv1, v3 = Oacc[vj][3] * inv1;
        __nv_bfloat16 h0 = __float2bfloat16(v0), h1 = __float2bfloat16(v1);
        __nv_bfloat16 h2 = __float2bfloat16(v2), h3 = __float2bfloat16(v3);
        __nv_bfloat16 e0 = __float2bfloat16(v0 - __bfloat162float(h0));
        __nv_bfloat16 e1 = __float2bfloat16(v1 - __bfloat162float(h1));
        __nv_bfloat16 e2 = __float2bfloat16(v2 - __bfloat162float(h2));
        __nv_bfloat16 e3 = __float2bfloat16(v3 - __bfloat162float(h3));
        *(__nv_bfloat162*)&g_AH[base0 + vj * 8 + ec] = __nv_bfloat162(h0, h1);
        *(__nv_bfloat162*)&g_AL[base0 + vj * 8 + ec] = __nv_bfloat162(e0, e1);
        *(__nv_bfloat162*)&g_AH[base1 + vj * 8 + ec] = __nv_bfloat162(h2, h3);
        *(__nv_bfloat162*)&g_AL[base1 + vj * 8 + ec] = __nv_bfloat162(e2, e3);
    }
}

// ---------------------------------------------------------------------------
extern "C" void kernel_launch(void* const* d_in, const int* in_sizes, int n_in,
                              void* d_out, int out_size)
{
    (void)in_sizes; (void)n_in; (void)out_size;

    const float* xq   = (const float*)d_in[0];
    const float* xkv  = (const float*)d_in[1];
    const int*   mask = (const int*)d_in[2];
    const float* Wq = (const float*)d_in[3];
    const float* bq = (const float*)d_in[4];
    const float* Wk = (const float*)d_in[5];
    const float* bk = (const float*)d_in[6];
    const float* Wv = (const float*)d_in[7];
    const float* bv = (const float*)d_in[8];
    const float* Wo = (const float*)d_in[9];
    const float* bo = (const float*)d_in[10];
    float* out = (float*)d_out;

    __half *Qh, *Kh, *Vh, *Xqh, *Xkvh, *Wqh, *Wkh, *Wvh;
    __nv_bfloat16 *WoH, *WoL, *AHp, *ALp;
    unsigned long long *Mbp;
    cudaGetSymbolAddress((void**)&Qh,   g_Qh);
    cudaGetSymbolAddress((void**)&Kh,   g_Kh);
    cudaGetSymbolAddress((void**)&Vh,   g_Vh);
    cudaGetSymbolAddress((void**)&Mbp,  g_Mb);
    cudaGetSymbolAddress((void**)&Xqh,  g_Xqh);
    cudaGetSymbolAddress((void**)&Xkvh, g_Xkvh);
    cudaGetSymbolAddress((void**)&Wqh,  g_Wqh);
    cudaGetSymbolAddress((void**)&Wkh,  g_Wkh);
    cudaGetSymbolAddress((void**)&Wvh,  g_Wvh);
    cudaGetSymbolAddress((void**)&WoH,  g_WoH);
    cudaGetSymbolAddress((void**)&WoL,  g_WoL);
    cudaGetSymbolAddress((void**)&AHp,  g_AH);
    cudaGetSymbolAddress((void**)&ALp,  g_AL);

    const int smem_attn = SQ_BYTES + 4 * SKV_BYTES + 2 * 128 * 8;
    const int smem_f16  = 2 * F16_STAGE;
    const int smem_fkv  = 2 * FKV_STAGE;
    const int smem_b3   = 2 * B3_STAGE;
    static int configured = 0;
    if (!configured) {
        cudaFuncSetAttribute(attn2_kernel,
                             cudaFuncAttributeMaxDynamicSharedMemorySize, smem_attn);
        cudaFuncSetAttribute(gemm_f16_kernel,
                             cudaFuncAttributeMaxDynamicSharedMemorySize, smem_f16);
        cudaFuncSetAttribute(gemm_fkv_kernel,
                             cudaFuncAttributeMaxDynamicSharedMemorySize, smem_fkv);
        cudaFuncSetAttribute(gemm_bf16x3_kernel,
                             cudaFuncAttributeMaxDynamicSharedMemorySize, smem_b3);
        configured = 1;
    }

    dim3 thr(256);
    const int nW8  = DMODEL * DMODEL / 8;          // 131072
    const int nXq8 = NB * TQL * DMODEL / 8;        // 262144
    const int nXk8 = NB * TKVL * DMODEL / 8;       // 2097152

    mask_pack_kernel<<<1024, thr>>>(mask, (unsigned*)Mbp);
    cvt_f16_kernel<<<1024, thr>>>((const float4*)xq,  (uint4*)Xqh,  nXq8);
    cvt_f16_kernel<<<2048, thr>>>((const float4*)xkv, (uint4*)Xkvh, nXk8);
    cvt3_f16_kernel<<<1536, thr>>>((const float4*)Wq, (const float4*)Wk,
                                   (const float4*)Wv,
                                   (uint4*)Wqh, (uint4*)Wkh, (uint4*)Wvh, nW8);
    split_bf16_kernel<<<512, thr>>>((const float4*)Wo, (uint4*)WoH, (uint4*)WoL, nW8);

    gemm_f16_kernel<<<dim3(8, 16),  thr, smem_f16>>>(Xqh, Wqh, bq, Qh);
    gemm_fkv_kernel<<<dim3(8, 128), thr, smem_fkv>>>(Xkvh, Wkh, Wvh, bk, bv, Kh, Vh);

    attn2_kernel<<<dim3(TQL / 128, NH, NB), thr, smem_attn>>>();

    gemm_bf16x3_kernel<<<dim3(8, 16), thr, smem_b3>>>(AHp, ALp, WoH, WoL, bo, out);
}

// round 17
// speedup vs baseline: 6.4214x; 1.0145x over previous
#include <cuda_runtime.h>
#include <cuda_bf16.h>
#include <cuda_fp16.h>
#include <stdint.h>
#include <math.h>
#include <float.h>

#define DMODEL 1024
#define NB     4
#define TQL    512
#define TKVL   4096
#define NH     8
#define HD     128

// --------------------------- device scratch --------------------------------
__device__ __half g_Qh[NB * TQL  * DMODEL];
__device__ __half g_Kh[NB * TKVL * DMODEL];
__device__ __half g_Vh[NB * TKVL * DMODEL];
__device__ unsigned long long g_Mb[NB * TQL * (TKVL / 64)];

// pre-converted operands
__device__ __half g_Xqh [NB * TQL  * DMODEL];
__device__ __half g_Xkvh[NB * TKVL * DMODEL];
__device__ __half g_Wqh [DMODEL * DMODEL];
__device__ __half g_Wkh [DMODEL * DMODEL];
__device__ __half g_Wvh [DMODEL * DMODEL];
__device__ __nv_bfloat16 g_WoH[DMODEL * DMODEL];
__device__ __nv_bfloat16 g_WoL[DMODEL * DMODEL];
__device__ __nv_bfloat16 g_AH [NB * TQL * DMODEL];
__device__ __nv_bfloat16 g_AL [NB * TQL * DMODEL];

// ---------------------------- mma helpers ----------------------------------
__device__ __forceinline__ unsigned smem_u32(const void* p) {
    return (unsigned)__cvta_generic_to_shared(p);
}
__device__ __forceinline__ void ldsm_x4(unsigned& r0, unsigned& r1,
                                        unsigned& r2, unsigned& r3, unsigned a) {
    asm volatile("ldmatrix.sync.aligned.m8n8.x4.shared.b16 {%0,%1,%2,%3}, [%4];"
                 : "=r"(r0), "=r"(r1), "=r"(r2), "=r"(r3) : "r"(a));
}
__device__ __forceinline__ void ldsm_x4t(unsigned& r0, unsigned& r1,
                                         unsigned& r2, unsigned& r3, unsigned a) {
    asm volatile("ldmatrix.sync.aligned.m8n8.x4.trans.shared.b16 {%0,%1,%2,%3}, [%4];"
                 : "=r"(r0), "=r"(r1), "=r"(r2), "=r"(r3) : "r"(a));
}
__device__ __forceinline__ void mma_bf16(float* d, const unsigned* a, const unsigned* b) {
    asm volatile(
        "mma.sync.aligned.m16n8k16.row.col.f32.bf16.bf16.f32 "
        "{%0,%1,%2,%3}, {%4,%5,%6,%7}, {%8,%9}, {%0,%1,%2,%3};"
        : "+f"(d[0]), "+f"(d[1]), "+f"(d[2]), "+f"(d[3])
        : "r"(a[0]), "r"(a[1]), "r"(a[2]), "r"(a[3]), "r"(b[0]), "r"(b[1]));
}
__device__ __forceinline__ void mma_f16(float* d, const unsigned* a, const unsigned* b) {
    asm volatile(
        "mma.sync.aligned.m16n8k16.row.col.f32.f16.f16.f32 "
        "{%0,%1,%2,%3}, {%4,%5,%6,%7}, {%8,%9}, {%0,%1,%2,%3};"
        : "+f"(d[0]), "+f"(d[1]), "+f"(d[2]), "+f"(d[3])
        : "r"(a[0]), "r"(a[1]), "r"(a[2]), "r"(a[3]), "r"(b[0]), "r"(b[1]));
}
#define CP_ASYNC16(dst, src) \
    asm volatile("cp.async.cg.shared.global [%0], [%1], 16;" :: "r"(dst), "l"(src))
#define CP_ASYNC8(dst, src) \
    asm volatile("cp.async.ca.shared.global [%0], [%1], 8;"  :: "r"(dst), "l"(src))
#define CP_COMMIT()  asm volatile("cp.async.commit_group;")
#define CP_WAIT0()   asm volatile("cp.async.wait_group 0;")
#define CP_WAIT1()   asm volatile("cp.async.wait_group 1;")

__device__ __forceinline__ float ex2(float x) {
    float y;
    asm("ex2.approx.f32 %0, %1;" : "=f"(y) : "f"(x));
    return y;
}

// ======================= convert / split kernels ===========================
__device__ __forceinline__ uint4 pack_f16x8(float4 a, float4 b) {
    __half2 h0 = __floats2half2_rn(a.x, a.y), h1 = __floats2half2_rn(a.z, a.w);
    __half2 h2 = __floats2half2_rn(b.x, b.y), h3 = __floats2half2_rn(b.z, b.w);
    uint4 u;
    u.x = *(unsigned*)&h0; u.y = *(unsigned*)&h1;
    u.z = *(unsigned*)&h2; u.w = *(unsigned*)&h3;
    return u;
}
__global__ __launch_bounds__(256) void cvt_f16_kernel(
    const float4* __restrict__ x, uint4* __restrict__ out, int n8)
{
    int i = blockIdx.x * 256 + threadIdx.x;
    int stride = gridDim.x * 256;
    for (; i < n8; i += stride)
        out[i] = pack_f16x8(x[2 * i], x[2 * i + 1]);
}
__global__ __launch_bounds__(256) void cvt3_f16_kernel(
    const float4* __restrict__ w0, const float4* __restrict__ w1,
    const float4* __restrict__ w2,
    uint4* __restrict__ o0, uint4* __restrict__ o1, uint4* __restrict__ o2,
    int n8)
{
    int i = blockIdx.x * 256 + threadIdx.x;
    int stride = gridDim.x * 256;
    int total = 3 * n8;
    for (; i < total; i += stride) {
        int m = i / n8, j = i - m * n8;
        const float4* w = (m == 0) ? w0 : (m == 1) ? w1 : w2;
        uint4* o = (m == 0) ? o0 : (m == 1) ? o1 : o2;
        o[j] = pack_f16x8(w[2 * j], w[2 * j + 1]);
    }
}
__global__ __launch_bounds__(256) void split_bf16_kernel(
    const float4* __restrict__ x, uint4* __restrict__ hi,
    uint4* __restrict__ lo, int n8)
{
    int i = blockIdx.x * 256 + threadIdx.x;
    int stride = gridDim.x * 256;
    for (; i < n8; i += stride) {
        float4 a = x[2 * i], b = x[2 * i + 1];
        float v[8] = { a.x, a.y, a.z, a.w, b.x, b.y, b.z, b.w };
        __nv_bfloat16 h[8], l[8];
#pragma unroll
        for (int k = 0; k < 8; k++) {
            h[k] = __float2bfloat16(v[k]);
            l[k] = __float2bfloat16(v[k] - __bfloat162float(h[k]));
        }
        uint4 uh, ul;
        __nv_bfloat162 t;
        t = __nv_bfloat162(h[0], h[1]); uh.x = *(unsigned*)&t;
        t = __nv_bfloat162(h[2], h[3]); uh.y = *(unsigned*)&t;
        t = __nv_bfloat162(h[4], h[5]); uh.z = *(unsigned*)&t;
        t = __nv_bfloat162(h[6], h[7]); uh.w = *(unsigned*)&t;
        t = __nv_bfloat162(l[0], l[1]); ul.x = *(unsigned*)&t;
        t = __nv_bfloat162(l[2], l[3]); ul.y = *(unsigned*)&t;
        t = __nv_bfloat162(l[4], l[5]); ul.z = *(unsigned*)&t;
        t = __nv_bfloat162(l[6], l[7]); ul.w = *(unsigned*)&t;
        hi[i] = uh;
        lo[i] = ul;
    }
}

// =========================== mask bit-pack =================================
__global__ __launch_bounds__(256) void mask_pack_kernel(const int* __restrict__ m,
                                                        unsigned* __restrict__ out)
{
    const int lane = threadIdx.x & 31;
    const int wg   = (blockIdx.x * 256 + threadIdx.x) >> 5;
    const int base = wg * 1024;
    unsigned myw = 0;
#pragma unroll
    for (int it = 0; it < 32; it++) {
        int v = m[base + it * 32 + lane];
        unsigned b = __ballot_sync(0xffffffffu, v != 0);
        if (lane == it) myw = b;
    }
    out[wg * 32 + lane] = myw;
}

// ===========================================================================
// fp16 GEMM (Q projection): C = A @ W + bias, fp16 in/out, fp32 acc.
// ===========================================================================
#define AS 40
#define WS 136

#define F16_A_BYTES (128 * AS * 2)
#define F16_W_BYTES (32 * WS * 2)
#define F16_STAGE   (F16_A_BYTES + F16_W_BYTES)

__global__ __launch_bounds__(256) void gemm_f16_kernel(
    const __half* __restrict__ A, const __half* __restrict__ W,
    const float* __restrict__ bias, __half* __restrict__ Ch)
{
    extern __shared__ __align__(16) char smraw[];

    const int tid  = threadIdx.x;
    const int lane = tid & 31;
    const int wid  = tid >> 5;
    const int bm   = blockIdx.y * 128;
    const int bn   = blockIdx.x * 128;
    const int wm   = (wid >> 2) * 64;
    const int wn   = (wid & 3) * 32;

    float acc[4][4][4];
#pragma unroll
    for (int mi = 0; mi < 4; mi++)
#pragma unroll
        for (int nj = 0; nj < 4; nj++)
#pragma unroll
            for (int r = 0; r < 4; r++) acc[mi][nj][r] = 0.0f;

    const int a_row = tid >> 1,  a_c = (tid & 1) * 16;
    const int w_row = tid >> 3,  w_c = (tid & 7) * 16;

    const __half* Ap = A + (size_t)(bm + a_row) * DMODEL + a_c;
    const __half* Wp = W + (size_t)w_row * DMODEL + bn + w_c;

    auto issue = [&](int kt, int st) {
        char* base = smraw + st * F16_STAGE;
        __half* sA = (__half*)base;
        __half* sW = (__half*)(base + F16_A_BYTES);
        const int k0 = kt * 32;
        CP_ASYNC16(smem_u32(&sA[a_row * AS + a_c]),     Ap + k0);
        CP_ASYNC16(smem_u32(&sA[a_row * AS + a_c + 8]), Ap + k0 + 8);
        CP_ASYNC16(smem_u32(&sW[w_row * WS + w_c]),     Wp + (size_t)k0 * DMODEL);
        CP_ASYNC16(smem_u32(&sW[w_row * WS + w_c + 8]), Wp + (size_t)k0 * DMODEL + 8);
    };

    issue(0, 0);
    CP_COMMIT();

    const int NT = DMODEL / 32;
    for (int kt = 0; kt < NT; kt++) {
        const int st = kt & 1;
        if (kt + 1 < NT) { issue(kt + 1, st ^ 1); CP_COMMIT(); CP_WAIT1(); }
        else             { CP_WAIT0(); }
        __syncthreads();

        char* base = smraw + st * F16_STAGE;
        __half* sA = (__half*)base;
        __half* sW = (__half*)(base + F16_A_BYTES);

#pragma unroll
        for (int ks = 0; ks < 2; ks++) {
            const int k16 = ks * 16;
            unsigned ah[4][4], bw[4][2];
            const int ar = lane & 15, ac = (lane >> 4) * 8;
#pragma unroll
            for (int mi = 0; mi < 4; mi++)
                ldsm_x4(ah[mi][0], ah[mi][1], ah[mi][2], ah[mi][3],
                        smem_u32(&sA[(wm + mi * 16 + ar) * AS + k16 + ac]));
#pragma unroll
            for (int njp = 0; njp < 2; njp++) {
                unsigned t0, t1, t2, t3;
                ldsm_x4t(t0, t1, t2, t3,
                         smem_u32(&sW[(k16 + (lane & 15)) * WS
                                      + wn + (njp * 2 + (lane >> 4)) * 8]));
                bw[2 * njp][0] = t0; bw[2 * njp][1] = t1;
                bw[2 * njp + 1][0] = t2; bw[2 * njp + 1][1] = t3;
            }
#pragma unroll
            for (int mi = 0; mi < 4; mi++)
#pragma unroll
                for (int nj = 0; nj < 4; nj++)
                    mma_f16(acc[mi][nj], ah[mi], bw[nj]);
        }
        __syncthreads();
    }

    const int er = lane >> 2, ec = (lane & 3) * 2;
#pragma unroll
    for (int mi = 0; mi < 4; mi++)
#pragma unroll
        for (int nj = 0; nj < 4; nj++) {
            int row = bm + wm + mi * 16 + er;
            int col = bn + wn + nj * 8 + ec;
            float2 bv = *(const float2*)&bias[col];
            *(__half2*)&Ch[(size_t)row * DMODEL + col] =
                __floats2half2_rn(acc[mi][nj][0] + bv.x, acc[mi][nj][1] + bv.y);
            *(__half2*)&Ch[(size_t)(row + 8) * DMODEL + col] =
                __floats2half2_rn(acc[mi][nj][2] + bv.x, acc[mi][nj][3] + bv.y);
        }
}

// ===========================================================================
// Fused K+V projection GEMM: one A tile feeds both W_k and W_v.
// ===========================================================================
#define FKV_STAGE (F16_A_BYTES + 2 * F16_W_BYTES)

__global__ __launch_bounds__(256) void gemm_fkv_kernel(
    const __half* __restrict__ A,
    const __half* __restrict__ Wk, const __half* __restrict__ Wv,
    const float* __restrict__ biask, const float* __restrict__ biasv,
    __half* __restrict__ Ck, __half* __restrict__ Cv)
{
    extern __shared__ __align__(16) char smraw[];

    const int tid  = threadIdx.x;
    const int lane = tid & 31;
    const int wid  = tid >> 5;
    const int bm   = blockIdx.y * 128;
    const int bn   = blockIdx.x * 128;
    const int wm   = (wid >> 2) * 64;
    const int wn   = (wid & 3) * 32;

    float accK[4][4][4], accV[4][4][4];
#pragma unroll
    for (int mi = 0; mi < 4; mi++)
#pragma unroll
        for (int nj = 0; nj < 4; nj++)
#pragma unroll
            for (int r = 0; r < 4; r++) { accK[mi][nj][r] = 0.0f; accV[mi][nj][r] = 0.0f; }

    const int a_row = tid >> 1,  a_c = (tid & 1) * 16;
    const int w_row = tid >> 3,  w_c = (tid & 7) * 16;

    const __half* Ap  = A  + (size_t)(bm + a_row) * DMODEL + a_c;
    const __half* Wkp = Wk + (size_t)w_row * DMODEL + bn + w_c;
    const __half* Wvp = Wv + (size_t)w_row * DMODEL + bn + w_c;

    auto issue = [&](int kt, int st) {
        char* base = smraw + st * FKV_STAGE;
        __half* sA  = (__half*)base;
        __half* sWk = (__half*)(base + F16_A_BYTES);
        __half* sWv = (__half*)(base + F16_A_BYTES + F16_W_BYTES);
        const int k0 = kt * 32;
        CP_ASYNC16(smem_u32(&sA[a_row * AS + a_c]),      Ap + k0);
        CP_ASYNC16(smem_u32(&sA[a_row * AS + a_c + 8]),  Ap + k0 + 8);
        CP_ASYNC16(smem_u32(&sWk[w_row * WS + w_c]),     Wkp + (size_t)k0 * DMODEL);
        CP_ASYNC16(smem_u32(&sWk[w_row * WS + w_c + 8]), Wkp + (size_t)k0 * DMODEL + 8);
        CP_ASYNC16(smem_u32(&sWv[w_row * WS + w_c]),     Wvp + (size_t)k0 * DMODEL);
        CP_ASYNC16(smem_u32(&sWv[w_row * WS + w_c + 8]), Wvp + (size_t)k0 * DMODEL + 8);
    };

    issue(0, 0);
    CP_COMMIT();

    const int NT = DMODEL / 32;
    for (int kt = 0; kt < NT; kt++) {
        const int st = kt & 1;
        if (kt + 1 < NT) { issue(kt + 1, st ^ 1); CP_COMMIT(); CP_WAIT1(); }
        else             { CP_WAIT0(); }
        __syncthreads();

        char* base = smraw + st * FKV_STAGE;
        __half* sA  = (__half*)base;
        __half* sWk = (__half*)(base + F16_A_BYTES);
        __half* sWv = (__half*)(base + F16_A_BYTES + F16_W_BYTES);

#pragma unroll
        for (int ks = 0; ks < 2; ks++) {
            const int k16 = ks * 16;
            unsigned ah[4][4], bk[4][2], bv[4][2];
            const int ar = lane & 15, ac = (lane >> 4) * 8;
#pragma unroll
            for (int mi = 0; mi < 4; mi++)
                ldsm_x4(ah[mi][0], ah[mi][1], ah[mi][2], ah[mi][3],
                        smem_u32(&sA[(wm + mi * 16 + ar) * AS + k16 + ac]));
#pragma unroll
            for (int njp = 0; njp < 2; njp++) {
                unsigned t0, t1, t2, t3;
                ldsm_x4t(t0, t1, t2, t3,
                         smem_u32(&sWk[(k16 + (lane & 15)) * WS
                                       + wn + (njp * 2 + (lane >> 4)) * 8]));
                bk[2 * njp][0] = t0; bk[2 * njp][1] = t1;
                bk[2 * njp + 1][0] = t2; bk[2 * njp + 1][1] = t3;
                ldsm_x4t(t0, t1, t2, t3,
                         smem_u32(&sWv[(k16 + (lane & 15)) * WS
                                       + wn + (njp * 2 + (lane >> 4)) * 8]));
                bv[2 * njp][0] = t0; bv[2 * njp][1] = t1;
                bv[2 * njp + 1][0] = t2; bv[2 * njp + 1][1] = t3;
            }
#pragma unroll
            for (int mi = 0; mi < 4; mi++)
#pragma unroll
                for (int nj = 0; nj < 4; nj++) {
                    mma_f16(accK[mi][nj], ah[mi], bk[nj]);
                    mma_f16(accV[mi][nj], ah[mi], bv[nj]);
                }
        }
        __syncthreads();
    }

    const int er = lane >> 2, ec = (lane & 3) * 2;
#pragma unroll
    for (int mi = 0; mi < 4; mi++)
#pragma unroll
        for (int nj = 0; nj < 4; nj++) {
            int row = bm + wm + mi * 16 + er;
            int col = bn + wn + nj * 8 + ec;
            float2 bk2 = *(const float2*)&biask[col];
            float2 bv2 = *(const float2*)&biasv[col];
            *(__half2*)&Ck[(size_t)row * DMODEL + col] =
                __floats2half2_rn(accK[mi][nj][0] + bk2.x, accK[mi][nj][1] + bk2.y);
            *(__half2*)&Ck[(size_t)(row + 8) * DMODEL + col] =
                __floats2half2_rn(accK[mi][nj][2] + bk2.x, accK[mi][nj][3] + bk2.y);
            *(__half2*)&Cv[(size_t)row * DMODEL + col] =
                __floats2half2_rn(accV[mi][nj][0] + bv2.x, accV[mi][nj][1] + bv2.y);
            *(__half2*)&Cv[(size_t)(row + 8) * DMODEL + col] =
                __floats2half2_rn(accV[mi][nj][2] + bv2.x, accV[mi][nj][3] + bv2.y);
        }
}

// ===========================================================================
// bf16x3 GEMM (O projection): pre-split hi/lo both operands, fp32 out.
// ===========================================================================
#define B3_A_BYTES (128 * AS * 2)
#define B3_W_BYTES (32 * WS * 2)
#define B3_STAGE   (2 * B3_A_BYTES + 2 * B3_W_BYTES)

__global__ __launch_bounds__(256) void gemm_bf16x3_kernel(
    const __nv_bfloat16* __restrict__ AH, const __nv_bfloat16* __restrict__ AL,
    const __nv_bfloat16* __restrict__ WH, const __nv_bfloat16* __restrict__ WL,
    const float* __restrict__ bias, float* __restrict__ C)
{
    extern __shared__ __align__(16) char smraw[];

    const int tid  = threadIdx.x;
    const int lane = tid & 31;
    const int wid  = tid >> 5;
    const int bm   = blockIdx.y * 128;
    const int bn   = blockIdx.x * 128;
    const int wm   = (wid >> 2) * 64;
    const int wn   = (wid & 3) * 32;

    float acc[4][4][4];
#pragma unroll
    for (int mi = 0; mi < 4; mi++)
#pragma unroll
        for (int nj = 0; nj < 4; nj++)
#pragma unroll
            for (int r = 0; r < 4; r++) acc[mi][nj][r] = 0.0f;

    const int a_row = tid >> 1,  a_c = (tid & 1) * 16;
    const int w_row = tid >> 3,  w_c = (tid & 7) * 16;

    const __nv_bfloat16* ApH = AH + (size_t)(bm + a_row) * DMODEL + a_c;
    const __nv_bfloat16* ApL = AL + (size_t)(bm + a_row) * DMODEL + a_c;
    const __nv_bfloat16* WpH = WH + (size_t)w_row * DMODEL + bn + w_c;
    const __nv_bfloat16* WpL = WL + (size_t)w_row * DMODEL + bn + w_c;

    auto issue = [&](int kt, int st) {
        char* base = smraw + st * B3_STAGE;
        __nv_bfloat16* sAH = (__nv_bfloat16*)base;
        __nv_bfloat16* sAL = (__nv_bfloat16*)(base + B3_A_BYTES);
        __nv_bfloat16* sWH = (__nv_bfloat16*)(base + 2 * B3_A_BYTES);
        __nv_bfloat16* sWL = (__nv_bfloat16*)(base + 2 * B3_A_BYTES + B3_W_BYTES);
        const int k0 = kt * 32;
        CP_ASYNC16(smem_u32(&sAH[a_row * AS + a_c]),     ApH + k0);
        CP_ASYNC16(smem_u32(&sAH[a_row * AS + a_c + 8]), ApH + k0 + 8);
        CP_ASYNC16(smem_u32(&sAL[a_row * AS + a_c]),     ApL + k0);
        CP_ASYNC16(smem_u32(&sAL[a_row * AS + a_c + 8]), ApL + k0 + 8);
        CP_ASYNC16(smem_u32(&sWH[w_row * WS + w_c]),     WpH + (size_t)k0 * DMODEL);
        CP_ASYNC16(smem_u32(&sWH[w_row * WS + w_c + 8]), WpH + (size_t)k0 * DMODEL + 8);
        CP_ASYNC16(smem_u32(&sWL[w_row * WS + w_c]),     WpL + (size_t)k0 * DMODEL);
        CP_ASYNC16(smem_u32(&sWL[w_row * WS + w_c + 8]), WpL + (size_t)k0 * DMODEL + 8);
    };

    issue(0, 0);
    CP_COMMIT();

    const int NT = DMODEL / 32;
    for (int kt = 0; kt < NT; kt++) {
        const int st = kt & 1;
        if (kt + 1 < NT) { issue(kt + 1, st ^ 1); CP_COMMIT(); CP_WAIT1(); }
        else             { CP_WAIT0(); }
        __syncthreads();

        char* base = smraw + st * B3_STAGE;
        __nv_bfloat16* sAH = (__nv_bfloat16*)base;
        __nv_bfloat16* sAL = (__nv_bfloat16*)(base + B3_A_BYTES);
        __nv_bfloat16* sWH = (__nv_bfloat16*)(base + 2 * B3_A_BYTES);
        __nv_bfloat16* sWL = (__nv_bfloat16*)(base + 2 * B3_A_BYTES + B3_W_BYTES);

#pragma unroll
        for (int ks = 0; ks < 2; ks++) {
            const int k16 = ks * 16;
            unsigned ah[4][4], al[4][4], bh[4][2], bl[4][2];
            const int ar = lane & 15, ac = (lane >> 4) * 8;
#pragma unroll
            for (int mi = 0; mi < 4; mi++) {
                ldsm_x4(ah[mi][0], ah[mi][1], ah[mi][2], ah[mi][3],
                        smem_u32(&sAH[(wm + mi * 16 + ar) * AS + k16 + ac]));
                ldsm_x4(al[mi][0], al[mi][1], al[mi][2], al[mi][3],
                        smem_u32(&sAL[(wm + mi * 16 + ar) * AS + k16 + ac]));
            }
#pragma unroll
            for (int njp = 0; njp < 2; njp++) {
                unsigned t0, t1, t2, t3;
                ldsm_x4t(t0, t1, t2, t3,
                         smem_u32(&sWH[(k16 + (lane & 15)) * WS
                                       + wn + (njp * 2 + (lane >> 4)) * 8]));
                bh[2 * njp][0] = t0; bh[2 * njp][1] = t1;
                bh[2 * njp + 1][0] = t2; bh[2 * njp + 1][1] = t3;
                ldsm_x4t(t0, t1, t2, t3,
                         smem_u32(&sWL[(k16 + (lane & 15)) * WS
                                       + wn + (njp * 2 + (lane >> 4)) * 8]));
                bl[2 * njp][0] = t0; bl[2 * njp][1] = t1;
                bl[2 * njp + 1][0] = t2; bl[2 * njp + 1][1] = t3;
            }
#pragma unroll
            for (int mi = 0; mi < 4; mi++)
#pragma unroll
                for (int nj = 0; nj < 4; nj++) {
                    mma_bf16(acc[mi][nj], ah[mi], bh[nj]);
                    mma_bf16(acc[mi][nj], ah[mi], bl[nj]);
                    mma_bf16(acc[mi][nj], al[mi], bh[nj]);
                }
        }
        __syncthreads();
    }

    const int er = lane >> 2, ec = (lane & 3) * 2;
#pragma unroll
    for (int mi = 0; mi < 4; mi++)
#pragma unroll
        for (int nj = 0; nj < 4; nj++) {
            int row = bm + wm + mi * 16 + er;
            int col = bn + wn + nj * 8 + ec;
            float2 bv = *(const float2*)&bias[col];
            *(float2*)&C[(size_t)row * DMODEL + col] =
                make_float2(acc[mi][nj][0] + bv.x, acc[mi][nj][1] + bv.y);
            *(float2*)&C[(size_t)(row + 8) * DMODEL + col] =
                make_float2(acc[mi][nj][2] + bv.x, acc[mi][nj][3] + bv.y);
        }
}

// ===========================================================================
// Flash attention v3-style: cross-tile pipelining. Q frags in registers.
// Loop: S-mma(t) -> PV-mma(t-1) -> softmax(t). V ring of 3, K/mask ring of 2.
// ===========================================================================
#define DST 136
#define SQ_BYTES  (128 * DST * 2)
#define SKV_BYTES (64  * DST * 2)
// smem: Q + 2K + 3V + 2 mask
#define ATTN_SMEM (SQ_BYTES + 2 * SKV_BYTES + 3 * SKV_BYTES + 2 * 1024)

__global__ __launch_bounds__(256, 1) void attn2_kernel()
{
    extern __shared__ __align__(16) char smraw[];
    __half* Qs = (__half*)smraw;
    __half* Ks[2] = { (__half*)(smraw + SQ_BYTES),
                      (__half*)(smraw + SQ_BYTES + SKV_BYTES) };
    __half* Vs[3] = { (__half*)(smraw + SQ_BYTES + 2 * SKV_BYTES),
                      (__half*)(smraw + SQ_BYTES + 3 * SKV_BYTES),
                      (__half*)(smraw + SQ_BYTES + 4 * SKV_BYTES) };
    unsigned long long* Mb[2] = {
        (unsigned long long*)(smraw + SQ_BYTES + 5 * SKV_BYTES),
        (unsigned long long*)(smraw + SQ_BYTES + 5 * SKV_BYTES + 1024) };

    const int tid  = threadIdx.x;
    const int lane = tid & 31;
    const int wid  = tid >> 5;
    const int wq   = wid * 16;
    const int er   = lane >> 2;
    const int ec   = (lane & 3) * 2;
    const int q0   = blockIdx.x * 128;
    const int h    = blockIdx.y;
    const int b    = blockIdx.z;

    const __half* Qg = g_Qh + (size_t)(b * TQL + q0) * DMODEL + h * HD;
    const __half* Kg = g_Kh + (size_t)(b * TKVL) * DMODEL + h * HD;
    const __half* Vg = g_Vh + (size_t)(b * TKVL) * DMODEL + h * HD;
    const unsigned long long* Mg = g_Mb + (size_t)(b * TQL + q0) * (TKVL / 64);

    // issue kv(0) into ring slot 0
    {
#pragma unroll
        for (int it = 0; it < 4; it++) {
            int c = tid + it * 256;
            int r = c >> 4, c8 = (c & 15) * 8;
            CP_ASYNC16(smem_u32(&Ks[0][r * DST + c8]), Kg + (size_t)r * DMODEL + c8);
            CP_ASYNC16(smem_u32(&Vs[0][r * DST + c8]), Vg + (size_t)r * DMODEL + c8);
        }
        if (tid < 128)
            CP_ASYNC8(smem_u32(&Mb[0][tid]), Mg + (size_t)tid * (TKVL / 64));
        CP_COMMIT();
    }
    // Q tile -> smem, then frags -> registers (kept for whole kernel)
#pragma unroll
    for (int it = 0; it < 8; it++) {
        int c = tid + it * 256;
        int r = c >> 4, c8 = (c & 15) * 8;
        *(uint4*)&Qs[r * DST + c8] = *(const uint4*)(Qg + (size_t)r * DMODEL + c8);
    }
    __syncthreads();
    unsigned qreg[8][4];
#pragma unroll
    for (int kk = 0; kk < 8; kk++)
        ldsm_x4(qreg[kk][0], qreg[kk][1], qreg[kk][2], qreg[kk][3],
                smem_u32(&Qs[(wq + (lane & 15)) * DST + kk * 16 + (lane >> 4) * 8]));

    const float YC = 1.4426950408889634f * 0.08838834764831845f;

    float Oacc[16][4];
#pragma unroll
    for (int v = 0; v < 16; v++)
#pragma unroll
        for (int r = 0; r < 4; r++) Oacc[v][r] = 0.0f;
    float m_run[2] = { -12000.0f, -12000.0f };
    float l_run[2] = { 0.0f, 0.0f };
    unsigned phP[2][8];   // P(t-1) fragments

    const int NTT = TKVL / 64;
    for (int t = 0; t < NTT; t++) {
        const int kb = t & 1;
        const int vb = t % 3;
        if (t + 1 < NTT) {
            const int kv1 = (t + 1) * 64;
            const int knb = (t + 1) & 1, vnb = (t + 1) % 3;
#pragma unroll
            for (int it = 0; it < 4; it++) {
                int c = tid + it * 256;
                int r = c >> 4, c8 = (c & 15) * 8;
                CP_ASYNC16(smem_u32(&Ks[knb][r * DST + c8]),
                           Kg + (size_t)(kv1 + r) * DMODEL + c8);
                CP_ASYNC16(smem_u32(&Vs[vnb][r * DST + c8]),
                           Vg + (size_t)(kv1 + r) * DMODEL + c8);
            }
            if (tid < 128)
                CP_ASYNC8(smem_u32(&Mb[knb][tid]),
                          Mg + (size_t)tid * (TKVL / 64) + (kv1 >> 6));
            CP_COMMIT();
            CP_WAIT1();
        } else {
            CP_WAIT0();
        }
        __syncthreads();

        // ---- S = Q K^T (t): Q from registers, paired K fragments
        float sa[8][4];
#pragma unroll
        for (int nj = 0; nj < 8; nj++)
#pragma unroll
            for (int r = 0; r < 4; r++) sa[nj][r] = 0.0f;
#pragma unroll
        for (int kk = 0; kk < 8; kk++) {
#pragma unroll
            for (int njp = 0; njp < 4; njp++) {
                unsigned kbf[4];
                ldsm_x4(kbf[0], kbf[1], kbf[2], kbf[3],
                        smem_u32(&Ks[kb][((njp * 2 + ((lane >> 4) & 1)) * 8
                                          + (lane & 7)) * DST
                                         + kk * 16 + ((lane >> 3) & 1) * 8]));
                mma_f16(sa[2 * njp],     qreg[kk], kbf);
                mma_f16(sa[2 * njp + 1], qreg[kk], kbf + 2);
            }
        }

        // ---- PV(t-1): overlaps S(t) completion; Oacc still at scale m(t-1)
        if (t > 0) {
            const int vpb = (t - 1) % 3;
#pragma unroll
            for (int kk = 0; kk < 4; kk++) {
                unsigned aH[4] = { phP[0][2 * kk], phP[1][2 * kk],
                                   phP[0][2 * kk + 1], phP[1][2 * kk + 1] };
#pragma unroll
                for (int vjp = 0; vjp < 8; vjp++) {
                    unsigned vbf[4];
                    ldsm_x4t(vbf[0], vbf[1], vbf[2], vbf[3],
                             smem_u32(&Vs[vpb][(kk * 16 + (lane & 15)) * DST
                                               + (vjp * 2 + (lane >> 4)) * 8]));
                    mma_f16(Oacc[2 * vjp],     aH, vbf);
                    mma_f16(Oacc[2 * vjp + 1], aH, vbf + 2);
                }
            }
        }

        // ---- softmax(t): mask, scale, online max/sum, rescale Oacc, P(t)
        const unsigned long long mb0 = Mb[kb][wq + er];
        const unsigned long long mb1 = Mb[kb][wq + er + 8];
        float rm0 = -1e30f, rm1 = -1e30f;
#pragma unroll
        for (int nj = 0; nj < 8; nj++) {
            unsigned b0 = (unsigned)(mb0 >> (nj * 8 + ec)) & 3u;
            unsigned b1 = (unsigned)(mb1 >> (nj * 8 + ec)) & 3u;
            float y0 = sa[nj][0] * YC, y1 = sa[nj][1] * YC;
            float y2 = sa[nj][2] * YC, y3 = sa[nj][3] * YC;
            sa[nj][0] = (b0 & 1u) ? y0 : -1e30f;
            sa[nj][1] = (b0 & 2u) ? y1 : -1e30f;
            sa[nj][2] = (b1 & 1u) ? y2 : -1e30f;
            sa[nj][3] = (b1 & 2u) ? y3 : -1e30f;
            rm0 = fmaxf(rm0, fmaxf(sa[nj][0], sa[nj][1]));
            rm1 = fmaxf(rm1, fmaxf(sa[nj][2], sa[nj][3]));
        }
        rm0 = fmaxf(rm0, __shfl_xor_sync(0xffffffffu, rm0, 1));
        rm0 = fmaxf(rm0, __shfl_xor_sync(0xffffffffu, rm0, 2));
        rm1 = fmaxf(rm1, __shfl_xor_sync(0xffffffffu, rm1, 1));
        rm1 = fmaxf(rm1, __shfl_xor_sync(0xffffffffu, rm1, 2));
        float mn0 = fmaxf(fmaxf(m_run[0], rm0), -12000.0f);
        float mn1 = fmaxf(fmaxf(m_run[1], rm1), -12000.0f);
        float al0 = ex2(m_run[0] - mn0);
        float al1 = ex2(m_run[1] - mn1);
        m_run[0] = mn0; m_run[1] = mn1;
        l_run[0] *= al0; l_run[1] *= al1;
#pragma unroll
        for (int v = 0; v < 16; v++) {
            Oacc[v][0] *= al0; Oacc[v][1] *= al0;
            Oacc[v][2] *= al1; Oacc[v][3] *= al1;
        }
#pragma unroll
        for (int nj = 0; nj < 8; nj++) {
            float p0 = ex2(sa[nj][0] - mn0);
            float p1 = ex2(sa[nj][1] - mn0);
            float p2 = ex2(sa[nj][2] - mn1);
            float p3 = ex2(sa[nj][3] - mn1);
            l_run[0] += p0 + p1;
            l_run[1] += p2 + p3;
            __half2 h0 = __floats2half2_rn(p0, p1);
            __half2 h1 = __floats2half2_rn(p2, p3);
            phP[0][nj] = *(unsigned*)&h0;
            phP[1][nj] = *(unsigned*)&h1;
        }
        __syncthreads();
    }

    // ---- final PV(NTT-1)
    {
        const int vpb = (NTT - 1) % 3;
#pragma unroll
        for (int kk = 0; kk < 4; kk++) {
            unsigned aH[4] = { phP[0][2 * kk], phP[1][2 * kk],
                               phP[0][2 * kk + 1], phP[1][2 * kk + 1] };
#pragma unroll
            for (int vjp = 0; vjp < 8; vjp++) {
                unsigned vbf[4];
                ldsm_x4t(vbf[0], vbf[1], vbf[2], vbf[3],
                         smem_u32(&Vs[vpb][(kk * 16 + (lane & 15)) * DST
                                           + (vjp * 2 + (lane >> 4)) * 8]));
                mma_f16(Oacc[2 * vjp],     aH, vbf);
                mma_f16(Oacc[2 * vjp + 1], aH, vbf + 2);
            }
        }
    }

    float l0 = l_run[0], l1 = l_run[1];
    l0 += __shfl_xor_sync(0xffffffffu, l0, 1);
    l0 += __shfl_xor_sync(0xffffffffu, l0, 2);
    l1 += __shfl_xor_sync(0xffffffffu, l1, 1);
    l1 += __shfl_xor_sync(0xffffffffu, l1, 2);
    float inv0 = (l0 > 1e-10f) ? (1.0f / l0) : 0.0f;
    float inv1 = (l1 > 1e-10f) ? (1.0f / l1) : 0.0f;

    // epilogue: write bf16 hi/lo split of O directly (feeds O-projection)
    size_t base0 = (size_t)(b * TQL + q0 + wq + er) * DMODEL + h * HD;
    size_t base1 = base0 + 8 * DMODEL;
#pragma unroll
    for (int vj = 0; vj < 16; vj++) {
        float v0 = Oacc[vj][0] * inv0, v1 = Oacc[vj][1] * inv0;
        float v2 = Oacc[vj][2] * inv1, v3 = Oacc[vj][3] * inv1;
        __nv_bfloat16 h0 = __float2bfloat16(v0), h1 = __float2bfloat16(v1);
        __nv_bfloat16 h2 = __float2bfloat16(v2), h3 = __float2bfloat16(v3);
        __nv_bfloat16 e0 = __float2bfloat16(v0 - __bfloat162float(h0));
        __nv_bfloat16 e1 = __float2bfloat16(v1 - __bfloat162float(h1));
        __nv_bfloat16 e2 = __float2bfloat16(v2 - __bfloat162float(h2));
        __nv_bfloat16 e3 = __float2bfloat16(v3 - __bfloat162float(h3));
        *(__nv_bfloat162*)&g_AH[base0 + vj * 8 + ec] = __nv_bfloat162(h0, h1);
        *(__nv_bfloat162*)&g_AL[base0 + vj * 8 + ec] = __nv_bfloat162(e0, e1);
        *(__nv_bfloat162*)&g_AH[base1 + vj * 8 + ec] = __nv_bfloat162(h2, h3);
        *(__nv_bfloat162*)&g_AL[base1 + vj * 8 + ec] = __nv_bfloat162(e2, e3);
    }
}

// ---------------------------------------------------------------------------
extern "C" void kernel_launch(void* const* d_in, const int* in_sizes, int n_in,
                              void* d_out, int out_size)
{
    (void)in_sizes; (void)n_in; (void)out_size;

    const float* xq   = (const float*)d_in[0];
    const float* xkv  = (const float*)d_in[1];
    const int*   mask = (const int*)d_in[2];
    const float* Wq = (const float*)d_in[3];
    const float* bq = (const float*)d_in[4];
    const float* Wk = (const float*)d_in[5];
    const float* bk = (const float*)d_in[6];
    const float* Wv = (const float*)d_in[7];
    const float* bv = (const float*)d_in[8];
    const float* Wo = (const float*)d_in[9];
    const float* bo = (const float*)d_in[10];
    float* out = (float*)d_out;

    __half *Qh, *Kh, *Vh, *Xqh, *Xkvh, *Wqh, *Wkh, *Wvh;
    __nv_bfloat16 *WoH, *WoL, *AHp, *ALp;
    unsigned long long *Mbp;
    cudaGetSymbolAddress((void**)&Qh,   g_Qh);
    cudaGetSymbolAddress((void**)&Kh,   g_Kh);
    cudaGetSymbolAddress((void**)&Vh,   g_Vh);
    cudaGetSymbolAddress((void**)&Mbp,  g_Mb);
    cudaGetSymbolAddress((void**)&Xqh,  g_Xqh);
    cudaGetSymbolAddress((void**)&Xkvh, g_Xkvh);
    cudaGetSymbolAddress((void**)&Wqh,  g_Wqh);
    cudaGetSymbolAddress((void**)&Wkh,  g_Wkh);
    cudaGetSymbolAddress((void**)&Wvh,  g_Wvh);
    cudaGetSymbolAddress((void**)&WoH,  g_WoH);
    cudaGetSymbolAddress((void**)&WoL,  g_WoL);
    cudaGetSymbolAddress((void**)&AHp,  g_AH);
    cudaGetSymbolAddress((void**)&ALp,  g_AL);

    const int smem_attn = ATTN_SMEM;
    const int smem_f16  = 2 * F16_STAGE;
    const int smem_fkv  = 2 * FKV_STAGE;
    const int smem_b3   = 2 * B3_STAGE;
    static int configured = 0;
    if (!configured) {
        cudaFuncSetAttribute(attn2_kernel,
                             cudaFuncAttributeMaxDynamicSharedMemorySize, smem_attn);
        cudaFuncSetAttribute(gemm_f16_kernel,
                             cudaFuncAttributeMaxDynamicSharedMemorySize, smem_f16);
        cudaFuncSetAttribute(gemm_fkv_kernel,
                             cudaFuncAttributeMaxDynamicSharedMemorySize, smem_fkv);
        cudaFuncSetAttribute(gemm_bf16x3_kernel,
                             cudaFuncAttributeMaxDynamicSharedMemorySize, smem_b3);
        configured = 1;
    }

    dim3 thr(256);
    const int nW8  = DMODEL * DMODEL / 8;
    const int nXq8 = NB * TQL * DMODEL / 8;
    const int nXk8 = NB * TKVL * DMODEL / 8;

    mask_pack_kernel<<<1024, thr>>>(mask, (unsigned*)Mbp);
    cvt_f16_kernel<<<1024, thr>>>((const float4*)xq,  (uint4*)Xqh,  nXq8);
    cvt_f16_kernel<<<2048, thr>>>((const float4*)xkv, (uint4*)Xkvh, nXk8);
    cvt3_f16_kernel<<<1536, thr>>>((const float4*)Wq, (const float4*)Wk,
                                   (const float4*)Wv,
                                   (uint4*)Wqh, (uint4*)Wkh, (uint4*)Wvh, nW8);
    split_bf16_kernel<<<512, thr>>>((const float4*)Wo, (uint4*)WoH, (uint4*)WoL, nW8);

    gemm_f16_kernel<<<dim3(8, 16),  thr, smem_f16>>>(Xqh, Wqh, bq, Qh);
    gemm_fkv_kernel<<<dim3(8, 128), thr, smem_fkv>>>(Xkvh, Wkh, Wvh, bk, bv, Kh, Vh);

    attn2_kernel<<<dim3(TQL / 128, NH, NB), thr, smem_attn>>>();

    gemm_bf16x3_kernel<<<dim3(8, 16), thr, smem_b3>>>(AHp, ALp, WoH, WoL, bo, out);
}